// round 1
// baseline (speedup 1.0000x reference)
#include <cuda_runtime.h>
#include <math.h>

// Problem constants
#define B_ 4
#define T_ 2048
#define D_ 1024
#define ROWS (B_ * T_)        // 8192
#define EPS 1e-5f

// Scratch (allocation-free: __device__ globals)
__device__ float g_h   [ROWS * D_];          // ln1 out
__device__ float g_kqv [ROWS * 3 * D_];      // qkv
__device__ float g_sc  [(size_t)B_ * T_ * T_]; // scores
__device__ float g_attn[ROWS * D_];          // attn @ v
__device__ float g_a   [ROWS * D_];          // proj out
__device__ float g_h2  [ROWS * D_];          // ln2 out
__device__ float g_mid [ROWS * 4 * D_];      // mlp mid

// ---------------------------------------------------------------------------
// LayerNorm: one block per row, 256 threads
// ---------------------------------------------------------------------------
__global__ void __launch_bounds__(256) ln_kernel(
    const float* __restrict__ x, const float* __restrict__ gamma,
    const float* __restrict__ beta, float* __restrict__ out)
{
    const int row = blockIdx.x;
    const float* xr = x + (size_t)row * D_;
    float* orow = out + (size_t)row * D_;

    float s = 0.f, ss = 0.f;
    for (int i = threadIdx.x; i < D_; i += 256) {
        float v = xr[i];
        s += v; ss += v * v;
    }
    __shared__ float rs[8], rss[8];
    #pragma unroll
    for (int o = 16; o > 0; o >>= 1) {
        s  += __shfl_down_sync(0xffffffffu, s,  o);
        ss += __shfl_down_sync(0xffffffffu, ss, o);
    }
    int wid = threadIdx.x >> 5, lid = threadIdx.x & 31;
    if (lid == 0) { rs[wid] = s; rss[wid] = ss; }
    __syncthreads();
    __shared__ float s_mu, s_rstd;
    if (threadIdx.x == 0) {
        float ts = 0.f, tss = 0.f;
        #pragma unroll
        for (int i = 0; i < 8; i++) { ts += rs[i]; tss += rss[i]; }
        float mu = ts / D_;
        float var = tss / D_ - mu * mu;
        s_mu = mu;
        s_rstd = rsqrtf(var + EPS);
    }
    __syncthreads();
    float mu = s_mu, rstd = s_rstd;
    for (int i = threadIdx.x; i < D_; i += 256)
        orow[i] = (xr[i] - mu) * rstd * gamma[i] + beta[i];
}

// ---------------------------------------------------------------------------
// Causal softmax: one block per (t, b) row; scores already scaled
// ---------------------------------------------------------------------------
__global__ void __launch_bounds__(256) softmax_causal(float* __restrict__ sc)
{
    const int t = blockIdx.x, b = blockIdx.y;
    float* row = sc + ((size_t)b * T_ + t) * T_;
    const int n = t + 1;

    __shared__ float red[8];
    __shared__ float s_bc;

    float mx = -INFINITY;
    for (int i = threadIdx.x; i < n; i += 256) mx = fmaxf(mx, row[i]);
    #pragma unroll
    for (int o = 16; o > 0; o >>= 1) mx = fmaxf(mx, __shfl_down_sync(0xffffffffu, mx, o));
    int wid = threadIdx.x >> 5, lid = threadIdx.x & 31;
    if (lid == 0) red[wid] = mx;
    __syncthreads();
    if (threadIdx.x == 0) {
        float m = red[0];
        #pragma unroll
        for (int i = 1; i < 8; i++) m = fmaxf(m, red[i]);
        s_bc = m;
    }
    __syncthreads();
    mx = s_bc;

    float sum = 0.f;
    for (int i = threadIdx.x; i < n; i += 256) {
        float e = expf(row[i] - mx);
        row[i] = e;
        sum += e;
    }
    #pragma unroll
    for (int o = 16; o > 0; o >>= 1) sum += __shfl_down_sync(0xffffffffu, sum, o);
    if (lid == 0) red[wid] = sum;
    __syncthreads();
    if (threadIdx.x == 0) {
        float tot = 0.f;
        #pragma unroll
        for (int i = 0; i < 8; i++) tot += red[i];
        s_bc = 1.f / tot;
    }
    __syncthreads();
    float inv = s_bc;
    for (int i = threadIdx.x; i < n; i += 256) row[i] *= inv;
    for (int i = n + threadIdx.x; i < T_; i += 256) row[i] = 0.f;
}

// ---------------------------------------------------------------------------
// SGEMM: C = alpha * A@B (+bias) (+gelu). 128x128x8 tile, 256 thr, 8x8/thr.
// TRANSB=false: B is [K,N] row-major. TRANSB=true: B is [N,K] row-major.
// Batched via blockIdx.z with element strides sA/sB/sC.
// All dims assumed multiples of tile sizes (true for this problem).
// ---------------------------------------------------------------------------
template <bool TRANSB, int EPI>
__global__ void __launch_bounds__(256) sgemm(
    const float* __restrict__ A, const float* __restrict__ Bm,
    const float* __restrict__ bias, float* __restrict__ C,
    int M, int N, int K, int lda, int ldb, int ldc,
    long long sA, long long sB, long long sC, float alpha)
{
    __shared__ float As[8][128];
    __shared__ float Bs[8][128];

    const int bz = blockIdx.z;
    A  += sA * bz;
    Bm += sB * bz;
    C  += sC * bz;

    const int m0 = blockIdx.y * 128;
    const int n0 = blockIdx.x * 128;
    const int tid = threadIdx.x;
    const int tx = tid & 15;       // 0..15  -> n
    const int ty = tid >> 4;       // 0..15  -> m

    float acc[8][8];
    #pragma unroll
    for (int i = 0; i < 8; i++)
        #pragma unroll
        for (int j = 0; j < 8; j++) acc[i][j] = 0.f;

    for (int k0 = 0; k0 < K; k0 += 8) {
        // load A tile: As[k][m]
        #pragma unroll
        for (int i = 0; i < 4; i++) {
            int e = tid + i * 256;
            int m = e >> 3, k = e & 7;
            As[k][m] = A[(size_t)(m0 + m) * lda + (k0 + k)];
        }
        // load B tile: Bs[k][n]
        if (!TRANSB) {
            #pragma unroll
            for (int i = 0; i < 4; i++) {
                int e = tid + i * 256;
                int k = e >> 7, n = e & 127;
                Bs[k][n] = Bm[(size_t)(k0 + k) * ldb + (n0 + n)];
            }
        } else {
            #pragma unroll
            for (int i = 0; i < 4; i++) {
                int e = tid + i * 256;
                int n = e >> 3, k = e & 7;
                Bs[k][n] = Bm[(size_t)(n0 + n) * ldb + (k0 + k)];
            }
        }
        __syncthreads();

        #pragma unroll
        for (int k = 0; k < 8; k++) {
            float ar[8], br[8];
            #pragma unroll
            for (int i = 0; i < 8; i++) ar[i] = As[k][ty * 8 + i];
            #pragma unroll
            for (int j = 0; j < 8; j++) br[j] = Bs[k][tx * 8 + j];
            #pragma unroll
            for (int i = 0; i < 8; i++)
                #pragma unroll
                for (int j = 0; j < 8; j++)
                    acc[i][j] = fmaf(ar[i], br[j], acc[i][j]);
        }
        __syncthreads();
    }

    #pragma unroll
    for (int i = 0; i < 8; i++) {
        int m = m0 + ty * 8 + i;
        #pragma unroll
        for (int j = 0; j < 8; j++) {
            int n = n0 + tx * 8 + j;
            float v = acc[i][j] * alpha + (bias ? bias[n] : 0.f);
            if (EPI == 1) {
                float u = v;
                v = 0.5f * u * (1.f + tanhf(0.7978845608028654f * (u + 0.044715f * u * u * u)));
            }
            C[(size_t)m * ldc + n] = v;
        }
    }
}

// ---------------------------------------------------------------------------
// launch
// ---------------------------------------------------------------------------
extern "C" void kernel_launch(void* const* d_in, const int* in_sizes, int n_in,
                              void* d_out, int out_size)
{
    const float* x     = (const float*)d_in[0];
    const float* ln1_g = (const float*)d_in[1];
    const float* ln1_b = (const float*)d_in[2];
    const float* Wqkv  = (const float*)d_in[3];
    const float* bqkv  = (const float*)d_in[4];
    const float* Wproj = (const float*)d_in[5];
    const float* bproj = (const float*)d_in[6];
    const float* ln2_g = (const float*)d_in[7];
    const float* ln2_b = (const float*)d_in[8];
    const float* W1    = (const float*)d_in[9];
    const float* b1    = (const float*)d_in[10];
    const float* W2    = (const float*)d_in[11];
    const float* b2    = (const float*)d_in[12];
    float* out = (float*)d_out;

    float *p_h, *p_kqv, *p_sc, *p_attn, *p_a, *p_h2, *p_mid;
    cudaGetSymbolAddress((void**)&p_h,    g_h);
    cudaGetSymbolAddress((void**)&p_kqv,  g_kqv);
    cudaGetSymbolAddress((void**)&p_sc,   g_sc);
    cudaGetSymbolAddress((void**)&p_attn, g_attn);
    cudaGetSymbolAddress((void**)&p_a,    g_a);
    cudaGetSymbolAddress((void**)&p_h2,   g_h2);
    cudaGetSymbolAddress((void**)&p_mid,  g_mid);

    const float inv_sqrt_T = 1.0f / sqrtf((float)T_);

    // 1. LN1
    ln_kernel<<<ROWS, 256>>>(x, ln1_g, ln1_b, p_h);

    // 2. QKV GEMM: [8192,1024] @ [1024,3072] + bias
    {
        dim3 grid(3 * D_ / 128, ROWS / 128, 1);
        sgemm<false, 0><<<grid, 256>>>(p_h, Wqkv, bqkv, p_kqv,
                                       ROWS, 3 * D_, D_, D_, 3 * D_, 3 * D_,
                                       0, 0, 0, 1.f);
    }

    // 3. scores = q @ k^T * (1/sqrt(T)), batched over B
    //    kqv layout per row: [k(0:D) | q(D:2D) | v(2D:3D)]
    {
        dim3 grid(T_ / 128, T_ / 128, B_);
        sgemm<true, 0><<<grid, 256>>>(
            p_kqv + D_,              // q
            p_kqv,                   // k
            nullptr, p_sc,
            T_, T_, D_, 3 * D_, 3 * D_, T_,
            (long long)T_ * 3 * D_, (long long)T_ * 3 * D_, (long long)T_ * T_,
            inv_sqrt_T);
    }

    // 4. causal softmax
    {
        dim3 grid(T_, B_);
        softmax_causal<<<grid, 256>>>(p_sc);
    }

    // 5. attn @ v, batched over B
    {
        dim3 grid(D_ / 128, T_ / 128, B_);
        sgemm<false, 0><<<grid, 256>>>(
            p_sc,
            p_kqv + 2 * D_,          // v
            nullptr, p_attn,
            T_, D_, T_, T_, 3 * D_, D_,
            (long long)T_ * T_, (long long)T_ * 3 * D_, (long long)T_ * D_,
            1.f);
    }

    // 6. proj
    {
        dim3 grid(D_ / 128, ROWS / 128, 1);
        sgemm<false, 0><<<grid, 256>>>(p_attn, Wproj, bproj, p_a,
                                       ROWS, D_, D_, D_, D_, D_,
                                       0, 0, 0, 1.f);
    }

    // 7. LN2
    ln_kernel<<<ROWS, 256>>>(p_a, ln2_g, ln2_b, p_h2);

    // 8. MLP up + GELU(tanh)
    {
        dim3 grid(4 * D_ / 128, ROWS / 128, 1);
        sgemm<false, 1><<<grid, 256>>>(p_h2, W1, b1, p_mid,
                                       ROWS, 4 * D_, D_, D_, 4 * D_, 4 * D_,
                                       0, 0, 0, 1.f);
    }

    // 9. MLP down -> output
    {
        dim3 grid(D_ / 128, ROWS / 128, 1);
        sgemm<false, 0><<<grid, 256>>>(p_mid, W2, b2, out,
                                       ROWS, D_, 4 * D_, 4 * D_, D_, D_,
                                       0, 0, 0, 1.f);
    }
}

// round 3
// speedup vs baseline: 2.0262x; 2.0262x over previous
#include <cuda_runtime.h>
#include <cuda_bf16.h>
#include <math.h>
#include <stdint.h>

// Problem constants
#define B_ 4
#define T_ 2048
#define D_ 1024
#define ROWS (B_ * T_)        // 8192
#define EPS 1e-5f

// Scratch (allocation-free: __device__ globals)
__device__ float g_h    [ROWS * D_];
__device__ float g_kqv  [ROWS * 3 * D_];
__device__ float g_sc   [(size_t)B_ * T_ * T_];
__device__ float g_attn [ROWS * D_];
__device__ float g_a    [ROWS * D_];
__device__ float g_h2   [ROWS * D_];
__device__ float g_mid  [ROWS * 4 * D_];
__device__ float g_vT   [(size_t)B_ * D_ * T_];     // V^T per batch [D][T]
__device__ float g_WqkvT[3 * D_ * D_];
__device__ float g_WprojT[D_ * D_];
__device__ float g_W1T  [4 * D_ * D_];
__device__ float g_W2T  [D_ * 4 * D_];

// ---------------------------------------------------------------------------
// mma.sync bf16 helper (base PTX, sm_80+, legal on compute_103)
// ---------------------------------------------------------------------------
__device__ __forceinline__ void mma_bf16(float* d, const uint32_t* a, const uint32_t* b) {
    asm volatile(
        "mma.sync.aligned.m16n8k16.row.col.f32.bf16.bf16.f32 "
        "{%0,%1,%2,%3}, {%4,%5,%6,%7}, {%8,%9}, {%0,%1,%2,%3};"
        : "+f"(d[0]), "+f"(d[1]), "+f"(d[2]), "+f"(d[3])
        : "r"(a[0]), "r"(a[1]), "r"(a[2]), "r"(a[3]),
          "r"(b[0]), "r"(b[1]));
}

__device__ __forceinline__ uint32_t pack_bf16(__nv_bfloat16 lo, __nv_bfloat16 hi) {
    return (uint32_t)__bfloat16_as_ushort(lo) | ((uint32_t)__bfloat16_as_ushort(hi) << 16);
}

// SMEM tile: 128 rows x 32 cols bf16, row stride 40 elems (80B) -> conflict-free
#define LDS_STRIDE 40

__device__ __forceinline__ uint32_t lds2(const __nv_bfloat16* base, int row, int col) {
    return *(const uint32_t*)(base + row * LDS_STRIDE + col);
}

// split one float4 into bf16 hi/lo packed pairs and store (8B each)
__device__ __forceinline__ void split_store(
    __nv_bfloat16* Hh, __nv_bfloat16* Hl, int row, int col4, float4 v)
{
    __nv_bfloat16 h0 = __float2bfloat16_rn(v.x);
    __nv_bfloat16 h1 = __float2bfloat16_rn(v.y);
    __nv_bfloat16 h2 = __float2bfloat16_rn(v.z);
    __nv_bfloat16 h3 = __float2bfloat16_rn(v.w);
    __nv_bfloat16 l0 = __float2bfloat16_rn(v.x - __bfloat162float(h0));
    __nv_bfloat16 l1 = __float2bfloat16_rn(v.y - __bfloat162float(h1));
    __nv_bfloat16 l2 = __float2bfloat16_rn(v.z - __bfloat162float(h2));
    __nv_bfloat16 l3 = __float2bfloat16_rn(v.w - __bfloat162float(h3));
    uint2 ph = make_uint2(pack_bf16(h0, h1), pack_bf16(h2, h3));
    uint2 pl = make_uint2(pack_bf16(l0, l1), pack_bf16(l2, l3));
    *(uint2*)(Hh + row * LDS_STRIDE + col4) = ph;
    *(uint2*)(Hl + row * LDS_STRIDE + col4) = pl;
}

// ---------------------------------------------------------------------------
// bf16 3-pass NT GEMM: C[M,N] = alpha*(A[M,K] @ B[N,K]^T) (+bias)(+gelu)
// 128x128 CTA tile, 8 warps (64x32 warp tile), K chunk 32.
// CMODE: 0=dense, 1=causal block skip (bx>by), 2=causal K clip
// ---------------------------------------------------------------------------
template <int EPI, int CMODE>
__global__ void __launch_bounds__(256) gemm_mma(
    const float* __restrict__ A, const float* __restrict__ Bm,
    const float* __restrict__ bias, float* __restrict__ C,
    int K, int lda, int ldb, int ldc,
    long long sA, long long sB, long long sC, float alpha)
{
    const int bx = blockIdx.x, by = blockIdx.y, bz = blockIdx.z;
    if (CMODE == 1 && bx > by) return;

    __shared__ __align__(16) __nv_bfloat16 Ah[128 * LDS_STRIDE];
    __shared__ __align__(16) __nv_bfloat16 Al[128 * LDS_STRIDE];
    __shared__ __align__(16) __nv_bfloat16 Bh[128 * LDS_STRIDE];
    __shared__ __align__(16) __nv_bfloat16 Bl[128 * LDS_STRIDE];

    A  += sA * bz;
    Bm += sB * bz;
    C  += sC * bz;
    const int m0 = by * 128, n0 = bx * 128;
    int Kend = K;
    if (CMODE == 2) { int ke = (by + 1) * 128; if (ke < K) Kend = ke; }
    const int NC = Kend >> 5;

    const int tid = threadIdx.x;
    const int wid = tid >> 5, lane = tid & 31;
    const int wm = wid & 1, wn = wid >> 1;       // warp grid 2(m) x 4(n)
    const int g = lane >> 2, tig = lane & 3;

    float acc[4][4][4];
    #pragma unroll
    for (int i = 0; i < 4; i++)
        #pragma unroll
        for (int j = 0; j < 4; j++)
            #pragma unroll
            for (int r = 0; r < 4; r++) acc[i][j][r] = 0.f;

    // loader indices: 4 float4 per thread per tile
    const int lr = tid >> 3;        // 0..31 base row (x4 via i)
    const int lq = tid & 7;         // 0..7 -> col4 = lq*4

    for (int kc = 0; kc < NC; kc++) {
        const float* Ag = A + (size_t)m0 * lda + (size_t)kc * 32;
        const float* Bg = Bm + (size_t)n0 * ldb + (size_t)kc * 32;
        #pragma unroll
        for (int i = 0; i < 4; i++) {
            int r = lr + i * 32;
            float4 va = __ldg((const float4*)(Ag + (size_t)r * lda + lq * 4));
            split_store(Ah, Al, r, lq * 4, va);
            float4 vb = __ldg((const float4*)(Bg + (size_t)r * ldb + lq * 4));
            split_store(Bh, Bl, r, lq * 4, vb);
        }
        __syncthreads();

        #pragma unroll
        for (int kk = 0; kk < 32; kk += 16) {
            uint32_t af[4][4], bh[4][2], bl[4][2];
            #pragma unroll
            for (int mt = 0; mt < 4; mt++) {
                int row = wm * 64 + mt * 16 + g;
                int col = kk + tig * 2;
                af[mt][0] = lds2(Ah, row,     col);
                af[mt][1] = lds2(Ah, row + 8, col);
                af[mt][2] = lds2(Ah, row,     col + 8);
                af[mt][3] = lds2(Ah, row + 8, col + 8);
            }
            #pragma unroll
            for (int nt = 0; nt < 4; nt++) {
                int rn = wn * 32 + nt * 8 + g;
                int col = kk + tig * 2;
                bh[nt][0] = lds2(Bh, rn, col);
                bh[nt][1] = lds2(Bh, rn, col + 8);
            }
            // pass 1: Ah x Bh
            #pragma unroll
            for (int mt = 0; mt < 4; mt++)
                #pragma unroll
                for (int nt = 0; nt < 4; nt++)
                    mma_bf16(acc[mt][nt], af[mt], bh[nt]);
            // pass 2: Ah x Bl
            #pragma unroll
            for (int nt = 0; nt < 4; nt++) {
                int rn = wn * 32 + nt * 8 + g;
                int col = kk + tig * 2;
                bl[nt][0] = lds2(Bl, rn, col);
                bl[nt][1] = lds2(Bl, rn, col + 8);
            }
            #pragma unroll
            for (int mt = 0; mt < 4; mt++)
                #pragma unroll
                for (int nt = 0; nt < 4; nt++)
                    mma_bf16(acc[mt][nt], af[mt], bl[nt]);
            // pass 3: Al x Bh (reuse af regs)
            #pragma unroll
            for (int mt = 0; mt < 4; mt++) {
                int row = wm * 64 + mt * 16 + g;
                int col = kk + tig * 2;
                af[mt][0] = lds2(Al, row,     col);
                af[mt][1] = lds2(Al, row + 8, col);
                af[mt][2] = lds2(Al, row,     col + 8);
                af[mt][3] = lds2(Al, row + 8, col + 8);
            }
            #pragma unroll
            for (int mt = 0; mt < 4; mt++)
                #pragma unroll
                for (int nt = 0; nt < 4; nt++)
                    mma_bf16(acc[mt][nt], af[mt], bh[nt]);
        }
        __syncthreads();
    }

    // epilogue
    #pragma unroll
    for (int mt = 0; mt < 4; mt++) {
        #pragma unroll
        for (int nt = 0; nt < 4; nt++) {
            int m = m0 + wm * 64 + mt * 16 + g;
            int n = n0 + wn * 32 + nt * 8 + tig * 2;
            float2 bv = make_float2(0.f, 0.f);
            if (bias) bv = __ldg((const float2*)(bias + n));
            #pragma unroll
            for (int half = 0; half < 2; half++) {
                float vx = acc[mt][nt][half * 2 + 0] * alpha + bv.x;
                float vy = acc[mt][nt][half * 2 + 1] * alpha + bv.y;
                if (EPI == 1) {
                    const float c0 = 0.7978845608028654f, c1 = 0.044715f;
                    vx = 0.5f * vx * (1.f + tanhf(c0 * (vx + c1 * vx * vx * vx)));
                    vy = 0.5f * vy * (1.f + tanhf(c0 * (vy + c1 * vy * vy * vy)));
                }
                *(float2*)(C + (size_t)(m + half * 8) * ldc + n) = make_float2(vx, vy);
            }
        }
    }
}

// ---------------------------------------------------------------------------
// Transpose: out[c][r] = in[r][c], tiles 32x32, block (32,8). Batched.
// ---------------------------------------------------------------------------
__global__ void __launch_bounds__(256) transpose_k(
    const float* __restrict__ in, float* __restrict__ out,
    int ldi, int ldo, long long sI, long long sO)
{
    __shared__ float t[32][33];
    in  += sI * blockIdx.z;
    out += sO * blockIdx.z;
    const int c0 = blockIdx.x * 32, r0 = blockIdx.y * 32;
    const int x = threadIdx.x, y = threadIdx.y;
    #pragma unroll
    for (int i = 0; i < 4; i++)
        t[y + i * 8][x] = in[(size_t)(r0 + y + i * 8) * ldi + c0 + x];
    __syncthreads();
    #pragma unroll
    for (int i = 0; i < 4; i++)
        out[(size_t)(c0 + y + i * 8) * ldo + r0 + x] = t[x][y + i * 8];
}

// ---------------------------------------------------------------------------
// LayerNorm: one block per row, 256 threads
// ---------------------------------------------------------------------------
__global__ void __launch_bounds__(256) ln_kernel(
    const float* __restrict__ x, const float* __restrict__ gamma,
    const float* __restrict__ beta, float* __restrict__ out)
{
    const int row = blockIdx.x;
    const float* xr = x + (size_t)row * D_;
    float* orow = out + (size_t)row * D_;

    float s = 0.f, ss = 0.f;
    for (int i = threadIdx.x; i < D_; i += 256) {
        float v = xr[i];
        s += v; ss += v * v;
    }
    __shared__ float rs[8], rss[8];
    #pragma unroll
    for (int o = 16; o > 0; o >>= 1) {
        s  += __shfl_down_sync(0xffffffffu, s,  o);
        ss += __shfl_down_sync(0xffffffffu, ss, o);
    }
    int wid = threadIdx.x >> 5, lid = threadIdx.x & 31;
    if (lid == 0) { rs[wid] = s; rss[wid] = ss; }
    __syncthreads();
    __shared__ float s_mu, s_rstd;
    if (threadIdx.x == 0) {
        float ts = 0.f, tss = 0.f;
        #pragma unroll
        for (int i = 0; i < 8; i++) { ts += rs[i]; tss += rss[i]; }
        float mu = ts / D_;
        float var = tss / D_ - mu * mu;
        s_mu = mu;
        s_rstd = rsqrtf(var + EPS);
    }
    __syncthreads();
    float mu = s_mu, rstd = s_rstd;
    for (int i = threadIdx.x; i < D_; i += 256)
        orow[i] = (xr[i] - mu) * rstd * gamma[i] + beta[i];
}

// ---------------------------------------------------------------------------
// Causal softmax
// ---------------------------------------------------------------------------
__global__ void __launch_bounds__(256) softmax_causal(float* __restrict__ sc)
{
    const int t = blockIdx.x, b = blockIdx.y;
    float* row = sc + ((size_t)b * T_ + t) * T_;
    const int n = t + 1;

    __shared__ float red[8];
    __shared__ float s_bc;

    float mx = -INFINITY;
    for (int i = threadIdx.x; i < n; i += 256) mx = fmaxf(mx, row[i]);
    #pragma unroll
    for (int o = 16; o > 0; o >>= 1) mx = fmaxf(mx, __shfl_down_sync(0xffffffffu, mx, o));
    int wid = threadIdx.x >> 5, lid = threadIdx.x & 31;
    if (lid == 0) red[wid] = mx;
    __syncthreads();
    if (threadIdx.x == 0) {
        float m = red[0];
        #pragma unroll
        for (int i = 1; i < 8; i++) m = fmaxf(m, red[i]);
        s_bc = m;
    }
    __syncthreads();
    mx = s_bc;

    float sum = 0.f;
    for (int i = threadIdx.x; i < n; i += 256) {
        float e = expf(row[i] - mx);
        row[i] = e;
        sum += e;
    }
    #pragma unroll
    for (int o = 16; o > 0; o >>= 1) sum += __shfl_down_sync(0xffffffffu, sum, o);
    if (lid == 0) red[wid] = sum;
    __syncthreads();
    if (threadIdx.x == 0) {
        float tot = 0.f;
        #pragma unroll
        for (int i = 0; i < 8; i++) tot += red[i];
        s_bc = 1.f / tot;
    }
    __syncthreads();
    float inv = s_bc;
    for (int i = threadIdx.x; i < n; i += 256) row[i] *= inv;
    for (int i = n + threadIdx.x; i < T_; i += 256) row[i] = 0.f;
}

// ---------------------------------------------------------------------------
// launch
// ---------------------------------------------------------------------------
extern "C" void kernel_launch(void* const* d_in, const int* in_sizes, int n_in,
                              void* d_out, int out_size)
{
    const float* x     = (const float*)d_in[0];
    const float* ln1_g = (const float*)d_in[1];
    const float* ln1_b = (const float*)d_in[2];
    const float* Wqkv  = (const float*)d_in[3];
    const float* bqkv  = (const float*)d_in[4];
    const float* Wproj = (const float*)d_in[5];
    const float* bproj = (const float*)d_in[6];
    const float* ln2_g = (const float*)d_in[7];
    const float* ln2_b = (const float*)d_in[8];
    const float* W1    = (const float*)d_in[9];
    const float* b1    = (const float*)d_in[10];
    const float* W2    = (const float*)d_in[11];
    const float* b2    = (const float*)d_in[12];
    float* out = (float*)d_out;

    float *p_h, *p_kqv, *p_sc, *p_attn, *p_a, *p_h2, *p_mid, *p_vT;
    float *p_WqkvT, *p_WprojT, *p_W1T, *p_W2T;
    cudaGetSymbolAddress((void**)&p_h,     g_h);
    cudaGetSymbolAddress((void**)&p_kqv,   g_kqv);
    cudaGetSymbolAddress((void**)&p_sc,    g_sc);
    cudaGetSymbolAddress((void**)&p_attn,  g_attn);
    cudaGetSymbolAddress((void**)&p_a,     g_a);
    cudaGetSymbolAddress((void**)&p_h2,    g_h2);
    cudaGetSymbolAddress((void**)&p_mid,   g_mid);
    cudaGetSymbolAddress((void**)&p_vT,    g_vT);
    cudaGetSymbolAddress((void**)&p_WqkvT, g_WqkvT);
    cudaGetSymbolAddress((void**)&p_WprojT, g_WprojT);
    cudaGetSymbolAddress((void**)&p_W1T,   g_W1T);
    cudaGetSymbolAddress((void**)&p_W2T,   g_W2T);

    const float inv_sqrt_T = 1.0f / sqrtf((float)T_);
    dim3 tb(32, 8);

    // Weight transposes (to NT form)
    transpose_k<<<dim3(3 * D_ / 32, D_ / 32, 1), tb>>>(Wqkv,  p_WqkvT,  3 * D_, D_,     0, 0);
    transpose_k<<<dim3(D_ / 32,     D_ / 32, 1), tb>>>(Wproj, p_WprojT, D_,     D_,     0, 0);
    transpose_k<<<dim3(4 * D_ / 32, D_ / 32, 1), tb>>>(W1,    p_W1T,    4 * D_, D_,     0, 0);
    transpose_k<<<dim3(D_ / 32, 4 * D_ / 32, 1), tb>>>(W2,    p_W2T,    D_,     4 * D_, 0, 0);

    // 1. LN1
    ln_kernel<<<ROWS, 256>>>(x, ln1_g, ln1_b, p_h);

    // 2. QKV
    gemm_mma<0, 0><<<dim3(3 * D_ / 128, ROWS / 128, 1), 256>>>(
        p_h, p_WqkvT, bqkv, p_kqv, D_, D_, D_, 3 * D_, 0, 0, 0, 1.f);

    // 3. V^T per batch
    transpose_k<<<dim3(D_ / 32, T_ / 32, B_), tb>>>(
        p_kqv + 2 * D_, p_vT, 3 * D_, T_,
        (long long)T_ * 3 * D_, (long long)D_ * T_);

    // 4. scores = q @ k^T * inv_sqrt_T (lower-triangular blocks only)
    gemm_mma<0, 1><<<dim3(T_ / 128, T_ / 128, B_), 256>>>(
        p_kqv + D_, p_kqv, nullptr, p_sc, D_, 3 * D_, 3 * D_, T_,
        (long long)T_ * 3 * D_, (long long)T_ * 3 * D_, (long long)T_ * T_, inv_sqrt_T);

    // 5. softmax
    softmax_causal<<<dim3(T_, B_), 256>>>(p_sc);

    // 6. attn @ v  (K clipped to causal extent)
    gemm_mma<0, 2><<<dim3(D_ / 128, T_ / 128, B_), 256>>>(
        p_sc, p_vT, nullptr, p_attn, T_, T_, T_, D_,
        (long long)T_ * T_, (long long)D_ * T_, (long long)T_ * D_, 1.f);

    // 7. proj
    gemm_mma<0, 0><<<dim3(D_ / 128, ROWS / 128, 1), 256>>>(
        p_attn, p_WprojT, bproj, p_a, D_, D_, D_, D_, 0, 0, 0, 1.f);

    // 8. LN2
    ln_kernel<<<ROWS, 256>>>(p_a, ln2_g, ln2_b, p_h2);

    // 9. MLP up + GELU
    gemm_mma<1, 0><<<dim3(4 * D_ / 128, ROWS / 128, 1), 256>>>(
        p_h2, p_W1T, b1, p_mid, D_, D_, D_, 4 * D_, 0, 0, 0, 1.f);

    // 10. MLP down -> out
    gemm_mma<0, 0><<<dim3(D_ / 128, ROWS / 128, 1), 256>>>(
        p_mid, p_W2T, b2, out, 4 * D_, 4 * D_, 4 * D_, D_, 0, 0, 0, 1.f);
}

// round 4
// speedup vs baseline: 2.6746x; 1.3200x over previous
#include <cuda_runtime.h>
#include <cuda_bf16.h>
#include <math.h>
#include <stdint.h>

// Problem constants
#define B_ 4
#define T_ 2048
#define D_ 1024
#define ROWS (B_ * T_)        // 8192
#define EPS 1e-5f

typedef __nv_bfloat16 bf16;

// ---------------------------------------------------------------------------
// Scratch (allocation-free: __device__ globals)
// ---------------------------------------------------------------------------
__device__ float g_sc [(size_t)B_ * T_ * T_];   // fp32 scores
__device__ float g_a  [ROWS * D_];              // fp32 proj out (LN2 input)

__device__ bf16 g_h_hi   [ROWS * D_],      g_h_lo   [ROWS * D_];
__device__ bf16 g_kqv_hi [ROWS * 3 * D_],  g_kqv_lo [ROWS * 3 * D_];
__device__ bf16 g_p_hi   [(size_t)B_ * T_ * T_], g_p_lo [(size_t)B_ * T_ * T_];
__device__ bf16 g_vT_hi  [(size_t)B_ * D_ * T_], g_vT_lo [(size_t)B_ * D_ * T_];
__device__ bf16 g_at_hi  [ROWS * D_],      g_at_lo  [ROWS * D_];
__device__ bf16 g_h2_hi  [ROWS * D_],      g_h2_lo  [ROWS * D_];
__device__ bf16 g_mid_hi [ROWS * 4 * D_],  g_mid_lo [ROWS * 4 * D_];
__device__ bf16 g_Wqkv_hi[3 * D_ * D_],    g_Wqkv_lo[3 * D_ * D_];
__device__ bf16 g_Wprj_hi[D_ * D_],        g_Wprj_lo[D_ * D_];
__device__ bf16 g_W1_hi  [4 * D_ * D_],    g_W1_lo  [4 * D_ * D_];
__device__ bf16 g_W2_hi  [D_ * 4 * D_],    g_W2_lo  [D_ * 4 * D_];

// ---------------------------------------------------------------------------
// helpers
// ---------------------------------------------------------------------------
__device__ __forceinline__ void split1(float v, bf16& h, bf16& l) {
    h = __float2bfloat16_rn(v);
    l = __float2bfloat16_rn(v - __bfloat162float(h));
}
__device__ __forceinline__ uint32_t pack2(bf16 a, bf16 b) {
    return (uint32_t)__bfloat16_as_ushort(a) | ((uint32_t)__bfloat16_as_ushort(b) << 16);
}
__device__ __forceinline__ void mma_bf16(float* d, const uint32_t* a, const uint32_t* b) {
    asm volatile(
        "mma.sync.aligned.m16n8k16.row.col.f32.bf16.bf16.f32 "
        "{%0,%1,%2,%3}, {%4,%5,%6,%7}, {%8,%9}, {%0,%1,%2,%3};"
        : "+f"(d[0]), "+f"(d[1]), "+f"(d[2]), "+f"(d[3])
        : "r"(a[0]), "r"(a[1]), "r"(a[2]), "r"(a[3]),
          "r"(b[0]), "r"(b[1]));
}
__device__ __forceinline__ uint32_t smem_u32(const void* p) {
    uint32_t a;
    asm("{ .reg .u64 t; cvta.to.shared.u64 t, %1; cvt.u32.u64 %0, t; }" : "=r"(a) : "l"(p));
    return a;
}
__device__ __forceinline__ void cp16(uint32_t dst, const void* src) {
    asm volatile("cp.async.ca.shared.global [%0], [%1], 16;" :: "r"(dst), "l"(src));
}
#define CP_COMMIT() asm volatile("cp.async.commit_group;" ::: "memory")
#define CP_WAIT(n)  asm volatile("cp.async.wait_group %0;" :: "n"(n) : "memory")

// SMEM tile geometry: 128 rows x 32 bf16, row stride 40 elems (80B)
#define LDS_STRIDE 40
#define TILE_ELEMS (128 * LDS_STRIDE)          // 5120 elems = 10240 B
#define STAGE_ELEMS (4 * TILE_ELEMS)           // 20480 elems = 40960 B
#define SMEM_BYTES (2 * STAGE_ELEMS * 2)       // 81920 B

__device__ __forceinline__ uint32_t lds2(const bf16* base, int row, int col) {
    return *(const uint32_t*)(base + row * LDS_STRIDE + col);
}

// ---------------------------------------------------------------------------
// GEMM: C[M,N] = alpha*(A @ B^T) (+bias), A/B pre-split bf16 hi/lo (NT, K-major)
// 128x128 CTA tile, 8 warps (64x32), K chunk 32, cp.async double buffered.
// EPI: 0=fp32 out, 1=split out, 2=gelu+split out
// CMODE: 0=dense, 1=causal block skip, 2=causal K clip
// ---------------------------------------------------------------------------
template <int EPI, int CMODE>
__global__ void __launch_bounds__(256) gemm_cs(
    const bf16* __restrict__ Ahi, const bf16* __restrict__ Alo,
    const bf16* __restrict__ Bhi, const bf16* __restrict__ Blo,
    const float* __restrict__ bias,
    float* __restrict__ Cf, bf16* __restrict__ Chi, bf16* __restrict__ Clo,
    int K, int lda, int ldb, int ldc,
    long long sA, long long sB, long long sC, float alpha)
{
    const int bx = blockIdx.x, by = blockIdx.y, bz = blockIdx.z;
    if (CMODE == 1 && bx > by) return;

    extern __shared__ bf16 smem[];
    const uint32_t sb = smem_u32(smem);

    Ahi += sA * bz; Alo += sA * bz;
    Bhi += sB * bz; Blo += sB * bz;

    const int m0 = by * 128, n0 = bx * 128;
    int Kend = K;
    if (CMODE == 2) { int ke = (by + 1) * 128; if (ke < K) Kend = ke; }
    const int NC = Kend >> 5;

    const int tid = threadIdx.x;
    const int wid = tid >> 5, lane = tid & 31;
    const int wm = wid & 1, wn = wid >> 1;
    const int g = lane >> 2, tig = lane & 3;

    // loader: thread covers one row, 2 of 4 16B chunks, for each of 4 tiles
    const int lrow = tid >> 1;
    const int lc   = (tid & 1) * 2;      // chunk base (each chunk = 8 elems)

    const bf16* pA_hi = Ahi + (size_t)(m0 + lrow) * lda + lc * 8;
    const bf16* pA_lo = Alo + (size_t)(m0 + lrow) * lda + lc * 8;
    const bf16* pB_hi = Bhi + (size_t)(n0 + lrow) * ldb + lc * 8;
    const bf16* pB_lo = Blo + (size_t)(n0 + lrow) * ldb + lc * 8;
    const uint32_t dbase = sb + lrow * 80 + lc * 16;

    auto issue = [&](int kc, int buf) {
        const uint32_t d0 = dbase + buf * (STAGE_ELEMS * 2);
        const int ko = kc * 32;
        cp16(d0,                 pA_hi + ko);
        cp16(d0 + 16,            pA_hi + ko + 8);
        cp16(d0 + 10240,         pA_lo + ko);
        cp16(d0 + 10240 + 16,    pA_lo + ko + 8);
        cp16(d0 + 20480,         pB_hi + ko);
        cp16(d0 + 20480 + 16,    pB_hi + ko + 8);
        cp16(d0 + 30720,         pB_lo + ko);
        cp16(d0 + 30720 + 16,    pB_lo + ko + 8);
    };

    float acc[4][4][4];
    #pragma unroll
    for (int i = 0; i < 4; i++)
        #pragma unroll
        for (int j = 0; j < 4; j++)
            #pragma unroll
            for (int r = 0; r < 4; r++) acc[i][j][r] = 0.f;

    issue(0, 0);
    CP_COMMIT();

    int buf = 0;
    for (int kc = 0; kc < NC; kc++) {
        if (kc + 1 < NC) {
            issue(kc + 1, buf ^ 1);
            CP_COMMIT();
            CP_WAIT(1);
        } else {
            CP_WAIT(0);
        }
        __syncthreads();

        const bf16* sAh = smem + buf * STAGE_ELEMS;
        const bf16* sAl = sAh + TILE_ELEMS;
        const bf16* sBh = sAh + 2 * TILE_ELEMS;
        const bf16* sBl = sAh + 3 * TILE_ELEMS;

        #pragma unroll
        for (int kk = 0; kk < 32; kk += 16) {
            uint32_t af[4][4], bh[4][2], bl[4][2];
            #pragma unroll
            for (int mt = 0; mt < 4; mt++) {
                int row = wm * 64 + mt * 16 + g;
                int col = kk + tig * 2;
                af[mt][0] = lds2(sAh, row,     col);
                af[mt][1] = lds2(sAh, row + 8, col);
                af[mt][2] = lds2(sAh, row,     col + 8);
                af[mt][3] = lds2(sAh, row + 8, col + 8);
            }
            #pragma unroll
            for (int nt = 0; nt < 4; nt++) {
                int rn = wn * 32 + nt * 8 + g;
                int col = kk + tig * 2;
                bh[nt][0] = lds2(sBh, rn, col);
                bh[nt][1] = lds2(sBh, rn, col + 8);
            }
            #pragma unroll
            for (int mt = 0; mt < 4; mt++)
                #pragma unroll
                for (int nt = 0; nt < 4; nt++)
                    mma_bf16(acc[mt][nt], af[mt], bh[nt]);
            #pragma unroll
            for (int nt = 0; nt < 4; nt++) {
                int rn = wn * 32 + nt * 8 + g;
                int col = kk + tig * 2;
                bl[nt][0] = lds2(sBl, rn, col);
                bl[nt][1] = lds2(sBl, rn, col + 8);
            }
            #pragma unroll
            for (int mt = 0; mt < 4; mt++)
                #pragma unroll
                for (int nt = 0; nt < 4; nt++)
                    mma_bf16(acc[mt][nt], af[mt], bl[nt]);
            #pragma unroll
            for (int mt = 0; mt < 4; mt++) {
                int row = wm * 64 + mt * 16 + g;
                int col = kk + tig * 2;
                af[mt][0] = lds2(sAl, row,     col);
                af[mt][1] = lds2(sAl, row + 8, col);
                af[mt][2] = lds2(sAl, row,     col + 8);
                af[mt][3] = lds2(sAl, row + 8, col + 8);
            }
            #pragma unroll
            for (int mt = 0; mt < 4; mt++)
                #pragma unroll
                for (int nt = 0; nt < 4; nt++)
                    mma_bf16(acc[mt][nt], af[mt], bh[nt]);
        }
        __syncthreads();
        buf ^= 1;
    }

    // epilogue
    if (EPI == 0) Cf += sC * bz;
    else { Chi += sC * bz; Clo += sC * bz; }

    #pragma unroll
    for (int mt = 0; mt < 4; mt++) {
        #pragma unroll
        for (int nt = 0; nt < 4; nt++) {
            int m = m0 + wm * 64 + mt * 16 + g;
            int n = n0 + wn * 32 + nt * 8 + tig * 2;
            float2 bv = make_float2(0.f, 0.f);
            if (bias) bv = __ldg((const float2*)(bias + n));
            #pragma unroll
            for (int half = 0; half < 2; half++) {
                float vx = acc[mt][nt][half * 2 + 0] * alpha + bv.x;
                float vy = acc[mt][nt][half * 2 + 1] * alpha + bv.y;
                if (EPI == 2) {
                    const float c0 = 0.7978845608028654f, c1 = 0.044715f;
                    vx = 0.5f * vx * (1.f + tanhf(c0 * (vx + c1 * vx * vx * vx)));
                    vy = 0.5f * vy * (1.f + tanhf(c0 * (vy + c1 * vy * vy * vy)));
                }
                size_t off = (size_t)(m + half * 8) * ldc + n;
                if (EPI == 0) {
                    *(float2*)(Cf + off) = make_float2(vx, vy);
                } else {
                    bf16 hx, lx, hy, ly;
                    split1(vx, hx, lx);
                    split1(vy, hy, ly);
                    *(uint32_t*)(Chi + off) = pack2(hx, hy);
                    *(uint32_t*)(Clo + off) = pack2(lx, ly);
                }
            }
        }
    }
}

// ---------------------------------------------------------------------------
// Weight transpose + split: out_hi/lo[c][r] = split(in[r][c])
// ---------------------------------------------------------------------------
__global__ void __launch_bounds__(256) transpose_split_f32(
    const float* __restrict__ in, bf16* __restrict__ ohi, bf16* __restrict__ olo,
    int ldi, int ldo)
{
    __shared__ float t[32][33];
    const int c0 = blockIdx.x * 32, r0 = blockIdx.y * 32;
    const int x = threadIdx.x, y = threadIdx.y;
    #pragma unroll
    for (int i = 0; i < 4; i++)
        t[y + i * 8][x] = in[(size_t)(r0 + y + i * 8) * ldi + c0 + x];
    __syncthreads();
    #pragma unroll
    for (int i = 0; i < 4; i++) {
        float v = t[x][y + i * 8];
        bf16 h, l;
        split1(v, h, l);
        size_t off = (size_t)(c0 + y + i * 8) * ldo + r0 + x;
        ohi[off] = h;
        olo[off] = l;
    }
}

// ---------------------------------------------------------------------------
// bf16 pair transpose (for V -> V^T), batched
// ---------------------------------------------------------------------------
__global__ void __launch_bounds__(256) transpose_bf16_pair(
    const bf16* __restrict__ ihi, const bf16* __restrict__ ilo,
    bf16* __restrict__ ohi, bf16* __restrict__ olo,
    int ldi, int ldo, long long sI, long long sO)
{
    __shared__ bf16 th[32][33], tl[32][33];
    ihi += sI * blockIdx.z; ilo += sI * blockIdx.z;
    ohi += sO * blockIdx.z; olo += sO * blockIdx.z;
    const int c0 = blockIdx.x * 32, r0 = blockIdx.y * 32;
    const int x = threadIdx.x, y = threadIdx.y;
    #pragma unroll
    for (int i = 0; i < 4; i++) {
        size_t off = (size_t)(r0 + y + i * 8) * ldi + c0 + x;
        th[y + i * 8][x] = ihi[off];
        tl[y + i * 8][x] = ilo[off];
    }
    __syncthreads();
    #pragma unroll
    for (int i = 0; i < 4; i++) {
        size_t off = (size_t)(c0 + y + i * 8) * ldo + r0 + x;
        ohi[off] = th[x][y + i * 8];
        olo[off] = tl[x][y + i * 8];
    }
}

// ---------------------------------------------------------------------------
// LayerNorm -> split bf16 out
// ---------------------------------------------------------------------------
__global__ void __launch_bounds__(256) ln_split(
    const float* __restrict__ x, const float* __restrict__ gamma,
    const float* __restrict__ beta,
    bf16* __restrict__ ohi, bf16* __restrict__ olo)
{
    const int row = blockIdx.x;
    const float* xr = x + (size_t)row * D_;

    float s = 0.f, ss = 0.f;
    for (int i = threadIdx.x; i < D_; i += 256) {
        float v = xr[i];
        s += v; ss += v * v;
    }
    __shared__ float rs[8], rss[8];
    #pragma unroll
    for (int o = 16; o > 0; o >>= 1) {
        s  += __shfl_down_sync(0xffffffffu, s,  o);
        ss += __shfl_down_sync(0xffffffffu, ss, o);
    }
    int wid = threadIdx.x >> 5, lid = threadIdx.x & 31;
    if (lid == 0) { rs[wid] = s; rss[wid] = ss; }
    __syncthreads();
    __shared__ float s_mu, s_rstd;
    if (threadIdx.x == 0) {
        float ts = 0.f, tss = 0.f;
        #pragma unroll
        for (int i = 0; i < 8; i++) { ts += rs[i]; tss += rss[i]; }
        float mu = ts / D_;
        float var = tss / D_ - mu * mu;
        s_mu = mu;
        s_rstd = rsqrtf(var + EPS);
    }
    __syncthreads();
    float mu = s_mu, rstd = s_rstd;
    for (int i = threadIdx.x; i < D_; i += 256) {
        float v = (xr[i] - mu) * rstd * gamma[i] + beta[i];
        bf16 h, l;
        split1(v, h, l);
        ohi[(size_t)row * D_ + i] = h;
        olo[(size_t)row * D_ + i] = l;
    }
}

// ---------------------------------------------------------------------------
// Causal softmax: fp32 scores in -> split bf16 probs out (zeros above diag)
// ---------------------------------------------------------------------------
__global__ void __launch_bounds__(256) softmax_split(
    const float* __restrict__ sc, bf16* __restrict__ phi, bf16* __restrict__ plo)
{
    const int t = blockIdx.x, b = blockIdx.y;
    const size_t ro = ((size_t)b * T_ + t) * T_;
    const float* row = sc + ro;
    const int n = t + 1;

    __shared__ float red[8];
    __shared__ float s_bc;

    float mx = -INFINITY;
    for (int i = threadIdx.x; i < n; i += 256) mx = fmaxf(mx, row[i]);
    #pragma unroll
    for (int o = 16; o > 0; o >>= 1) mx = fmaxf(mx, __shfl_down_sync(0xffffffffu, mx, o));
    int wid = threadIdx.x >> 5, lid = threadIdx.x & 31;
    if (lid == 0) red[wid] = mx;
    __syncthreads();
    if (threadIdx.x == 0) {
        float m = red[0];
        #pragma unroll
        for (int i = 1; i < 8; i++) m = fmaxf(m, red[i]);
        s_bc = m;
    }
    __syncthreads();
    mx = s_bc;

    float sum = 0.f;
    for (int i = threadIdx.x; i < n; i += 256) sum += expf(row[i] - mx);
    #pragma unroll
    for (int o = 16; o > 0; o >>= 1) sum += __shfl_down_sync(0xffffffffu, sum, o);
    if (lid == 0) red[wid] = sum;
    __syncthreads();
    if (threadIdx.x == 0) {
        float tot = 0.f;
        #pragma unroll
        for (int i = 0; i < 8; i++) tot += red[i];
        s_bc = 1.f / tot;
    }
    __syncthreads();
    float inv = s_bc;
    for (int i = threadIdx.x; i < n; i += 256) {
        float p = expf(row[i] - mx) * inv;
        bf16 h, l;
        split1(p, h, l);
        phi[ro + i] = h;
        plo[ro + i] = l;
    }
    const bf16 z = __float2bfloat16(0.f);
    for (int i = n + threadIdx.x; i < T_; i += 256) {
        phi[ro + i] = z;
        plo[ro + i] = z;
    }
}

// ---------------------------------------------------------------------------
// launch
// ---------------------------------------------------------------------------
extern "C" void kernel_launch(void* const* d_in, const int* in_sizes, int n_in,
                              void* d_out, int out_size)
{
    const float* x     = (const float*)d_in[0];
    const float* ln1_g = (const float*)d_in[1];
    const float* ln1_b = (const float*)d_in[2];
    const float* Wqkv  = (const float*)d_in[3];
    const float* bqkv  = (const float*)d_in[4];
    const float* Wproj = (const float*)d_in[5];
    const float* bproj = (const float*)d_in[6];
    const float* ln2_g = (const float*)d_in[7];
    const float* ln2_b = (const float*)d_in[8];
    const float* W1    = (const float*)d_in[9];
    const float* b1    = (const float*)d_in[10];
    const float* W2    = (const float*)d_in[11];
    const float* b2    = (const float*)d_in[12];
    float* out = (float*)d_out;

    float *p_sc, *p_a;
    bf16 *h_hi, *h_lo, *kqv_hi, *kqv_lo, *pp_hi, *pp_lo, *vT_hi, *vT_lo;
    bf16 *at_hi, *at_lo, *h2_hi, *h2_lo, *mid_hi, *mid_lo;
    bf16 *Wq_hi, *Wq_lo, *Wp_hi, *Wp_lo, *W1_hi, *W1_lo, *W2_hi, *W2_lo;

    cudaGetSymbolAddress((void**)&p_sc,   g_sc);
    cudaGetSymbolAddress((void**)&p_a,    g_a);
    cudaGetSymbolAddress((void**)&h_hi,   g_h_hi);   cudaGetSymbolAddress((void**)&h_lo,   g_h_lo);
    cudaGetSymbolAddress((void**)&kqv_hi, g_kqv_hi); cudaGetSymbolAddress((void**)&kqv_lo, g_kqv_lo);
    cudaGetSymbolAddress((void**)&pp_hi,  g_p_hi);   cudaGetSymbolAddress((void**)&pp_lo,  g_p_lo);
    cudaGetSymbolAddress((void**)&vT_hi,  g_vT_hi);  cudaGetSymbolAddress((void**)&vT_lo,  g_vT_lo);
    cudaGetSymbolAddress((void**)&at_hi,  g_at_hi);  cudaGetSymbolAddress((void**)&at_lo,  g_at_lo);
    cudaGetSymbolAddress((void**)&h2_hi,  g_h2_hi);  cudaGetSymbolAddress((void**)&h2_lo,  g_h2_lo);
    cudaGetSymbolAddress((void**)&mid_hi, g_mid_hi); cudaGetSymbolAddress((void**)&mid_lo, g_mid_lo);
    cudaGetSymbolAddress((void**)&Wq_hi,  g_Wqkv_hi); cudaGetSymbolAddress((void**)&Wq_lo, g_Wqkv_lo);
    cudaGetSymbolAddress((void**)&Wp_hi,  g_Wprj_hi); cudaGetSymbolAddress((void**)&Wp_lo, g_Wprj_lo);
    cudaGetSymbolAddress((void**)&W1_hi,  g_W1_hi);  cudaGetSymbolAddress((void**)&W1_lo,  g_W1_lo);
    cudaGetSymbolAddress((void**)&W2_hi,  g_W2_hi);  cudaGetSymbolAddress((void**)&W2_lo,  g_W2_lo);

    cudaFuncSetAttribute((const void*)gemm_cs<0, 0>, cudaFuncAttributeMaxDynamicSharedMemorySize, SMEM_BYTES);
    cudaFuncSetAttribute((const void*)gemm_cs<0, 1>, cudaFuncAttributeMaxDynamicSharedMemorySize, SMEM_BYTES);
    cudaFuncSetAttribute((const void*)gemm_cs<1, 0>, cudaFuncAttributeMaxDynamicSharedMemorySize, SMEM_BYTES);
    cudaFuncSetAttribute((const void*)gemm_cs<1, 2>, cudaFuncAttributeMaxDynamicSharedMemorySize, SMEM_BYTES);
    cudaFuncSetAttribute((const void*)gemm_cs<2, 0>, cudaFuncAttributeMaxDynamicSharedMemorySize, SMEM_BYTES);

    const float inv_sqrt_T = 1.0f / sqrtf((float)T_);
    dim3 tb(32, 8);

    // Weight transpose + split (once)
    transpose_split_f32<<<dim3(3 * D_ / 32, D_ / 32), tb>>>(Wqkv,  Wq_hi, Wq_lo, 3 * D_, D_);
    transpose_split_f32<<<dim3(D_ / 32,     D_ / 32), tb>>>(Wproj, Wp_hi, Wp_lo, D_,     D_);
    transpose_split_f32<<<dim3(4 * D_ / 32, D_ / 32), tb>>>(W1,    W1_hi, W1_lo, 4 * D_, D_);
    transpose_split_f32<<<dim3(D_ / 32, 4 * D_ / 32), tb>>>(W2,    W2_hi, W2_lo, D_, 4 * D_);

    // 1. LN1 -> split h
    ln_split<<<ROWS, 256>>>(x, ln1_g, ln1_b, h_hi, h_lo);

    // 2. QKV GEMM -> split kqv
    gemm_cs<1, 0><<<dim3(3 * D_ / 128, ROWS / 128, 1), 256, SMEM_BYTES>>>(
        h_hi, h_lo, Wq_hi, Wq_lo, bqkv, nullptr, kqv_hi, kqv_lo,
        D_, D_, D_, 3 * D_, 0, 0, 0, 1.f);

    // 3. V^T (split pair transpose), batched
    transpose_bf16_pair<<<dim3(D_ / 32, T_ / 32, B_), tb>>>(
        kqv_hi + 2 * D_, kqv_lo + 2 * D_, vT_hi, vT_lo,
        3 * D_, T_, (long long)T_ * 3 * D_, (long long)D_ * T_);

    // 4. scores = q @ k^T * inv_sqrt_T -> fp32 (lower-tri blocks only)
    gemm_cs<0, 1><<<dim3(T_ / 128, T_ / 128, B_), 256, SMEM_BYTES>>>(
        kqv_hi + D_, kqv_lo + D_, kqv_hi, kqv_lo, nullptr, p_sc, nullptr, nullptr,
        D_, 3 * D_, 3 * D_, T_,
        (long long)T_ * 3 * D_, (long long)T_ * 3 * D_, (long long)T_ * T_, inv_sqrt_T);

    // 5. softmax -> split probs
    softmax_split<<<dim3(T_, B_), 256>>>(p_sc, pp_hi, pp_lo);

    // 6. attn @ v -> split attn_out (K clipped)
    gemm_cs<1, 2><<<dim3(D_ / 128, T_ / 128, B_), 256, SMEM_BYTES>>>(
        pp_hi, pp_lo, vT_hi, vT_lo, nullptr, nullptr, at_hi, at_lo,
        T_, T_, T_, D_,
        (long long)T_ * T_, (long long)D_ * T_, (long long)T_ * D_, 1.f);

    // 7. proj -> fp32 a
    gemm_cs<0, 0><<<dim3(D_ / 128, ROWS / 128, 1), 256, SMEM_BYTES>>>(
        at_hi, at_lo, Wp_hi, Wp_lo, bproj, p_a, nullptr, nullptr,
        D_, D_, D_, D_, 0, 0, 0, 1.f);

    // 8. LN2 -> split h2
    ln_split<<<ROWS, 256>>>(p_a, ln2_g, ln2_b, h2_hi, h2_lo);

    // 9. MLP up + GELU -> split mid
    gemm_cs<2, 0><<<dim3(4 * D_ / 128, ROWS / 128, 1), 256, SMEM_BYTES>>>(
        h2_hi, h2_lo, W1_hi, W1_lo, b1, nullptr, mid_hi, mid_lo,
        D_, D_, D_, 4 * D_, 0, 0, 0, 1.f);

    // 10. MLP down -> fp32 out
    gemm_cs<0, 0><<<dim3(D_ / 128, ROWS / 128, 1), 256, SMEM_BYTES>>>(
        mid_hi, mid_lo, W2_hi, W2_lo, b2, out, nullptr, nullptr,
        4 * D_, 4 * D_, 4 * D_, D_, 0, 0, 0, 1.f);
}

// round 5
// speedup vs baseline: 3.2138x; 1.2016x over previous
#include <cuda_runtime.h>
#include <cuda_bf16.h>
#include <math.h>
#include <stdint.h>

// Problem constants
#define B_ 4
#define T_ 2048
#define D_ 1024
#define ROWS (B_ * T_)        // 8192
#define EPS 1e-5f

typedef __nv_bfloat16 bf16;

// ---------------------------------------------------------------------------
// Scratch (allocation-free: __device__ globals)
// ---------------------------------------------------------------------------
__device__ float g_sc [(size_t)B_ * T_ * T_];   // fp32 scores
__device__ float g_a  [ROWS * D_];              // fp32 proj out (LN2 input)

__device__ bf16 g_h_hi   [ROWS * D_],      g_h_lo   [ROWS * D_];
__device__ bf16 g_kqv_hi [ROWS * 3 * D_],  g_kqv_lo [ROWS * 3 * D_];
__device__ bf16 g_p_hi   [(size_t)B_ * T_ * T_], g_p_lo [(size_t)B_ * T_ * T_];
__device__ bf16 g_vT_hi  [(size_t)B_ * D_ * T_], g_vT_lo [(size_t)B_ * D_ * T_];
__device__ bf16 g_at_hi  [ROWS * D_],      g_at_lo  [ROWS * D_];
__device__ bf16 g_h2_hi  [ROWS * D_],      g_h2_lo  [ROWS * D_];
__device__ bf16 g_mid_hi [ROWS * 4 * D_],  g_mid_lo [ROWS * 4 * D_];
__device__ bf16 g_Wqkv_hi[3 * D_ * D_],    g_Wqkv_lo[3 * D_ * D_];
__device__ bf16 g_Wprj_hi[D_ * D_],        g_Wprj_lo[D_ * D_];
__device__ bf16 g_W1_hi  [4 * D_ * D_],    g_W1_lo  [4 * D_ * D_];
__device__ bf16 g_W2_hi  [D_ * 4 * D_],    g_W2_lo  [D_ * 4 * D_];

// ---------------------------------------------------------------------------
// helpers
// ---------------------------------------------------------------------------
__device__ __forceinline__ void split1(float v, bf16& h, bf16& l) {
    h = __float2bfloat16_rn(v);
    l = __float2bfloat16_rn(v - __bfloat162float(h));
}
__device__ __forceinline__ uint32_t pack2(bf16 a, bf16 b) {
    return (uint32_t)__bfloat16_as_ushort(a) | ((uint32_t)__bfloat16_as_ushort(b) << 16);
}
__device__ __forceinline__ void mma_bf16(float* d, const uint32_t* a, const uint32_t* b) {
    asm volatile(
        "mma.sync.aligned.m16n8k16.row.col.f32.bf16.bf16.f32 "
        "{%0,%1,%2,%3}, {%4,%5,%6,%7}, {%8,%9}, {%0,%1,%2,%3};"
        : "+f"(d[0]), "+f"(d[1]), "+f"(d[2]), "+f"(d[3])
        : "r"(a[0]), "r"(a[1]), "r"(a[2]), "r"(a[3]),
          "r"(b[0]), "r"(b[1]));
}
__device__ __forceinline__ uint32_t smem_u32(const void* p) {
    uint32_t a;
    asm("{ .reg .u64 t; cvta.to.shared.u64 t, %1; cvt.u32.u64 %0, t; }" : "=r"(a) : "l"(p));
    return a;
}
__device__ __forceinline__ void cp16(uint32_t dst, const void* src) {
    asm volatile("cp.async.ca.shared.global [%0], [%1], 16;" :: "r"(dst), "l"(src));
}
#define CP_COMMIT() asm volatile("cp.async.commit_group;" ::: "memory")
#define CP_WAIT(n)  asm volatile("cp.async.wait_group %0;" :: "n"(n) : "memory")

#define LDSM_X4(d0, d1, d2, d3, addr) \
    asm volatile("ldmatrix.sync.aligned.m8n8.x4.shared.b16 {%0,%1,%2,%3}, [%4];" \
        : "=r"(d0), "=r"(d1), "=r"(d2), "=r"(d3) : "r"(addr))

// SMEM tile geometry: 128 rows x 32 bf16, row stride 40 elems (80B, 16B aligned)
#define LDS_STRIDE 40
#define TILE_BYTES 10240                       // 128 * 80
#define STAGE_BYTES (4 * TILE_BYTES)           // 40960
#define SMEM_BYTES (2 * STAGE_BYTES)           // 81920

// ---------------------------------------------------------------------------
// GEMM: C[M,N] = alpha*(A @ B^T) (+bias), A/B pre-split bf16 hi/lo (NT, K-major)
// 128x128 CTA tile, 8 warps (64x32), K chunk 32, cp.async double buffered,
// ldmatrix fragment loads.
// EPI: 0=fp32 out, 1=split out, 2=gelu+split out
// CMODE: 0=dense, 1=causal block skip, 2=causal K clip
// ---------------------------------------------------------------------------
template <int EPI, int CMODE>
__global__ void __launch_bounds__(256) gemm_cs(
    const bf16* __restrict__ Ahi, const bf16* __restrict__ Alo,
    const bf16* __restrict__ Bhi, const bf16* __restrict__ Blo,
    const float* __restrict__ bias,
    float* __restrict__ Cf, bf16* __restrict__ Chi, bf16* __restrict__ Clo,
    int K, int lda, int ldb, int ldc,
    long long sA, long long sB, long long sC, float alpha)
{
    const int bx = blockIdx.x, by = blockIdx.y, bz = blockIdx.z;
    if (CMODE == 1 && bx > by) return;

    extern __shared__ bf16 smem[];
    const uint32_t sb = smem_u32(smem);

    Ahi += sA * bz; Alo += sA * bz;
    Bhi += sB * bz; Blo += sB * bz;

    const int m0 = by * 128, n0 = bx * 128;
    int Kend = K;
    if (CMODE == 2) { int ke = (by + 1) * 128; if (ke < K) Kend = ke; }
    const int NC = Kend >> 5;

    const int tid = threadIdx.x;
    const int wid = tid >> 5, lane = tid & 31;
    const int wm = wid & 1, wn = wid >> 1;
    const int g = lane >> 2, tig = lane & 3;

    // ldmatrix per-lane byte offsets within a tile
    const uint32_t a_loff = (uint32_t)(((lane & 7) + ((lane >> 3) & 1) * 8) * 80 + ((lane >> 4) & 1) * 16);
    const uint32_t b_loff = (uint32_t)(((lane & 7) + ((lane >> 4) & 1) * 8) * 80 + ((lane >> 3) & 1) * 16);

    // loader: thread covers one row, 2 of 4 16B chunks, for each of 4 tiles
    const int lrow = tid >> 1;
    const int lc   = (tid & 1) * 2;

    const bf16* pA_hi = Ahi + (size_t)(m0 + lrow) * lda + lc * 8;
    const bf16* pA_lo = Alo + (size_t)(m0 + lrow) * lda + lc * 8;
    const bf16* pB_hi = Bhi + (size_t)(n0 + lrow) * ldb + lc * 8;
    const bf16* pB_lo = Blo + (size_t)(n0 + lrow) * ldb + lc * 8;
    const uint32_t dbase = sb + lrow * 80 + lc * 16;

    auto issue = [&](int kc, int buf) {
        const uint32_t d0 = dbase + buf * STAGE_BYTES;
        const int ko = kc * 32;
        cp16(d0,                     pA_hi + ko);
        cp16(d0 + 16,                pA_hi + ko + 8);
        cp16(d0 + TILE_BYTES,        pA_lo + ko);
        cp16(d0 + TILE_BYTES + 16,   pA_lo + ko + 8);
        cp16(d0 + 2*TILE_BYTES,      pB_hi + ko);
        cp16(d0 + 2*TILE_BYTES + 16, pB_hi + ko + 8);
        cp16(d0 + 3*TILE_BYTES,      pB_lo + ko);
        cp16(d0 + 3*TILE_BYTES + 16, pB_lo + ko + 8);
    };

    float acc[4][4][4];
    #pragma unroll
    for (int i = 0; i < 4; i++)
        #pragma unroll
        for (int j = 0; j < 4; j++)
            #pragma unroll
            for (int r = 0; r < 4; r++) acc[i][j][r] = 0.f;

    issue(0, 0);
    CP_COMMIT();

    int buf = 0;
    for (int kc = 0; kc < NC; kc++) {
        if (kc + 1 < NC) {
            issue(kc + 1, buf ^ 1);
            CP_COMMIT();
            CP_WAIT(1);
        } else {
            CP_WAIT(0);
        }
        __syncthreads();

        const uint32_t stage = sb + buf * STAGE_BYTES;
        const uint32_t aH = stage + (uint32_t)(wm * 64 * 80) + a_loff;
        const uint32_t aL = aH + TILE_BYTES;
        const uint32_t bH = stage + 2 * TILE_BYTES + (uint32_t)(wn * 32 * 80) + b_loff;
        const uint32_t bL = bH + TILE_BYTES;

        #pragma unroll
        for (int kk2 = 0; kk2 < 64; kk2 += 32) {   // kk in bytes: 0, 32
            uint32_t af[4][4], bh[4][2], bl[4][2];
            #pragma unroll
            for (int mt = 0; mt < 4; mt++)
                LDSM_X4(af[mt][0], af[mt][1], af[mt][2], af[mt][3], aH + mt * 1280 + kk2);
            #pragma unroll
            for (int p = 0; p < 2; p++)
                LDSM_X4(bh[2*p][0], bh[2*p][1], bh[2*p+1][0], bh[2*p+1][1], bH + p * 1280 + kk2);
            // pass 1: Ah x Bh
            #pragma unroll
            for (int mt = 0; mt < 4; mt++)
                #pragma unroll
                for (int nt = 0; nt < 4; nt++)
                    mma_bf16(acc[mt][nt], af[mt], bh[nt]);
            // pass 2: Ah x Bl
            #pragma unroll
            for (int p = 0; p < 2; p++)
                LDSM_X4(bl[2*p][0], bl[2*p][1], bl[2*p+1][0], bl[2*p+1][1], bL + p * 1280 + kk2);
            #pragma unroll
            for (int mt = 0; mt < 4; mt++)
                #pragma unroll
                for (int nt = 0; nt < 4; nt++)
                    mma_bf16(acc[mt][nt], af[mt], bl[nt]);
            // pass 3: Al x Bh (reuse af)
            #pragma unroll
            for (int mt = 0; mt < 4; mt++)
                LDSM_X4(af[mt][0], af[mt][1], af[mt][2], af[mt][3], aL + mt * 1280 + kk2);
            #pragma unroll
            for (int mt = 0; mt < 4; mt++)
                #pragma unroll
                for (int nt = 0; nt < 4; nt++)
                    mma_bf16(acc[mt][nt], af[mt], bh[nt]);
        }
        __syncthreads();
        buf ^= 1;
    }

    // epilogue
    if (EPI == 0) Cf += sC * bz;
    else { Chi += sC * bz; Clo += sC * bz; }

    #pragma unroll
    for (int mt = 0; mt < 4; mt++) {
        #pragma unroll
        for (int nt = 0; nt < 4; nt++) {
            int m = m0 + wm * 64 + mt * 16 + g;
            int n = n0 + wn * 32 + nt * 8 + tig * 2;
            float2 bv = make_float2(0.f, 0.f);
            if (bias) bv = __ldg((const float2*)(bias + n));
            #pragma unroll
            for (int half = 0; half < 2; half++) {
                float vx = acc[mt][nt][half * 2 + 0] * alpha + bv.x;
                float vy = acc[mt][nt][half * 2 + 1] * alpha + bv.y;
                if (EPI == 2) {
                    const float c0 = 0.7978845608028654f, c1 = 0.044715f;
                    vx = 0.5f * vx * (1.f + tanhf(c0 * (vx + c1 * vx * vx * vx)));
                    vy = 0.5f * vy * (1.f + tanhf(c0 * (vy + c1 * vy * vy * vy)));
                }
                size_t off = (size_t)(m + half * 8) * ldc + n;
                if (EPI == 0) {
                    *(float2*)(Cf + off) = make_float2(vx, vy);
                } else {
                    bf16 hx, lx, hy, ly;
                    split1(vx, hx, lx);
                    split1(vy, hy, ly);
                    *(uint32_t*)(Chi + off) = pack2(hx, hy);
                    *(uint32_t*)(Clo + off) = pack2(lx, ly);
                }
            }
        }
    }
}

// ---------------------------------------------------------------------------
// Weight transpose + split
// ---------------------------------------------------------------------------
__global__ void __launch_bounds__(256) transpose_split_f32(
    const float* __restrict__ in, bf16* __restrict__ ohi, bf16* __restrict__ olo,
    int ldi, int ldo)
{
    __shared__ float t[32][33];
    const int c0 = blockIdx.x * 32, r0 = blockIdx.y * 32;
    const int x = threadIdx.x, y = threadIdx.y;
    #pragma unroll
    for (int i = 0; i < 4; i++)
        t[y + i * 8][x] = in[(size_t)(r0 + y + i * 8) * ldi + c0 + x];
    __syncthreads();
    #pragma unroll
    for (int i = 0; i < 4; i++) {
        float v = t[x][y + i * 8];
        bf16 h, l;
        split1(v, h, l);
        size_t off = (size_t)(c0 + y + i * 8) * ldo + r0 + x;
        ohi[off] = h;
        olo[off] = l;
    }
}

// ---------------------------------------------------------------------------
// bf16 pair transpose (V -> V^T), batched
// ---------------------------------------------------------------------------
__global__ void __launch_bounds__(256) transpose_bf16_pair(
    const bf16* __restrict__ ihi, const bf16* __restrict__ ilo,
    bf16* __restrict__ ohi, bf16* __restrict__ olo,
    int ldi, int ldo, long long sI, long long sO)
{
    __shared__ bf16 th[32][33], tl[32][33];
    ihi += sI * blockIdx.z; ilo += sI * blockIdx.z;
    ohi += sO * blockIdx.z; olo += sO * blockIdx.z;
    const int c0 = blockIdx.x * 32, r0 = blockIdx.y * 32;
    const int x = threadIdx.x, y = threadIdx.y;
    #pragma unroll
    for (int i = 0; i < 4; i++) {
        size_t off = (size_t)(r0 + y + i * 8) * ldi + c0 + x;
        th[y + i * 8][x] = ihi[off];
        tl[y + i * 8][x] = ilo[off];
    }
    __syncthreads();
    #pragma unroll
    for (int i = 0; i < 4; i++) {
        size_t off = (size_t)(c0 + y + i * 8) * ldo + r0 + x;
        ohi[off] = th[x][y + i * 8];
        olo[off] = tl[x][y + i * 8];
    }
}

// ---------------------------------------------------------------------------
// LayerNorm -> split bf16 out (row cached in SMEM)
// ---------------------------------------------------------------------------
__global__ void __launch_bounds__(256) ln_split(
    const float* __restrict__ x, const float* __restrict__ gamma,
    const float* __restrict__ beta,
    bf16* __restrict__ ohi, bf16* __restrict__ olo)
{
    __shared__ float xc[D_];
    const int row = blockIdx.x;
    const float* xr = x + (size_t)row * D_;

    float s = 0.f, ss = 0.f;
    for (int i = threadIdx.x; i < D_; i += 256) {
        float v = xr[i];
        xc[i] = v;
        s += v; ss += v * v;
    }
    __shared__ float rs[8], rss[8];
    #pragma unroll
    for (int o = 16; o > 0; o >>= 1) {
        s  += __shfl_down_sync(0xffffffffu, s,  o);
        ss += __shfl_down_sync(0xffffffffu, ss, o);
    }
    int wid = threadIdx.x >> 5, lid = threadIdx.x & 31;
    if (lid == 0) { rs[wid] = s; rss[wid] = ss; }
    __syncthreads();
    __shared__ float s_mu, s_rstd;
    if (threadIdx.x == 0) {
        float ts = 0.f, tss = 0.f;
        #pragma unroll
        for (int i = 0; i < 8; i++) { ts += rs[i]; tss += rss[i]; }
        float mu = ts / D_;
        float var = tss / D_ - mu * mu;
        s_mu = mu;
        s_rstd = rsqrtf(var + EPS);
    }
    __syncthreads();
    float mu = s_mu, rstd = s_rstd;
    for (int i = threadIdx.x; i < D_; i += 256) {
        float v = (xc[i] - mu) * rstd * gamma[i] + beta[i];
        bf16 h, l;
        split1(v, h, l);
        ohi[(size_t)row * D_ + i] = h;
        olo[(size_t)row * D_ + i] = l;
    }
}

// ---------------------------------------------------------------------------
// Causal softmax: fp32 scores in -> split bf16 probs out (row cached in SMEM)
// ---------------------------------------------------------------------------
__global__ void __launch_bounds__(256) softmax_split(
    const float* __restrict__ sc, bf16* __restrict__ phi, bf16* __restrict__ plo)
{
    __shared__ float cache[T_];
    const int t = blockIdx.x, b = blockIdx.y;
    const size_t ro = ((size_t)b * T_ + t) * T_;
    const float* row = sc + ro;
    const int n = t + 1;

    __shared__ float red[8];
    __shared__ float s_bc;

    float mx = -INFINITY;
    for (int i = threadIdx.x; i < n; i += 256) {
        float v = row[i];
        cache[i] = v;
        mx = fmaxf(mx, v);
    }
    #pragma unroll
    for (int o = 16; o > 0; o >>= 1) mx = fmaxf(mx, __shfl_down_sync(0xffffffffu, mx, o));
    int wid = threadIdx.x >> 5, lid = threadIdx.x & 31;
    if (lid == 0) red[wid] = mx;
    __syncthreads();
    if (threadIdx.x == 0) {
        float m = red[0];
        #pragma unroll
        for (int i = 1; i < 8; i++) m = fmaxf(m, red[i]);
        s_bc = m;
    }
    __syncthreads();
    mx = s_bc;

    float sum = 0.f;
    for (int i = threadIdx.x; i < n; i += 256) {
        float e = expf(cache[i] - mx);
        cache[i] = e;
        sum += e;
    }
    #pragma unroll
    for (int o = 16; o > 0; o >>= 1) sum += __shfl_down_sync(0xffffffffu, sum, o);
    if (lid == 0) red[wid] = sum;
    __syncthreads();
    if (threadIdx.x == 0) {
        float tot = 0.f;
        #pragma unroll
        for (int i = 0; i < 8; i++) tot += red[i];
        s_bc = 1.f / tot;
    }
    __syncthreads();
    float inv = s_bc;
    for (int i = threadIdx.x; i < n; i += 256) {
        float p = cache[i] * inv;
        bf16 h, l;
        split1(p, h, l);
        phi[ro + i] = h;
        plo[ro + i] = l;
    }
    const bf16 z = __float2bfloat16(0.f);
    for (int i = n + threadIdx.x; i < T_; i += 256) {
        phi[ro + i] = z;
        plo[ro + i] = z;
    }
}

// ---------------------------------------------------------------------------
// launch
// ---------------------------------------------------------------------------
extern "C" void kernel_launch(void* const* d_in, const int* in_sizes, int n_in,
                              void* d_out, int out_size)
{
    const float* x     = (const float*)d_in[0];
    const float* ln1_g = (const float*)d_in[1];
    const float* ln1_b = (const float*)d_in[2];
    const float* Wqkv  = (const float*)d_in[3];
    const float* bqkv  = (const float*)d_in[4];
    const float* Wproj = (const float*)d_in[5];
    const float* bproj = (const float*)d_in[6];
    const float* ln2_g = (const float*)d_in[7];
    const float* ln2_b = (const float*)d_in[8];
    const float* W1    = (const float*)d_in[9];
    const float* b1    = (const float*)d_in[10];
    const float* W2    = (const float*)d_in[11];
    const float* b2    = (const float*)d_in[12];
    float* out = (float*)d_out;

    float *p_sc, *p_a;
    bf16 *h_hi, *h_lo, *kqv_hi, *kqv_lo, *pp_hi, *pp_lo, *vT_hi, *vT_lo;
    bf16 *at_hi, *at_lo, *h2_hi, *h2_lo, *mid_hi, *mid_lo;
    bf16 *Wq_hi, *Wq_lo, *Wp_hi, *Wp_lo, *W1_hi, *W1_lo, *W2_hi, *W2_lo;

    cudaGetSymbolAddress((void**)&p_sc,   g_sc);
    cudaGetSymbolAddress((void**)&p_a,    g_a);
    cudaGetSymbolAddress((void**)&h_hi,   g_h_hi);   cudaGetSymbolAddress((void**)&h_lo,   g_h_lo);
    cudaGetSymbolAddress((void**)&kqv_hi, g_kqv_hi); cudaGetSymbolAddress((void**)&kqv_lo, g_kqv_lo);
    cudaGetSymbolAddress((void**)&pp_hi,  g_p_hi);   cudaGetSymbolAddress((void**)&pp_lo,  g_p_lo);
    cudaGetSymbolAddress((void**)&vT_hi,  g_vT_hi);  cudaGetSymbolAddress((void**)&vT_lo,  g_vT_lo);
    cudaGetSymbolAddress((void**)&at_hi,  g_at_hi);  cudaGetSymbolAddress((void**)&at_lo,  g_at_lo);
    cudaGetSymbolAddress((void**)&h2_hi,  g_h2_hi);  cudaGetSymbolAddress((void**)&h2_lo,  g_h2_lo);
    cudaGetSymbolAddress((void**)&mid_hi, g_mid_hi); cudaGetSymbolAddress((void**)&mid_lo, g_mid_lo);
    cudaGetSymbolAddress((void**)&Wq_hi,  g_Wqkv_hi); cudaGetSymbolAddress((void**)&Wq_lo, g_Wqkv_lo);
    cudaGetSymbolAddress((void**)&Wp_hi,  g_Wprj_hi); cudaGetSymbolAddress((void**)&Wp_lo, g_Wprj_lo);
    cudaGetSymbolAddress((void**)&W1_hi,  g_W1_hi);  cudaGetSymbolAddress((void**)&W1_lo,  g_W1_lo);
    cudaGetSymbolAddress((void**)&W2_hi,  g_W2_hi);  cudaGetSymbolAddress((void**)&W2_lo,  g_W2_lo);

    cudaFuncSetAttribute((const void*)gemm_cs<0, 0>, cudaFuncAttributeMaxDynamicSharedMemorySize, SMEM_BYTES);
    cudaFuncSetAttribute((const void*)gemm_cs<0, 1>, cudaFuncAttributeMaxDynamicSharedMemorySize, SMEM_BYTES);
    cudaFuncSetAttribute((const void*)gemm_cs<1, 0>, cudaFuncAttributeMaxDynamicSharedMemorySize, SMEM_BYTES);
    cudaFuncSetAttribute((const void*)gemm_cs<1, 2>, cudaFuncAttributeMaxDynamicSharedMemorySize, SMEM_BYTES);
    cudaFuncSetAttribute((const void*)gemm_cs<2, 0>, cudaFuncAttributeMaxDynamicSharedMemorySize, SMEM_BYTES);

    const float inv_sqrt_T = 1.0f / sqrtf((float)T_);
    dim3 tb(32, 8);

    // Weight transpose + split (once)
    transpose_split_f32<<<dim3(3 * D_ / 32, D_ / 32), tb>>>(Wqkv,  Wq_hi, Wq_lo, 3 * D_, D_);
    transpose_split_f32<<<dim3(D_ / 32,     D_ / 32), tb>>>(Wproj, Wp_hi, Wp_lo, D_,     D_);
    transpose_split_f32<<<dim3(4 * D_ / 32, D_ / 32), tb>>>(W1,    W1_hi, W1_lo, 4 * D_, D_);
    transpose_split_f32<<<dim3(D_ / 32, 4 * D_ / 32), tb>>>(W2,    W2_hi, W2_lo, D_, 4 * D_);

    // 1. LN1 -> split h
    ln_split<<<ROWS, 256>>>(x, ln1_g, ln1_b, h_hi, h_lo);

    // 2. QKV GEMM -> split kqv
    gemm_cs<1, 0><<<dim3(3 * D_ / 128, ROWS / 128, 1), 256, SMEM_BYTES>>>(
        h_hi, h_lo, Wq_hi, Wq_lo, bqkv, nullptr, kqv_hi, kqv_lo,
        D_, D_, D_, 3 * D_, 0, 0, 0, 1.f);

    // 3. V^T (split pair transpose), batched
    transpose_bf16_pair<<<dim3(D_ / 32, T_ / 32, B_), tb>>>(
        kqv_hi + 2 * D_, kqv_lo + 2 * D_, vT_hi, vT_lo,
        3 * D_, T_, (long long)T_ * 3 * D_, (long long)D_ * T_);

    // 4. scores = q @ k^T * inv_sqrt_T -> fp32 (lower-tri blocks only)
    gemm_cs<0, 1><<<dim3(T_ / 128, T_ / 128, B_), 256, SMEM_BYTES>>>(
        kqv_hi + D_, kqv_lo + D_, kqv_hi, kqv_lo, nullptr, p_sc, nullptr, nullptr,
        D_, 3 * D_, 3 * D_, T_,
        (long long)T_ * 3 * D_, (long long)T_ * 3 * D_, (long long)T_ * T_, inv_sqrt_T);

    // 5. softmax -> split probs
    softmax_split<<<dim3(T_, B_), 256>>>(p_sc, pp_hi, pp_lo);

    // 6. attn @ v -> split attn_out (K clipped)
    gemm_cs<1, 2><<<dim3(D_ / 128, T_ / 128, B_), 256, SMEM_BYTES>>>(
        pp_hi, pp_lo, vT_hi, vT_lo, nullptr, nullptr, at_hi, at_lo,
        T_, T_, T_, D_,
        (long long)T_ * T_, (long long)D_ * T_, (long long)T_ * D_, 1.f);

    // 7. proj -> fp32 a
    gemm_cs<0, 0><<<dim3(D_ / 128, ROWS / 128, 1), 256, SMEM_BYTES>>>(
        at_hi, at_lo, Wp_hi, Wp_lo, bproj, p_a, nullptr, nullptr,
        D_, D_, D_, D_, 0, 0, 0, 1.f);

    // 8. LN2 -> split h2
    ln_split<<<ROWS, 256>>>(p_a, ln2_g, ln2_b, h2_hi, h2_lo);

    // 9. MLP up + GELU -> split mid
    gemm_cs<2, 0><<<dim3(4 * D_ / 128, ROWS / 128, 1), 256, SMEM_BYTES>>>(
        h2_hi, h2_lo, W1_hi, W1_lo, b1, nullptr, mid_hi, mid_lo,
        D_, D_, D_, 4 * D_, 0, 0, 0, 1.f);

    // 10. MLP down -> fp32 out
    gemm_cs<0, 0><<<dim3(D_ / 128, ROWS / 128, 1), 256, SMEM_BYTES>>>(
        mid_hi, mid_lo, W2_hi, W2_lo, b2, out, nullptr, nullptr,
        4 * D_, 4 * D_, 4 * D_, D_, 0, 0, 0, 1.f);
}

// round 6
// speedup vs baseline: 4.5564x; 1.4177x over previous
#include <cuda_runtime.h>
#include <cuda_fp16.h>
#include <math.h>
#include <stdint.h>

// Problem constants
#define B_ 4
#define T_ 2048
#define D_ 1024
#define ROWS (B_ * T_)        // 8192
#define EPS 1e-5f

typedef __half fp16;

// ---------------------------------------------------------------------------
// Scratch (allocation-free: __device__ globals)
// ---------------------------------------------------------------------------
__device__ float g_sc [(size_t)B_ * T_ * T_];   // fp32 scores
__device__ float g_a  [ROWS * D_];              // fp32 proj out (LN2 input)

__device__ fp16 g_h    [ROWS * D_];                                   // A only
__device__ fp16 g_kqv_hi[ROWS * 3 * D_],  g_kqv_lo[ROWS * 3 * D_];    // A+B (3-pass)
__device__ fp16 g_p_hi [(size_t)B_ * T_ * T_], g_p_lo [(size_t)B_ * T_ * T_];
__device__ fp16 g_vT_hi[(size_t)B_ * D_ * T_], g_vT_lo[(size_t)B_ * D_ * T_];
__device__ fp16 g_at   [ROWS * D_];                                   // A only
__device__ fp16 g_h2   [ROWS * D_];                                   // A only
__device__ fp16 g_mid  [ROWS * 4 * D_];                               // A only
__device__ fp16 g_Wqkv_hi[3 * D_ * D_],   g_Wqkv_lo[3 * D_ * D_];
__device__ fp16 g_Wprj_hi[D_ * D_],       g_Wprj_lo[D_ * D_];
__device__ fp16 g_W1_hi  [4 * D_ * D_],   g_W1_lo  [4 * D_ * D_];
__device__ fp16 g_W2_hi  [D_ * 4 * D_],   g_W2_lo  [D_ * 4 * D_];

#define WSCALE 32.0f
#define WALPHA (1.0f / 32.0f)

// ---------------------------------------------------------------------------
// helpers
// ---------------------------------------------------------------------------
__device__ __forceinline__ void split1(float v, fp16& h, fp16& l) {
    h = __float2half_rn(v);
    l = __float2half_rn(v - __half2float(h));
}
__device__ __forceinline__ uint32_t pack2h(fp16 a, fp16 b) {
    return (uint32_t)__half_as_ushort(a) | ((uint32_t)__half_as_ushort(b) << 16);
}
__device__ __forceinline__ void mma_fp16(float* d, const uint32_t* a, const uint32_t* b) {
    asm volatile(
        "mma.sync.aligned.m16n8k16.row.col.f32.f16.f16.f32 "
        "{%0,%1,%2,%3}, {%4,%5,%6,%7}, {%8,%9}, {%0,%1,%2,%3};"
        : "+f"(d[0]), "+f"(d[1]), "+f"(d[2]), "+f"(d[3])
        : "r"(a[0]), "r"(a[1]), "r"(a[2]), "r"(a[3]),
          "r"(b[0]), "r"(b[1]));
}
__device__ __forceinline__ uint32_t smem_u32(const void* p) {
    uint32_t a;
    asm("{ .reg .u64 t; cvta.to.shared.u64 t, %1; cvt.u32.u64 %0, t; }" : "=r"(a) : "l"(p));
    return a;
}
__device__ __forceinline__ void cp16(uint32_t dst, const void* src) {
    asm volatile("cp.async.ca.shared.global [%0], [%1], 16;" :: "r"(dst), "l"(src));
}
#define CP_COMMIT() asm volatile("cp.async.commit_group;" ::: "memory")
#define CP_WAIT(n)  asm volatile("cp.async.wait_group %0;" :: "n"(n) : "memory")

#define LDSM_X4(d0, d1, d2, d3, addr) \
    asm volatile("ldmatrix.sync.aligned.m8n8.x4.shared.b16 {%0,%1,%2,%3}, [%4];" \
        : "=r"(d0), "=r"(d1), "=r"(d2), "=r"(d3) : "r"(addr))

// SMEM tile geometry: 128 rows x 32 fp16, row stride 40 elems (80B)
#define TILE_BYTES 10240                        // 128 * 80

// ---------------------------------------------------------------------------
// GEMM: C[M,N] = alpha*(A @ B^T) (+bias)
// PASSES=2: A fp16 (rounded), B hi+lo.   PASSES=3: A hi+lo, B hi+lo.
// Tile order in stage: A_hi, B_hi, B_lo, [A_lo]
// EPI: 0=fp32 out, 1=split hi+lo out, 2=fp16 out, 3=gelu+fp16 out
// CMODE: 0=dense, 1=causal block skip, 2=causal K clip
// ---------------------------------------------------------------------------
template <int PASSES, int EPI, int CMODE>
__global__ void __launch_bounds__(256) gemm_cs(
    const fp16* __restrict__ Ahi, const fp16* __restrict__ Alo,
    const fp16* __restrict__ Bhi, const fp16* __restrict__ Blo,
    const float* __restrict__ bias,
    float* __restrict__ Cf, fp16* __restrict__ Chi, fp16* __restrict__ Clo,
    int K, int lda, int ldb, int ldc,
    long long sA, long long sB, long long sC, float alpha)
{
    constexpr int NTILES = (PASSES == 3) ? 4 : 3;
    constexpr int STAGE_BYTES = NTILES * TILE_BYTES;

    const int bx = blockIdx.x, by = blockIdx.y, bz = blockIdx.z;
    if (CMODE == 1 && bx > by) return;

    extern __shared__ fp16 smem[];
    const uint32_t sb = smem_u32(smem);

    Ahi += sA * bz;
    if (PASSES == 3) Alo += sA * bz;
    Bhi += sB * bz; Blo += sB * bz;

    const int m0 = by * 128, n0 = bx * 128;
    int Kend = K;
    if (CMODE == 2) { int ke = (by + 1) * 128; if (ke < K) Kend = ke; }
    const int NC = Kend >> 5;

    const int tid = threadIdx.x;
    const int wid = tid >> 5, lane = tid & 31;
    const int wm = wid & 1, wn = wid >> 1;
    const int g = lane >> 2, tig = lane & 3;

    const uint32_t a_loff = (uint32_t)(((lane & 7) + ((lane >> 3) & 1) * 8) * 80 + ((lane >> 4) & 1) * 16);
    const uint32_t b_loff = (uint32_t)(((lane & 7) + ((lane >> 4) & 1) * 8) * 80 + ((lane >> 3) & 1) * 16);

    const int lrow = tid >> 1;
    const int lc   = (tid & 1) * 2;

    const fp16* pA_hi = Ahi + (size_t)(m0 + lrow) * lda + lc * 8;
    const fp16* pA_lo = (PASSES == 3) ? (Alo + (size_t)(m0 + lrow) * lda + lc * 8) : nullptr;
    const fp16* pB_hi = Bhi + (size_t)(n0 + lrow) * ldb + lc * 8;
    const fp16* pB_lo = Blo + (size_t)(n0 + lrow) * ldb + lc * 8;
    const uint32_t dbase = sb + lrow * 80 + lc * 16;

    auto issue = [&](int kc, int buf) {
        const uint32_t d0 = dbase + buf * STAGE_BYTES;
        const int ko = kc * 32;
        cp16(d0,                     pA_hi + ko);
        cp16(d0 + 16,                pA_hi + ko + 8);
        cp16(d0 + TILE_BYTES,        pB_hi + ko);
        cp16(d0 + TILE_BYTES + 16,   pB_hi + ko + 8);
        cp16(d0 + 2*TILE_BYTES,      pB_lo + ko);
        cp16(d0 + 2*TILE_BYTES + 16, pB_lo + ko + 8);
        if (PASSES == 3) {
            cp16(d0 + 3*TILE_BYTES,      pA_lo + ko);
            cp16(d0 + 3*TILE_BYTES + 16, pA_lo + ko + 8);
        }
    };

    float acc[4][4][4];
    #pragma unroll
    for (int i = 0; i < 4; i++)
        #pragma unroll
        for (int j = 0; j < 4; j++)
            #pragma unroll
            for (int r = 0; r < 4; r++) acc[i][j][r] = 0.f;

    issue(0, 0);
    CP_COMMIT();

    int buf = 0;
    for (int kc = 0; kc < NC; kc++) {
        if (kc + 1 < NC) {
            issue(kc + 1, buf ^ 1);
            CP_COMMIT();
            CP_WAIT(1);
        } else {
            CP_WAIT(0);
        }
        __syncthreads();

        const uint32_t stage = sb + buf * STAGE_BYTES;
        const uint32_t aH = stage + (uint32_t)(wm * 64 * 80) + a_loff;
        const uint32_t bH = stage + TILE_BYTES + (uint32_t)(wn * 32 * 80) + b_loff;
        const uint32_t bL = bH + TILE_BYTES;
        const uint32_t aL = aH + 3 * TILE_BYTES;

        #pragma unroll
        for (int kk2 = 0; kk2 < 64; kk2 += 32) {
            uint32_t af[4][4], bh[4][2], bl[4][2];
            #pragma unroll
            for (int mt = 0; mt < 4; mt++)
                LDSM_X4(af[mt][0], af[mt][1], af[mt][2], af[mt][3], aH + mt * 1280 + kk2);
            #pragma unroll
            for (int p = 0; p < 2; p++)
                LDSM_X4(bh[2*p][0], bh[2*p][1], bh[2*p+1][0], bh[2*p+1][1], bH + p * 1280 + kk2);
            // pass 1: A_hi x B_hi
            #pragma unroll
            for (int mt = 0; mt < 4; mt++)
                #pragma unroll
                for (int nt = 0; nt < 4; nt++)
                    mma_fp16(acc[mt][nt], af[mt], bh[nt]);
            // pass 2: A_hi x B_lo
            #pragma unroll
            for (int p = 0; p < 2; p++)
                LDSM_X4(bl[2*p][0], bl[2*p][1], bl[2*p+1][0], bl[2*p+1][1], bL + p * 1280 + kk2);
            #pragma unroll
            for (int mt = 0; mt < 4; mt++)
                #pragma unroll
                for (int nt = 0; nt < 4; nt++)
                    mma_fp16(acc[mt][nt], af[mt], bl[nt]);
            // pass 3: A_lo x B_hi
            if (PASSES == 3) {
                #pragma unroll
                for (int mt = 0; mt < 4; mt++)
                    LDSM_X4(af[mt][0], af[mt][1], af[mt][2], af[mt][3], aL + mt * 1280 + kk2);
                #pragma unroll
                for (int mt = 0; mt < 4; mt++)
                    #pragma unroll
                    for (int nt = 0; nt < 4; nt++)
                        mma_fp16(acc[mt][nt], af[mt], bh[nt]);
            }
        }
        __syncthreads();
        buf ^= 1;
    }

    // epilogue
    if (EPI == 0) Cf += sC * bz;
    else { Chi += sC * bz; if (EPI == 1) Clo += sC * bz; }

    #pragma unroll
    for (int mt = 0; mt < 4; mt++) {
        #pragma unroll
        for (int nt = 0; nt < 4; nt++) {
            int m = m0 + wm * 64 + mt * 16 + g;
            int n = n0 + wn * 32 + nt * 8 + tig * 2;
            float2 bv = make_float2(0.f, 0.f);
            if (bias) bv = __ldg((const float2*)(bias + n));
            #pragma unroll
            for (int half_ = 0; half_ < 2; half_++) {
                float vx = acc[mt][nt][half_ * 2 + 0] * alpha + bv.x;
                float vy = acc[mt][nt][half_ * 2 + 1] * alpha + bv.y;
                if (EPI == 3) {
                    const float c0 = 0.7978845608028654f, c1 = 0.044715f;
                    vx = 0.5f * vx * (1.f + tanhf(c0 * (vx + c1 * vx * vx * vx)));
                    vy = 0.5f * vy * (1.f + tanhf(c0 * (vy + c1 * vy * vy * vy)));
                }
                size_t off = (size_t)(m + half_ * 8) * ldc + n;
                if (EPI == 0) {
                    *(float2*)(Cf + off) = make_float2(vx, vy);
                } else if (EPI == 1) {
                    fp16 hx, lx, hy, ly;
                    split1(vx, hx, lx);
                    split1(vy, hy, ly);
                    *(uint32_t*)(Chi + off) = pack2h(hx, hy);
                    *(uint32_t*)(Clo + off) = pack2h(lx, ly);
                } else {
                    *(uint32_t*)(Chi + off) = pack2h(__float2half_rn(vx), __float2half_rn(vy));
                }
            }
        }
    }
}

// ---------------------------------------------------------------------------
// Weight transpose + scale + split: out[c][r] = split(in[r][c] * scale)
// ---------------------------------------------------------------------------
__global__ void __launch_bounds__(256) transpose_split_f32(
    const float* __restrict__ in, fp16* __restrict__ ohi, fp16* __restrict__ olo,
    int ldi, int ldo, float scale)
{
    __shared__ float t[32][33];
    const int c0 = blockIdx.x * 32, r0 = blockIdx.y * 32;
    const int x = threadIdx.x, y = threadIdx.y;
    #pragma unroll
    for (int i = 0; i < 4; i++)
        t[y + i * 8][x] = in[(size_t)(r0 + y + i * 8) * ldi + c0 + x];
    __syncthreads();
    #pragma unroll
    for (int i = 0; i < 4; i++) {
        float v = t[x][y + i * 8] * scale;
        fp16 h, l;
        split1(v, h, l);
        size_t off = (size_t)(c0 + y + i * 8) * ldo + r0 + x;
        ohi[off] = h;
        olo[off] = l;
    }
}

// ---------------------------------------------------------------------------
// fp16 pair transpose (V -> V^T), batched
// ---------------------------------------------------------------------------
__global__ void __launch_bounds__(256) transpose_h_pair(
    const fp16* __restrict__ ihi, const fp16* __restrict__ ilo,
    fp16* __restrict__ ohi, fp16* __restrict__ olo,
    int ldi, int ldo, long long sI, long long sO)
{
    __shared__ fp16 th[32][33], tl[32][33];
    ihi += sI * blockIdx.z; ilo += sI * blockIdx.z;
    ohi += sO * blockIdx.z; olo += sO * blockIdx.z;
    const int c0 = blockIdx.x * 32, r0 = blockIdx.y * 32;
    const int x = threadIdx.x, y = threadIdx.y;
    #pragma unroll
    for (int i = 0; i < 4; i++) {
        size_t off = (size_t)(r0 + y + i * 8) * ldi + c0 + x;
        th[y + i * 8][x] = ihi[off];
        tl[y + i * 8][x] = ilo[off];
    }
    __syncthreads();
    #pragma unroll
    for (int i = 0; i < 4; i++) {
        size_t off = (size_t)(c0 + y + i * 8) * ldo + r0 + x;
        ohi[off] = th[x][y + i * 8];
        olo[off] = tl[x][y + i * 8];
    }
}

// ---------------------------------------------------------------------------
// LayerNorm -> fp16 out (row cached in SMEM)
// ---------------------------------------------------------------------------
__global__ void __launch_bounds__(256) ln_half(
    const float* __restrict__ x, const float* __restrict__ gamma,
    const float* __restrict__ beta, fp16* __restrict__ o)
{
    __shared__ float xc[D_];
    const int row = blockIdx.x;
    const float* xr = x + (size_t)row * D_;

    float s = 0.f, ss = 0.f;
    for (int i = threadIdx.x; i < D_; i += 256) {
        float v = xr[i];
        xc[i] = v;
        s += v; ss += v * v;
    }
    __shared__ float rs[8], rss[8];
    #pragma unroll
    for (int o2 = 16; o2 > 0; o2 >>= 1) {
        s  += __shfl_down_sync(0xffffffffu, s,  o2);
        ss += __shfl_down_sync(0xffffffffu, ss, o2);
    }
    int wid = threadIdx.x >> 5, lid = threadIdx.x & 31;
    if (lid == 0) { rs[wid] = s; rss[wid] = ss; }
    __syncthreads();
    __shared__ float s_mu, s_rstd;
    if (threadIdx.x == 0) {
        float ts = 0.f, tss = 0.f;
        #pragma unroll
        for (int i = 0; i < 8; i++) { ts += rs[i]; tss += rss[i]; }
        float mu = ts / D_;
        float var = tss / D_ - mu * mu;
        s_mu = mu;
        s_rstd = rsqrtf(var + EPS);
    }
    __syncthreads();
    float mu = s_mu, rstd = s_rstd;
    for (int i = threadIdx.x; i < D_; i += 256) {
        float v = (xc[i] - mu) * rstd * gamma[i] + beta[i];
        o[(size_t)row * D_ + i] = __float2half_rn(v);
    }
}

// ---------------------------------------------------------------------------
// Causal softmax: fp32 scores -> split fp16 probs (row cached in SMEM)
// ---------------------------------------------------------------------------
__global__ void __launch_bounds__(256) softmax_split(
    const float* __restrict__ sc, fp16* __restrict__ phi, fp16* __restrict__ plo)
{
    __shared__ float cache[T_];
    const int t = blockIdx.x, b = blockIdx.y;
    const size_t ro = ((size_t)b * T_ + t) * T_;
    const float* row = sc + ro;
    const int n = t + 1;

    __shared__ float red[8];
    __shared__ float s_bc;

    float mx = -INFINITY;
    for (int i = threadIdx.x; i < n; i += 256) {
        float v = row[i];
        cache[i] = v;
        mx = fmaxf(mx, v);
    }
    #pragma unroll
    for (int o = 16; o > 0; o >>= 1) mx = fmaxf(mx, __shfl_down_sync(0xffffffffu, mx, o));
    int wid = threadIdx.x >> 5, lid = threadIdx.x & 31;
    if (lid == 0) red[wid] = mx;
    __syncthreads();
    if (threadIdx.x == 0) {
        float m = red[0];
        #pragma unroll
        for (int i = 1; i < 8; i++) m = fmaxf(m, red[i]);
        s_bc = m;
    }
    __syncthreads();
    mx = s_bc;

    float sum = 0.f;
    for (int i = threadIdx.x; i < n; i += 256) {
        float e = expf(cache[i] - mx);
        cache[i] = e;
        sum += e;
    }
    #pragma unroll
    for (int o = 16; o > 0; o >>= 1) sum += __shfl_down_sync(0xffffffffu, sum, o);
    if (lid == 0) red[wid] = sum;
    __syncthreads();
    if (threadIdx.x == 0) {
        float tot = 0.f;
        #pragma unroll
        for (int i = 0; i < 8; i++) tot += red[i];
        s_bc = 1.f / tot;
    }
    __syncthreads();
    float inv = s_bc;
    for (int i = threadIdx.x; i < n; i += 256) {
        float p = cache[i] * inv;
        fp16 h, l;
        split1(p, h, l);
        phi[ro + i] = h;
        plo[ro + i] = l;
    }
    const fp16 z = __float2half(0.f);
    for (int i = n + threadIdx.x; i < T_; i += 256) {
        phi[ro + i] = z;
        plo[ro + i] = z;
    }
}

// ---------------------------------------------------------------------------
// launch
// ---------------------------------------------------------------------------
extern "C" void kernel_launch(void* const* d_in, const int* in_sizes, int n_in,
                              void* d_out, int out_size)
{
    const float* x     = (const float*)d_in[0];
    const float* ln1_g = (const float*)d_in[1];
    const float* ln1_b = (const float*)d_in[2];
    const float* Wqkv  = (const float*)d_in[3];
    const float* bqkv  = (const float*)d_in[4];
    const float* Wproj = (const float*)d_in[5];
    const float* bproj = (const float*)d_in[6];
    const float* ln2_g = (const float*)d_in[7];
    const float* ln2_b = (const float*)d_in[8];
    const float* W1    = (const float*)d_in[9];
    const float* b1    = (const float*)d_in[10];
    const float* W2    = (const float*)d_in[11];
    const float* b2    = (const float*)d_in[12];
    float* out = (float*)d_out;

    float *p_sc, *p_a;
    fp16 *p_h, *kqv_hi, *kqv_lo, *pp_hi, *pp_lo, *vT_hi, *vT_lo;
    fp16 *p_at, *p_h2, *p_mid;
    fp16 *Wq_hi, *Wq_lo, *Wp_hi, *Wp_lo, *W1_hi, *W1_lo, *W2_hi, *W2_lo;

    cudaGetSymbolAddress((void**)&p_sc,   g_sc);
    cudaGetSymbolAddress((void**)&p_a,    g_a);
    cudaGetSymbolAddress((void**)&p_h,    g_h);
    cudaGetSymbolAddress((void**)&kqv_hi, g_kqv_hi); cudaGetSymbolAddress((void**)&kqv_lo, g_kqv_lo);
    cudaGetSymbolAddress((void**)&pp_hi,  g_p_hi);   cudaGetSymbolAddress((void**)&pp_lo,  g_p_lo);
    cudaGetSymbolAddress((void**)&vT_hi,  g_vT_hi);  cudaGetSymbolAddress((void**)&vT_lo,  g_vT_lo);
    cudaGetSymbolAddress((void**)&p_at,   g_at);
    cudaGetSymbolAddress((void**)&p_h2,   g_h2);
    cudaGetSymbolAddress((void**)&p_mid,  g_mid);
    cudaGetSymbolAddress((void**)&Wq_hi,  g_Wqkv_hi); cudaGetSymbolAddress((void**)&Wq_lo, g_Wqkv_lo);
    cudaGetSymbolAddress((void**)&Wp_hi,  g_Wprj_hi); cudaGetSymbolAddress((void**)&Wp_lo, g_Wprj_lo);
    cudaGetSymbolAddress((void**)&W1_hi,  g_W1_hi);  cudaGetSymbolAddress((void**)&W1_lo,  g_W1_lo);
    cudaGetSymbolAddress((void**)&W2_hi,  g_W2_hi);  cudaGetSymbolAddress((void**)&W2_lo,  g_W2_lo);

    const int SMEM2 = 2 * 3 * TILE_BYTES;   // 61440
    const int SMEM3 = 2 * 4 * TILE_BYTES;   // 81920
    cudaFuncSetAttribute((const void*)gemm_cs<2, 1, 0>, cudaFuncAttributeMaxDynamicSharedMemorySize, SMEM2);
    cudaFuncSetAttribute((const void*)gemm_cs<2, 0, 0>, cudaFuncAttributeMaxDynamicSharedMemorySize, SMEM2);
    cudaFuncSetAttribute((const void*)gemm_cs<2, 3, 0>, cudaFuncAttributeMaxDynamicSharedMemorySize, SMEM2);
    cudaFuncSetAttribute((const void*)gemm_cs<3, 0, 1>, cudaFuncAttributeMaxDynamicSharedMemorySize, SMEM3);
    cudaFuncSetAttribute((const void*)gemm_cs<3, 2, 2>, cudaFuncAttributeMaxDynamicSharedMemorySize, SMEM3);

    const float inv_sqrt_T = 1.0f / sqrtf((float)T_);
    dim3 tb(32, 8);

    // Weight transpose + x32 scale + split (once)
    transpose_split_f32<<<dim3(3 * D_ / 32, D_ / 32), tb>>>(Wqkv,  Wq_hi, Wq_lo, 3 * D_, D_, WSCALE);
    transpose_split_f32<<<dim3(D_ / 32,     D_ / 32), tb>>>(Wproj, Wp_hi, Wp_lo, D_,     D_, WSCALE);
    transpose_split_f32<<<dim3(4 * D_ / 32, D_ / 32), tb>>>(W1,    W1_hi, W1_lo, 4 * D_, D_, WSCALE);
    transpose_split_f32<<<dim3(D_ / 32, 4 * D_ / 32), tb>>>(W2,    W2_hi, W2_lo, D_, 4 * D_, WSCALE);

    // 1. LN1 -> fp16 h
    ln_half<<<ROWS, 256>>>(x, ln1_g, ln1_b, p_h);

    // 2. QKV GEMM (2-pass) -> split kqv
    gemm_cs<2, 1, 0><<<dim3(3 * D_ / 128, ROWS / 128, 1), 256, SMEM2>>>(
        p_h, nullptr, Wq_hi, Wq_lo, bqkv, nullptr, kqv_hi, kqv_lo,
        D_, D_, D_, 3 * D_, 0, 0, 0, WALPHA);

    // 3. V^T (split pair transpose), batched
    transpose_h_pair<<<dim3(D_ / 32, T_ / 32, B_), tb>>>(
        kqv_hi + 2 * D_, kqv_lo + 2 * D_, vT_hi, vT_lo,
        3 * D_, T_, (long long)T_ * 3 * D_, (long long)D_ * T_);

    // 4. scores = q @ k^T * inv_sqrt_T (3-pass, lower-tri blocks)
    gemm_cs<3, 0, 1><<<dim3(T_ / 128, T_ / 128, B_), 256, SMEM3>>>(
        kqv_hi + D_, kqv_lo + D_, kqv_hi, kqv_lo, nullptr, p_sc, nullptr, nullptr,
        D_, 3 * D_, 3 * D_, T_,
        (long long)T_ * 3 * D_, (long long)T_ * 3 * D_, (long long)T_ * T_, inv_sqrt_T);

    // 5. softmax -> split probs
    softmax_split<<<dim3(T_, B_), 256>>>(p_sc, pp_hi, pp_lo);

    // 6. attn @ v (3-pass, K clipped) -> fp16 at
    gemm_cs<3, 2, 2><<<dim3(D_ / 128, T_ / 128, B_), 256, SMEM3>>>(
        pp_hi, pp_lo, vT_hi, vT_lo, nullptr, nullptr, p_at, nullptr,
        T_, T_, T_, D_,
        (long long)T_ * T_, (long long)D_ * T_, (long long)T_ * D_, 1.f);

    // 7. proj (2-pass) -> fp32 a
    gemm_cs<2, 0, 0><<<dim3(D_ / 128, ROWS / 128, 1), 256, SMEM2>>>(
        p_at, nullptr, Wp_hi, Wp_lo, bproj, p_a, nullptr, nullptr,
        D_, D_, D_, D_, 0, 0, 0, WALPHA);

    // 8. LN2 -> fp16 h2
    ln_half<<<ROWS, 256>>>(p_a, ln2_g, ln2_b, p_h2);

    // 9. MLP up + GELU (2-pass) -> fp16 mid
    gemm_cs<2, 3, 0><<<dim3(4 * D_ / 128, ROWS / 128, 1), 256, SMEM2>>>(
        p_h2, nullptr, W1_hi, W1_lo, b1, nullptr, p_mid, nullptr,
        D_, D_, D_, 4 * D_, 0, 0, 0, WALPHA);

    // 10. MLP down (2-pass) -> fp32 out
    gemm_cs<2, 0, 0><<<dim3(D_ / 128, ROWS / 128, 1), 256, SMEM2>>>(
        p_mid, nullptr, W2_hi, W2_lo, b2, out, nullptr, nullptr,
        4 * D_, 4 * D_, 4 * D_, D_, 0, 0, 0, WALPHA);
}

// round 7
// speedup vs baseline: 4.9106x; 1.0777x over previous
#include <cuda_runtime.h>
#include <cuda_fp16.h>
#include <math.h>
#include <stdint.h>

// Problem constants
#define B_ 4
#define T_ 2048
#define D_ 1024
#define ROWS (B_ * T_)        // 8192
#define EPS 1e-5f

typedef __half fp16;

// ---------------------------------------------------------------------------
// Scratch (allocation-free: __device__ globals)
// ---------------------------------------------------------------------------
__device__ float g_a  [ROWS * D_];              // fp32 proj out (LN2 input)

__device__ fp16 g_sc16 [(size_t)B_ * T_ * T_];  // fp16 scores
__device__ fp16 g_p    [(size_t)B_ * T_ * T_];  // fp16 probs
__device__ fp16 g_h    [ROWS * D_];
__device__ fp16 g_kqv_hi[ROWS * 3 * D_],  g_kqv_lo[ROWS * 3 * D_];
__device__ fp16 g_vT_hi[(size_t)B_ * D_ * T_], g_vT_lo[(size_t)B_ * D_ * T_];
__device__ fp16 g_at   [ROWS * D_];
__device__ fp16 g_h2   [ROWS * D_];
__device__ fp16 g_mid  [ROWS * 4 * D_];
__device__ fp16 g_Wqkv_hi[3 * D_ * D_],   g_Wqkv_lo[3 * D_ * D_];
__device__ fp16 g_Wprj_hi[D_ * D_],       g_Wprj_lo[D_ * D_];
__device__ fp16 g_W1_hi  [4 * D_ * D_],   g_W1_lo  [4 * D_ * D_];
__device__ fp16 g_W2_hi  [D_ * 4 * D_],   g_W2_lo  [D_ * 4 * D_];

#define WSCALE 32.0f
#define WALPHA (1.0f / 32.0f)

// ---------------------------------------------------------------------------
// helpers
// ---------------------------------------------------------------------------
__device__ __forceinline__ void split1(float v, fp16& h, fp16& l) {
    h = __float2half_rn(v);
    l = __float2half_rn(v - __half2float(h));
}
__device__ __forceinline__ uint32_t pack2h(fp16 a, fp16 b) {
    return (uint32_t)__half_as_ushort(a) | ((uint32_t)__half_as_ushort(b) << 16);
}
__device__ __forceinline__ void mma_fp16(float* d, const uint32_t* a, const uint32_t* b) {
    asm volatile(
        "mma.sync.aligned.m16n8k16.row.col.f32.f16.f16.f32 "
        "{%0,%1,%2,%3}, {%4,%5,%6,%7}, {%8,%9}, {%0,%1,%2,%3};"
        : "+f"(d[0]), "+f"(d[1]), "+f"(d[2]), "+f"(d[3])
        : "r"(a[0]), "r"(a[1]), "r"(a[2]), "r"(a[3]),
          "r"(b[0]), "r"(b[1]));
}
__device__ __forceinline__ uint32_t smem_u32(const void* p) {
    uint32_t a;
    asm("{ .reg .u64 t; cvta.to.shared.u64 t, %1; cvt.u32.u64 %0, t; }" : "=r"(a) : "l"(p));
    return a;
}
__device__ __forceinline__ void cp16(uint32_t dst, const void* src) {
    asm volatile("cp.async.ca.shared.global [%0], [%1], 16;" :: "r"(dst), "l"(src));
}
#define CP_COMMIT() asm volatile("cp.async.commit_group;" ::: "memory")
#define CP_WAIT(n)  asm volatile("cp.async.wait_group %0;" :: "n"(n) : "memory")

#define LDSM_X4(d0, d1, d2, d3, addr) \
    asm volatile("ldmatrix.sync.aligned.m8n8.x4.shared.b16 {%0,%1,%2,%3}, [%4];" \
        : "=r"(d0), "=r"(d1), "=r"(d2), "=r"(d3) : "r"(addr))

// SMEM tile geometry: 128 rows x 32 fp16, row stride 40 elems (80B)
#define TILE_BYTES 10240

// ---------------------------------------------------------------------------
// GEMM: C[M,N] = alpha*(A @ B^T) (+bias)
// PASSES=2: A fp16 (rounded), B hi+lo.   PASSES=3: A hi+lo, B hi+lo.
// Tile order in stage: A_hi, B_hi, B_lo, [A_lo]
// EPI: 0=fp32 out, 1=split hi+lo out, 2=fp16 out, 3=gelu+fp16 out
// CMODE: 0=dense, 1=causal block skip, 2=causal K clip
// ---------------------------------------------------------------------------
template <int PASSES, int EPI, int CMODE>
__global__ void __launch_bounds__(256) gemm_cs(
    const fp16* __restrict__ Ahi, const fp16* __restrict__ Alo,
    const fp16* __restrict__ Bhi, const fp16* __restrict__ Blo,
    const float* __restrict__ bias,
    float* __restrict__ Cf, fp16* __restrict__ Chi, fp16* __restrict__ Clo,
    int K, int lda, int ldb, int ldc,
    long long sA, long long sB, long long sC, float alpha)
{
    constexpr int NTILES = (PASSES == 3) ? 4 : 3;
    constexpr int STAGE_BYTES = NTILES * TILE_BYTES;

    const int bx = blockIdx.x, by = blockIdx.y, bz = blockIdx.z;
    if (CMODE == 1 && bx > by) return;

    extern __shared__ fp16 smem[];
    const uint32_t sb = smem_u32(smem);

    Ahi += sA * bz;
    if (PASSES == 3) Alo += sA * bz;
    Bhi += sB * bz; Blo += sB * bz;

    const int m0 = by * 128, n0 = bx * 128;
    int Kend = K;
    if (CMODE == 2) { int ke = (by + 1) * 128; if (ke < K) Kend = ke; }
    const int NC = Kend >> 5;

    const int tid = threadIdx.x;
    const int wid = tid >> 5, lane = tid & 31;
    const int wm = wid & 1, wn = wid >> 1;
    const int g = lane >> 2, tig = lane & 3;

    const uint32_t a_loff = (uint32_t)(((lane & 7) + ((lane >> 3) & 1) * 8) * 80 + ((lane >> 4) & 1) * 16);
    const uint32_t b_loff = (uint32_t)(((lane & 7) + ((lane >> 4) & 1) * 8) * 80 + ((lane >> 3) & 1) * 16);

    const int lrow = tid >> 1;
    const int lc   = (tid & 1) * 2;

    const fp16* pA_hi = Ahi + (size_t)(m0 + lrow) * lda + lc * 8;
    const fp16* pA_lo = (PASSES == 3) ? (Alo + (size_t)(m0 + lrow) * lda + lc * 8) : nullptr;
    const fp16* pB_hi = Bhi + (size_t)(n0 + lrow) * ldb + lc * 8;
    const fp16* pB_lo = Blo + (size_t)(n0 + lrow) * ldb + lc * 8;
    const uint32_t dbase = sb + lrow * 80 + lc * 16;

    auto issue = [&](int kc, int buf) {
        const uint32_t d0 = dbase + buf * STAGE_BYTES;
        const int ko = kc * 32;
        cp16(d0,                     pA_hi + ko);
        cp16(d0 + 16,                pA_hi + ko + 8);
        cp16(d0 + TILE_BYTES,        pB_hi + ko);
        cp16(d0 + TILE_BYTES + 16,   pB_hi + ko + 8);
        cp16(d0 + 2*TILE_BYTES,      pB_lo + ko);
        cp16(d0 + 2*TILE_BYTES + 16, pB_lo + ko + 8);
        if (PASSES == 3) {
            cp16(d0 + 3*TILE_BYTES,      pA_lo + ko);
            cp16(d0 + 3*TILE_BYTES + 16, pA_lo + ko + 8);
        }
    };

    float acc[4][4][4];
    #pragma unroll
    for (int i = 0; i < 4; i++)
        #pragma unroll
        for (int j = 0; j < 4; j++)
            #pragma unroll
            for (int r = 0; r < 4; r++) acc[i][j][r] = 0.f;

    issue(0, 0);
    CP_COMMIT();

    int buf = 0;
    for (int kc = 0; kc < NC; kc++) {
        if (kc + 1 < NC) {
            issue(kc + 1, buf ^ 1);
            CP_COMMIT();
            CP_WAIT(1);
        } else {
            CP_WAIT(0);
        }
        __syncthreads();

        const uint32_t stage = sb + buf * STAGE_BYTES;
        const uint32_t aH = stage + (uint32_t)(wm * 64 * 80) + a_loff;
        const uint32_t bH = stage + TILE_BYTES + (uint32_t)(wn * 32 * 80) + b_loff;
        const uint32_t bL = bH + TILE_BYTES;
        const uint32_t aL = aH + 3 * TILE_BYTES;

        #pragma unroll
        for (int kk2 = 0; kk2 < 64; kk2 += 32) {
            uint32_t af[4][4], bh[4][2], bl[4][2];
            #pragma unroll
            for (int mt = 0; mt < 4; mt++)
                LDSM_X4(af[mt][0], af[mt][1], af[mt][2], af[mt][3], aH + mt * 1280 + kk2);
            #pragma unroll
            for (int p = 0; p < 2; p++)
                LDSM_X4(bh[2*p][0], bh[2*p][1], bh[2*p+1][0], bh[2*p+1][1], bH + p * 1280 + kk2);
            // pass 1: A_hi x B_hi
            #pragma unroll
            for (int mt = 0; mt < 4; mt++)
                #pragma unroll
                for (int nt = 0; nt < 4; nt++)
                    mma_fp16(acc[mt][nt], af[mt], bh[nt]);
            // pass 2: A_hi x B_lo
            #pragma unroll
            for (int p = 0; p < 2; p++)
                LDSM_X4(bl[2*p][0], bl[2*p][1], bl[2*p+1][0], bl[2*p+1][1], bL + p * 1280 + kk2);
            #pragma unroll
            for (int mt = 0; mt < 4; mt++)
                #pragma unroll
                for (int nt = 0; nt < 4; nt++)
                    mma_fp16(acc[mt][nt], af[mt], bl[nt]);
            // pass 3: A_lo x B_hi
            if (PASSES == 3) {
                #pragma unroll
                for (int mt = 0; mt < 4; mt++)
                    LDSM_X4(af[mt][0], af[mt][1], af[mt][2], af[mt][3], aL + mt * 1280 + kk2);
                #pragma unroll
                for (int mt = 0; mt < 4; mt++)
                    #pragma unroll
                    for (int nt = 0; nt < 4; nt++)
                        mma_fp16(acc[mt][nt], af[mt], bh[nt]);
            }
        }
        __syncthreads();
        buf ^= 1;
    }

    // epilogue
    if (EPI == 0) Cf += sC * bz;
    else { Chi += sC * bz; if (EPI == 1) Clo += sC * bz; }

    #pragma unroll
    for (int mt = 0; mt < 4; mt++) {
        #pragma unroll
        for (int nt = 0; nt < 4; nt++) {
            int m = m0 + wm * 64 + mt * 16 + g;
            int n = n0 + wn * 32 + nt * 8 + tig * 2;
            float2 bv = make_float2(0.f, 0.f);
            if (bias) bv = __ldg((const float2*)(bias + n));
            #pragma unroll
            for (int half_ = 0; half_ < 2; half_++) {
                float vx = acc[mt][nt][half_ * 2 + 0] * alpha + bv.x;
                float vy = acc[mt][nt][half_ * 2 + 1] * alpha + bv.y;
                if (EPI == 3) {
                    const float c0 = 0.7978845608028654f, c1 = 0.044715f;
                    vx = 0.5f * vx * (1.f + tanhf(c0 * (vx + c1 * vx * vx * vx)));
                    vy = 0.5f * vy * (1.f + tanhf(c0 * (vy + c1 * vy * vy * vy)));
                }
                size_t off = (size_t)(m + half_ * 8) * ldc + n;
                if (EPI == 0) {
                    *(float2*)(Cf + off) = make_float2(vx, vy);
                } else if (EPI == 1) {
                    fp16 hx, lx, hy, ly;
                    split1(vx, hx, lx);
                    split1(vy, hy, ly);
                    *(uint32_t*)(Chi + off) = pack2h(hx, hy);
                    *(uint32_t*)(Clo + off) = pack2h(lx, ly);
                } else {
                    *(uint32_t*)(Chi + off) = pack2h(__float2half_rn(vx), __float2half_rn(vy));
                }
            }
        }
    }
}

// ---------------------------------------------------------------------------
// Weight transpose + scale + split
// ---------------------------------------------------------------------------
__global__ void __launch_bounds__(256) transpose_split_f32(
    const float* __restrict__ in, fp16* __restrict__ ohi, fp16* __restrict__ olo,
    int ldi, int ldo, float scale)
{
    __shared__ float t[32][33];
    const int c0 = blockIdx.x * 32, r0 = blockIdx.y * 32;
    const int x = threadIdx.x, y = threadIdx.y;
    #pragma unroll
    for (int i = 0; i < 4; i++)
        t[y + i * 8][x] = in[(size_t)(r0 + y + i * 8) * ldi + c0 + x];
    __syncthreads();
    #pragma unroll
    for (int i = 0; i < 4; i++) {
        float v = t[x][y + i * 8] * scale;
        fp16 h, l;
        split1(v, h, l);
        size_t off = (size_t)(c0 + y + i * 8) * ldo + r0 + x;
        ohi[off] = h;
        olo[off] = l;
    }
}

// ---------------------------------------------------------------------------
// fp16 pair transpose (V -> V^T), batched
// ---------------------------------------------------------------------------
__global__ void __launch_bounds__(256) transpose_h_pair(
    const fp16* __restrict__ ihi, const fp16* __restrict__ ilo,
    fp16* __restrict__ ohi, fp16* __restrict__ olo,
    int ldi, int ldo, long long sI, long long sO)
{
    __shared__ fp16 th[32][33], tl[32][33];
    ihi += sI * blockIdx.z; ilo += sI * blockIdx.z;
    ohi += sO * blockIdx.z; olo += sO * blockIdx.z;
    const int c0 = blockIdx.x * 32, r0 = blockIdx.y * 32;
    const int x = threadIdx.x, y = threadIdx.y;
    #pragma unroll
    for (int i = 0; i < 4; i++) {
        size_t off = (size_t)(r0 + y + i * 8) * ldi + c0 + x;
        th[y + i * 8][x] = ihi[off];
        tl[y + i * 8][x] = ilo[off];
    }
    __syncthreads();
    #pragma unroll
    for (int i = 0; i < 4; i++) {
        size_t off = (size_t)(c0 + y + i * 8) * ldo + r0 + x;
        ohi[off] = th[x][y + i * 8];
        olo[off] = tl[x][y + i * 8];
    }
}

// ---------------------------------------------------------------------------
// LayerNorm -> fp16 out (row cached in SMEM)
// ---------------------------------------------------------------------------
__global__ void __launch_bounds__(256) ln_half(
    const float* __restrict__ x, const float* __restrict__ gamma,
    const float* __restrict__ beta, fp16* __restrict__ o)
{
    __shared__ float xc[D_];
    const int row = blockIdx.x;
    const float* xr = x + (size_t)row * D_;

    float s = 0.f, ss = 0.f;
    for (int i = threadIdx.x; i < D_; i += 256) {
        float v = xr[i];
        xc[i] = v;
        s += v; ss += v * v;
    }
    __shared__ float rs[8], rss[8];
    #pragma unroll
    for (int o2 = 16; o2 > 0; o2 >>= 1) {
        s  += __shfl_down_sync(0xffffffffu, s,  o2);
        ss += __shfl_down_sync(0xffffffffu, ss, o2);
    }
    int wid = threadIdx.x >> 5, lid = threadIdx.x & 31;
    if (lid == 0) { rs[wid] = s; rss[wid] = ss; }
    __syncthreads();
    __shared__ float s_mu, s_rstd;
    if (threadIdx.x == 0) {
        float ts = 0.f, tss = 0.f;
        #pragma unroll
        for (int i = 0; i < 8; i++) { ts += rs[i]; tss += rss[i]; }
        float mu = ts / D_;
        float var = tss / D_ - mu * mu;
        s_mu = mu;
        s_rstd = rsqrtf(var + EPS);
    }
    __syncthreads();
    float mu = s_mu, rstd = s_rstd;
    for (int i = threadIdx.x; i < D_; i += 256) {
        float v = (xc[i] - mu) * rstd * gamma[i] + beta[i];
        o[(size_t)row * D_ + i] = __float2half_rn(v);
    }
}

// ---------------------------------------------------------------------------
// Causal softmax: fp16 scores -> fp16 probs (zero-fill only to block edge)
// ---------------------------------------------------------------------------
__global__ void __launch_bounds__(256) softmax_h(
    const fp16* __restrict__ sc, fp16* __restrict__ pr)
{
    __shared__ float cache[T_];
    const int t = blockIdx.x, b = blockIdx.y;
    const size_t ro = ((size_t)b * T_ + t) * T_;
    const fp16* row = sc + ro;
    const int n = t + 1;
    const int blk_end = ((t >> 7) + 1) << 7;   // causal K-clip boundary

    __shared__ float red[8];
    __shared__ float s_bc;

    float mx = -INFINITY;
    for (int i = threadIdx.x; i < n; i += 256) {
        float v = __half2float(row[i]);
        cache[i] = v;
        mx = fmaxf(mx, v);
    }
    #pragma unroll
    for (int o = 16; o > 0; o >>= 1) mx = fmaxf(mx, __shfl_down_sync(0xffffffffu, mx, o));
    int wid = threadIdx.x >> 5, lid = threadIdx.x & 31;
    if (lid == 0) red[wid] = mx;
    __syncthreads();
    if (threadIdx.x == 0) {
        float m = red[0];
        #pragma unroll
        for (int i = 1; i < 8; i++) m = fmaxf(m, red[i]);
        s_bc = m;
    }
    __syncthreads();
    mx = s_bc;

    float sum = 0.f;
    for (int i = threadIdx.x; i < n; i += 256) {
        float e = expf(cache[i] - mx);
        cache[i] = e;
        sum += e;
    }
    #pragma unroll
    for (int o = 16; o > 0; o >>= 1) sum += __shfl_down_sync(0xffffffffu, sum, o);
    if (lid == 0) red[wid] = sum;
    __syncthreads();
    if (threadIdx.x == 0) {
        float tot = 0.f;
        #pragma unroll
        for (int i = 0; i < 8; i++) tot += red[i];
        s_bc = 1.f / tot;
    }
    __syncthreads();
    float inv = s_bc;
    for (int i = threadIdx.x; i < n; i += 256)
        pr[ro + i] = __float2half_rn(cache[i] * inv);
    const fp16 z = __float2half(0.f);
    for (int i = n + threadIdx.x; i < blk_end; i += 256)
        pr[ro + i] = z;
}

// ---------------------------------------------------------------------------
// launch
// ---------------------------------------------------------------------------
extern "C" void kernel_launch(void* const* d_in, const int* in_sizes, int n_in,
                              void* d_out, int out_size)
{
    const float* x     = (const float*)d_in[0];
    const float* ln1_g = (const float*)d_in[1];
    const float* ln1_b = (const float*)d_in[2];
    const float* Wqkv  = (const float*)d_in[3];
    const float* bqkv  = (const float*)d_in[4];
    const float* Wproj = (const float*)d_in[5];
    const float* bproj = (const float*)d_in[6];
    const float* ln2_g = (const float*)d_in[7];
    const float* ln2_b = (const float*)d_in[8];
    const float* W1    = (const float*)d_in[9];
    const float* b1    = (const float*)d_in[10];
    const float* W2    = (const float*)d_in[11];
    const float* b2    = (const float*)d_in[12];
    float* out = (float*)d_out;

    float *p_a;
    fp16 *p_sc16, *p_p, *p_h, *kqv_hi, *kqv_lo, *vT_hi, *vT_lo;
    fp16 *p_at, *p_h2, *p_mid;
    fp16 *Wq_hi, *Wq_lo, *Wp_hi, *Wp_lo, *W1_hi, *W1_lo, *W2_hi, *W2_lo;

    cudaGetSymbolAddress((void**)&p_a,    g_a);
    cudaGetSymbolAddress((void**)&p_sc16, g_sc16);
    cudaGetSymbolAddress((void**)&p_p,    g_p);
    cudaGetSymbolAddress((void**)&p_h,    g_h);
    cudaGetSymbolAddress((void**)&kqv_hi, g_kqv_hi); cudaGetSymbolAddress((void**)&kqv_lo, g_kqv_lo);
    cudaGetSymbolAddress((void**)&vT_hi,  g_vT_hi);  cudaGetSymbolAddress((void**)&vT_lo,  g_vT_lo);
    cudaGetSymbolAddress((void**)&p_at,   g_at);
    cudaGetSymbolAddress((void**)&p_h2,   g_h2);
    cudaGetSymbolAddress((void**)&p_mid,  g_mid);
    cudaGetSymbolAddress((void**)&Wq_hi,  g_Wqkv_hi); cudaGetSymbolAddress((void**)&Wq_lo, g_Wqkv_lo);
    cudaGetSymbolAddress((void**)&Wp_hi,  g_Wprj_hi); cudaGetSymbolAddress((void**)&Wp_lo, g_Wprj_lo);
    cudaGetSymbolAddress((void**)&W1_hi,  g_W1_hi);  cudaGetSymbolAddress((void**)&W1_lo,  g_W1_lo);
    cudaGetSymbolAddress((void**)&W2_hi,  g_W2_hi);  cudaGetSymbolAddress((void**)&W2_lo,  g_W2_lo);

    const int SMEM2 = 2 * 3 * TILE_BYTES;   // 61440
    cudaFuncSetAttribute((const void*)gemm_cs<2, 1, 0>, cudaFuncAttributeMaxDynamicSharedMemorySize, SMEM2);
    cudaFuncSetAttribute((const void*)gemm_cs<2, 0, 0>, cudaFuncAttributeMaxDynamicSharedMemorySize, SMEM2);
    cudaFuncSetAttribute((const void*)gemm_cs<2, 3, 0>, cudaFuncAttributeMaxDynamicSharedMemorySize, SMEM2);
    cudaFuncSetAttribute((const void*)gemm_cs<2, 2, 0>, cudaFuncAttributeMaxDynamicSharedMemorySize, SMEM2);
    cudaFuncSetAttribute((const void*)gemm_cs<2, 2, 1>, cudaFuncAttributeMaxDynamicSharedMemorySize, SMEM2);
    cudaFuncSetAttribute((const void*)gemm_cs<2, 2, 2>, cudaFuncAttributeMaxDynamicSharedMemorySize, SMEM2);

    const float inv_sqrt_T = 1.0f / sqrtf((float)T_);
    dim3 tb(32, 8);

    // Weight transpose + x32 scale + split (once)
    transpose_split_f32<<<dim3(3 * D_ / 32, D_ / 32), tb>>>(Wqkv,  Wq_hi, Wq_lo, 3 * D_, D_, WSCALE);
    transpose_split_f32<<<dim3(D_ / 32,     D_ / 32), tb>>>(Wproj, Wp_hi, Wp_lo, D_,     D_, WSCALE);
    transpose_split_f32<<<dim3(4 * D_ / 32, D_ / 32), tb>>>(W1,    W1_hi, W1_lo, 4 * D_, D_, WSCALE);
    transpose_split_f32<<<dim3(D_ / 32, 4 * D_ / 32), tb>>>(W2,    W2_hi, W2_lo, D_, 4 * D_, WSCALE);

    // 1. LN1 -> fp16 h
    ln_half<<<ROWS, 256>>>(x, ln1_g, ln1_b, p_h);

    // 2. QKV GEMM (2-pass) -> split kqv (k/v need hi+lo as B operands later)
    gemm_cs<2, 1, 0><<<dim3(3 * D_ / 128, ROWS / 128, 1), 256, SMEM2>>>(
        p_h, nullptr, Wq_hi, Wq_lo, bqkv, nullptr, kqv_hi, kqv_lo,
        D_, D_, D_, 3 * D_, 0, 0, 0, WALPHA);

    // 3. V^T (split pair transpose), batched
    transpose_h_pair<<<dim3(D_ / 32, T_ / 32, B_), tb>>>(
        kqv_hi + 2 * D_, kqv_lo + 2 * D_, vT_hi, vT_lo,
        3 * D_, T_, (long long)T_ * 3 * D_, (long long)D_ * T_);

    // 4. scores = q_hi @ k^T * inv_sqrt_T (2-pass, lower-tri blocks) -> fp16
    gemm_cs<2, 2, 1><<<dim3(T_ / 128, T_ / 128, B_), 256, SMEM2>>>(
        kqv_hi + D_, nullptr, kqv_hi, kqv_lo, nullptr, nullptr, p_sc16, nullptr,
        D_, 3 * D_, 3 * D_, T_,
        (long long)T_ * 3 * D_, (long long)T_ * 3 * D_, (long long)T_ * T_, inv_sqrt_T);

    // 5. softmax -> fp16 probs
    softmax_h<<<dim3(T_, B_), 256>>>(p_sc16, p_p);

    // 6. attn @ v (2-pass, K clipped) -> fp16 at
    gemm_cs<2, 2, 2><<<dim3(D_ / 128, T_ / 128, B_), 256, SMEM2>>>(
        p_p, nullptr, vT_hi, vT_lo, nullptr, nullptr, p_at, nullptr,
        T_, T_, T_, D_,
        (long long)T_ * T_, (long long)D_ * T_, (long long)T_ * D_, 1.f);

    // 7. proj (2-pass) -> fp32 a
    gemm_cs<2, 0, 0><<<dim3(D_ / 128, ROWS / 128, 1), 256, SMEM2>>>(
        p_at, nullptr, Wp_hi, Wp_lo, bproj, p_a, nullptr, nullptr,
        D_, D_, D_, D_, 0, 0, 0, WALPHA);

    // 8. LN2 -> fp16 h2
    ln_half<<<ROWS, 256>>>(p_a, ln2_g, ln2_b, p_h2);

    // 9. MLP up + GELU (2-pass) -> fp16 mid
    gemm_cs<2, 3, 0><<<dim3(4 * D_ / 128, ROWS / 128, 1), 256, SMEM2>>>(
        p_h2, nullptr, W1_hi, W1_lo, b1, nullptr, p_mid, nullptr,
        D_, D_, D_, 4 * D_, 0, 0, 0, WALPHA);

    // 10. MLP down (2-pass) -> fp32 out
    gemm_cs<2, 0, 0><<<dim3(D_ / 128, ROWS / 128, 1), 256, SMEM2>>>(
        p_mid, nullptr, W2_hi, W2_lo, b2, out, nullptr, nullptr,
        4 * D_, 4 * D_, 4 * D_, D_, 0, 0, 0, WALPHA);
}

// round 8
// speedup vs baseline: 5.2187x; 1.0627x over previous
#include <cuda_runtime.h>
#include <cuda_fp16.h>
#include <math.h>
#include <stdint.h>

// Problem constants
#define B_ 4
#define T_ 2048
#define D_ 1024
#define ROWS (B_ * T_)        // 8192
#define EPS 1e-5f

typedef __half fp16;

// ---------------------------------------------------------------------------
// Scratch (allocation-free: __device__ globals)
// ---------------------------------------------------------------------------
__device__ float g_a  [ROWS * D_];              // fp32 proj out (LN2 input)

__device__ fp16 g_sc16 [(size_t)B_ * T_ * T_];  // fp16 scores
__device__ fp16 g_p    [(size_t)B_ * T_ * T_];  // fp16 probs
__device__ fp16 g_h    [ROWS * D_];
__device__ fp16 g_kqv  [ROWS * 3 * D_];         // plain fp16 (1-pass attention)
__device__ fp16 g_vT   [(size_t)B_ * D_ * T_];
__device__ fp16 g_at   [ROWS * D_];
__device__ fp16 g_h2   [ROWS * D_];
__device__ fp16 g_mid  [ROWS * 4 * D_];
__device__ fp16 g_Wqkv_hi[3 * D_ * D_],   g_Wqkv_lo[3 * D_ * D_];
__device__ fp16 g_Wprj_hi[D_ * D_],       g_Wprj_lo[D_ * D_];
__device__ fp16 g_W1_hi  [4 * D_ * D_],   g_W1_lo  [4 * D_ * D_];
__device__ fp16 g_W2_hi  [D_ * 4 * D_],   g_W2_lo  [D_ * 4 * D_];

#define WSCALE 32.0f
#define WALPHA (1.0f / 32.0f)

// ---------------------------------------------------------------------------
// helpers
// ---------------------------------------------------------------------------
__device__ __forceinline__ void split1(float v, fp16& h, fp16& l) {
    h = __float2half_rn(v);
    l = __float2half_rn(v - __half2float(h));
}
__device__ __forceinline__ uint32_t pack2h(fp16 a, fp16 b) {
    return (uint32_t)__half_as_ushort(a) | ((uint32_t)__half_as_ushort(b) << 16);
}
__device__ __forceinline__ void mma_fp16(float* d, const uint32_t* a, const uint32_t* b) {
    asm volatile(
        "mma.sync.aligned.m16n8k16.row.col.f32.f16.f16.f32 "
        "{%0,%1,%2,%3}, {%4,%5,%6,%7}, {%8,%9}, {%0,%1,%2,%3};"
        : "+f"(d[0]), "+f"(d[1]), "+f"(d[2]), "+f"(d[3])
        : "r"(a[0]), "r"(a[1]), "r"(a[2]), "r"(a[3]),
          "r"(b[0]), "r"(b[1]));
}
__device__ __forceinline__ uint32_t smem_u32(const void* p) {
    uint32_t a;
    asm("{ .reg .u64 t; cvta.to.shared.u64 t, %1; cvt.u32.u64 %0, t; }" : "=r"(a) : "l"(p));
    return a;
}
__device__ __forceinline__ void cp16(uint32_t dst, const void* src) {
    asm volatile("cp.async.ca.shared.global [%0], [%1], 16;" :: "r"(dst), "l"(src));
}
#define CP_COMMIT() asm volatile("cp.async.commit_group;" ::: "memory")
#define CP_WAIT(n)  asm volatile("cp.async.wait_group %0;" :: "n"(n) : "memory")

#define LDSM_X4(d0, d1, d2, d3, addr) \
    asm volatile("ldmatrix.sync.aligned.m8n8.x4.shared.b16 {%0,%1,%2,%3}, [%4];" \
        : "=r"(d0), "=r"(d1), "=r"(d2), "=r"(d3) : "r"(addr))

// SMEM tile geometry: 128 rows x 32 fp16, row stride 40 elems (80B)
#define TILE_BYTES 10240

// ---------------------------------------------------------------------------
// GEMM: C[M,N] = alpha*(A @ B^T) (+bias)
// PASSES=1: A fp16, B fp16.  PASSES=2: A fp16, B hi+lo.  PASSES=3: A,B hi+lo.
// Tile order in stage: A_hi, B_hi, [B_lo], [A_lo]
// EPI: 0=fp32 out, 2=fp16 out, 3=gelu+fp16 out
// CMODE: 0=dense, 1=causal block skip, 2=causal K clip
// ---------------------------------------------------------------------------
template <int PASSES, int EPI, int CMODE>
__global__ void __launch_bounds__(256) gemm_cs(
    const fp16* __restrict__ Ahi, const fp16* __restrict__ Alo,
    const fp16* __restrict__ Bhi, const fp16* __restrict__ Blo,
    const float* __restrict__ bias,
    float* __restrict__ Cf, fp16* __restrict__ Chi,
    int K, int lda, int ldb, int ldc,
    long long sA, long long sB, long long sC, float alpha)
{
    constexpr int NTILES = (PASSES == 3) ? 4 : (PASSES == 2 ? 3 : 2);
    constexpr int STAGE_BYTES = NTILES * TILE_BYTES;

    const int bx = blockIdx.x, by = blockIdx.y, bz = blockIdx.z;
    if (CMODE == 1 && bx > by) return;

    extern __shared__ fp16 smem[];
    const uint32_t sb = smem_u32(smem);

    Ahi += sA * bz;
    if (PASSES == 3) Alo += sA * bz;
    Bhi += sB * bz;
    if (PASSES >= 2) Blo += sB * bz;

    const int m0 = by * 128, n0 = bx * 128;
    int Kend = K;
    if (CMODE == 2) { int ke = (by + 1) * 128; if (ke < K) Kend = ke; }
    const int NC = Kend >> 5;

    const int tid = threadIdx.x;
    const int wid = tid >> 5, lane = tid & 31;
    const int wm = wid & 1, wn = wid >> 1;
    const int g = lane >> 2, tig = lane & 3;

    const uint32_t a_loff = (uint32_t)(((lane & 7) + ((lane >> 3) & 1) * 8) * 80 + ((lane >> 4) & 1) * 16);
    const uint32_t b_loff = (uint32_t)(((lane & 7) + ((lane >> 4) & 1) * 8) * 80 + ((lane >> 3) & 1) * 16);

    const int lrow = tid >> 1;
    const int lc   = (tid & 1) * 2;

    const fp16* pA_hi = Ahi + (size_t)(m0 + lrow) * lda + lc * 8;
    const fp16* pA_lo = (PASSES == 3) ? (Alo + (size_t)(m0 + lrow) * lda + lc * 8) : nullptr;
    const fp16* pB_hi = Bhi + (size_t)(n0 + lrow) * ldb + lc * 8;
    const fp16* pB_lo = (PASSES >= 2) ? (Blo + (size_t)(n0 + lrow) * ldb + lc * 8) : nullptr;
    const uint32_t dbase = sb + lrow * 80 + lc * 16;

    auto issue = [&](int kc, int buf) {
        const uint32_t d0 = dbase + buf * STAGE_BYTES;
        const int ko = kc * 32;
        cp16(d0,                     pA_hi + ko);
        cp16(d0 + 16,                pA_hi + ko + 8);
        cp16(d0 + TILE_BYTES,        pB_hi + ko);
        cp16(d0 + TILE_BYTES + 16,   pB_hi + ko + 8);
        if (PASSES >= 2) {
            cp16(d0 + 2*TILE_BYTES,      pB_lo + ko);
            cp16(d0 + 2*TILE_BYTES + 16, pB_lo + ko + 8);
        }
        if (PASSES == 3) {
            cp16(d0 + 3*TILE_BYTES,      pA_lo + ko);
            cp16(d0 + 3*TILE_BYTES + 16, pA_lo + ko + 8);
        }
    };

    float acc[4][4][4];
    #pragma unroll
    for (int i = 0; i < 4; i++)
        #pragma unroll
        for (int j = 0; j < 4; j++)
            #pragma unroll
            for (int r = 0; r < 4; r++) acc[i][j][r] = 0.f;

    issue(0, 0);
    CP_COMMIT();

    int buf = 0;
    for (int kc = 0; kc < NC; kc++) {
        if (kc + 1 < NC) {
            issue(kc + 1, buf ^ 1);
            CP_COMMIT();
            CP_WAIT(1);
        } else {
            CP_WAIT(0);
        }
        __syncthreads();

        const uint32_t stage = sb + buf * STAGE_BYTES;
        const uint32_t aH = stage + (uint32_t)(wm * 64 * 80) + a_loff;
        const uint32_t bH = stage + TILE_BYTES + (uint32_t)(wn * 32 * 80) + b_loff;
        const uint32_t bL = bH + TILE_BYTES;
        const uint32_t aL = aH + 3 * TILE_BYTES;

        #pragma unroll
        for (int kk2 = 0; kk2 < 64; kk2 += 32) {
            uint32_t af[4][4], bh[4][2], bl[4][2];
            #pragma unroll
            for (int mt = 0; mt < 4; mt++)
                LDSM_X4(af[mt][0], af[mt][1], af[mt][2], af[mt][3], aH + mt * 1280 + kk2);
            #pragma unroll
            for (int p = 0; p < 2; p++)
                LDSM_X4(bh[2*p][0], bh[2*p][1], bh[2*p+1][0], bh[2*p+1][1], bH + p * 1280 + kk2);
            // pass 1: A_hi x B_hi
            #pragma unroll
            for (int mt = 0; mt < 4; mt++)
                #pragma unroll
                for (int nt = 0; nt < 4; nt++)
                    mma_fp16(acc[mt][nt], af[mt], bh[nt]);
            // pass 2: A_hi x B_lo
            if (PASSES >= 2) {
                #pragma unroll
                for (int p = 0; p < 2; p++)
                    LDSM_X4(bl[2*p][0], bl[2*p][1], bl[2*p+1][0], bl[2*p+1][1], bL + p * 1280 + kk2);
                #pragma unroll
                for (int mt = 0; mt < 4; mt++)
                    #pragma unroll
                    for (int nt = 0; nt < 4; nt++)
                        mma_fp16(acc[mt][nt], af[mt], bl[nt]);
            }
            // pass 3: A_lo x B_hi
            if (PASSES == 3) {
                #pragma unroll
                for (int mt = 0; mt < 4; mt++)
                    LDSM_X4(af[mt][0], af[mt][1], af[mt][2], af[mt][3], aL + mt * 1280 + kk2);
                #pragma unroll
                for (int mt = 0; mt < 4; mt++)
                    #pragma unroll
                    for (int nt = 0; nt < 4; nt++)
                        mma_fp16(acc[mt][nt], af[mt], bh[nt]);
            }
        }
        __syncthreads();
        buf ^= 1;
    }

    // epilogue
    if (EPI == 0) Cf += sC * bz;
    else Chi += sC * bz;

    #pragma unroll
    for (int mt = 0; mt < 4; mt++) {
        #pragma unroll
        for (int nt = 0; nt < 4; nt++) {
            int m = m0 + wm * 64 + mt * 16 + g;
            int n = n0 + wn * 32 + nt * 8 + tig * 2;
            float2 bv = make_float2(0.f, 0.f);
            if (bias) bv = __ldg((const float2*)(bias + n));
            #pragma unroll
            for (int half_ = 0; half_ < 2; half_++) {
                float vx = acc[mt][nt][half_ * 2 + 0] * alpha + bv.x;
                float vy = acc[mt][nt][half_ * 2 + 1] * alpha + bv.y;
                if (EPI == 3) {
                    const float c0 = 0.7978845608028654f, c1 = 0.044715f;
                    vx = 0.5f * vx * (1.f + tanhf(c0 * (vx + c1 * vx * vx * vx)));
                    vy = 0.5f * vy * (1.f + tanhf(c0 * (vy + c1 * vy * vy * vy)));
                }
                size_t off = (size_t)(m + half_ * 8) * ldc + n;
                if (EPI == 0) {
                    *(float2*)(Cf + off) = make_float2(vx, vy);
                } else {
                    *(uint32_t*)(Chi + off) = pack2h(__float2half_rn(vx), __float2half_rn(vy));
                }
            }
        }
    }
}

// ---------------------------------------------------------------------------
// Weight transpose + scale + split
// ---------------------------------------------------------------------------
__global__ void __launch_bounds__(256) transpose_split_f32(
    const float* __restrict__ in, fp16* __restrict__ ohi, fp16* __restrict__ olo,
    int ldi, int ldo, float scale)
{
    __shared__ float t[32][33];
    const int c0 = blockIdx.x * 32, r0 = blockIdx.y * 32;
    const int x = threadIdx.x, y = threadIdx.y;
    #pragma unroll
    for (int i = 0; i < 4; i++)
        t[y + i * 8][x] = in[(size_t)(r0 + y + i * 8) * ldi + c0 + x];
    __syncthreads();
    #pragma unroll
    for (int i = 0; i < 4; i++) {
        float v = t[x][y + i * 8] * scale;
        fp16 h, l;
        split1(v, h, l);
        size_t off = (size_t)(c0 + y + i * 8) * ldo + r0 + x;
        ohi[off] = h;
        olo[off] = l;
    }
}

// ---------------------------------------------------------------------------
// fp16 transpose (V -> V^T), batched
// ---------------------------------------------------------------------------
__global__ void __launch_bounds__(256) transpose_h(
    const fp16* __restrict__ in, fp16* __restrict__ out,
    int ldi, int ldo, long long sI, long long sO)
{
    __shared__ fp16 t[32][33];
    in  += sI * blockIdx.z;
    out += sO * blockIdx.z;
    const int c0 = blockIdx.x * 32, r0 = blockIdx.y * 32;
    const int x = threadIdx.x, y = threadIdx.y;
    #pragma unroll
    for (int i = 0; i < 4; i++)
        t[y + i * 8][x] = in[(size_t)(r0 + y + i * 8) * ldi + c0 + x];
    __syncthreads();
    #pragma unroll
    for (int i = 0; i < 4; i++)
        out[(size_t)(c0 + y + i * 8) * ldo + r0 + x] = t[x][y + i * 8];
}

// ---------------------------------------------------------------------------
// LayerNorm -> fp16 out (row cached in SMEM)
// ---------------------------------------------------------------------------
__global__ void __launch_bounds__(256) ln_half(
    const float* __restrict__ x, const float* __restrict__ gamma,
    const float* __restrict__ beta, fp16* __restrict__ o)
{
    __shared__ float xc[D_];
    const int row = blockIdx.x;
    const float* xr = x + (size_t)row * D_;

    float s = 0.f, ss = 0.f;
    for (int i = threadIdx.x; i < D_; i += 256) {
        float v = xr[i];
        xc[i] = v;
        s += v; ss += v * v;
    }
    __shared__ float rs[8], rss[8];
    #pragma unroll
    for (int o2 = 16; o2 > 0; o2 >>= 1) {
        s  += __shfl_down_sync(0xffffffffu, s,  o2);
        ss += __shfl_down_sync(0xffffffffu, ss, o2);
    }
    int wid = threadIdx.x >> 5, lid = threadIdx.x & 31;
    if (lid == 0) { rs[wid] = s; rss[wid] = ss; }
    __syncthreads();
    __shared__ float s_mu, s_rstd;
    if (threadIdx.x == 0) {
        float ts = 0.f, tss = 0.f;
        #pragma unroll
        for (int i = 0; i < 8; i++) { ts += rs[i]; tss += rss[i]; }
        float mu = ts / D_;
        float var = tss / D_ - mu * mu;
        s_mu = mu;
        s_rstd = rsqrtf(var + EPS);
    }
    __syncthreads();
    float mu = s_mu, rstd = s_rstd;
    for (int i = threadIdx.x; i < D_; i += 256) {
        float v = (xc[i] - mu) * rstd * gamma[i] + beta[i];
        o[(size_t)row * D_ + i] = __float2half_rn(v);
    }
}

// ---------------------------------------------------------------------------
// Causal softmax: fp16 scores -> fp16 probs (zero-fill only to block edge)
// ---------------------------------------------------------------------------
__global__ void __launch_bounds__(256) softmax_h(
    const fp16* __restrict__ sc, fp16* __restrict__ pr)
{
    __shared__ float cache[T_];
    const int t = blockIdx.x, b = blockIdx.y;
    const size_t ro = ((size_t)b * T_ + t) * T_;
    const fp16* row = sc + ro;
    const int n = t + 1;
    const int blk_end = ((t >> 7) + 1) << 7;

    __shared__ float red[8];
    __shared__ float s_bc;

    float mx = -INFINITY;
    for (int i = threadIdx.x; i < n; i += 256) {
        float v = __half2float(row[i]);
        cache[i] = v;
        mx = fmaxf(mx, v);
    }
    #pragma unroll
    for (int o = 16; o > 0; o >>= 1) mx = fmaxf(mx, __shfl_down_sync(0xffffffffu, mx, o));
    int wid = threadIdx.x >> 5, lid = threadIdx.x & 31;
    if (lid == 0) red[wid] = mx;
    __syncthreads();
    if (threadIdx.x == 0) {
        float m = red[0];
        #pragma unroll
        for (int i = 1; i < 8; i++) m = fmaxf(m, red[i]);
        s_bc = m;
    }
    __syncthreads();
    mx = s_bc;

    float sum = 0.f;
    for (int i = threadIdx.x; i < n; i += 256) {
        float e = expf(cache[i] - mx);
        cache[i] = e;
        sum += e;
    }
    #pragma unroll
    for (int o = 16; o > 0; o >>= 1) sum += __shfl_down_sync(0xffffffffu, sum, o);
    if (lid == 0) red[wid] = sum;
    __syncthreads();
    if (threadIdx.x == 0) {
        float tot = 0.f;
        #pragma unroll
        for (int i = 0; i < 8; i++) tot += red[i];
        s_bc = 1.f / tot;
    }
    __syncthreads();
    float inv = s_bc;
    for (int i = threadIdx.x; i < n; i += 256)
        pr[ro + i] = __float2half_rn(cache[i] * inv);
    const fp16 z = __float2half(0.f);
    for (int i = n + threadIdx.x; i < blk_end; i += 256)
        pr[ro + i] = z;
}

// ---------------------------------------------------------------------------
// launch
// ---------------------------------------------------------------------------
extern "C" void kernel_launch(void* const* d_in, const int* in_sizes, int n_in,
                              void* d_out, int out_size)
{
    const float* x     = (const float*)d_in[0];
    const float* ln1_g = (const float*)d_in[1];
    const float* ln1_b = (const float*)d_in[2];
    const float* Wqkv  = (const float*)d_in[3];
    const float* bqkv  = (const float*)d_in[4];
    const float* Wproj = (const float*)d_in[5];
    const float* bproj = (const float*)d_in[6];
    const float* ln2_g = (const float*)d_in[7];
    const float* ln2_b = (const float*)d_in[8];
    const float* W1    = (const float*)d_in[9];
    const float* b1    = (const float*)d_in[10];
    const float* W2    = (const float*)d_in[11];
    const float* b2    = (const float*)d_in[12];
    float* out = (float*)d_out;

    float *p_a;
    fp16 *p_sc16, *p_p, *p_h, *p_kqv, *p_vT, *p_at, *p_h2, *p_mid;
    fp16 *Wq_hi, *Wq_lo, *Wp_hi, *Wp_lo, *W1_hi, *W1_lo, *W2_hi, *W2_lo;

    cudaGetSymbolAddress((void**)&p_a,    g_a);
    cudaGetSymbolAddress((void**)&p_sc16, g_sc16);
    cudaGetSymbolAddress((void**)&p_p,    g_p);
    cudaGetSymbolAddress((void**)&p_h,    g_h);
    cudaGetSymbolAddress((void**)&p_kqv,  g_kqv);
    cudaGetSymbolAddress((void**)&p_vT,   g_vT);
    cudaGetSymbolAddress((void**)&p_at,   g_at);
    cudaGetSymbolAddress((void**)&p_h2,   g_h2);
    cudaGetSymbolAddress((void**)&p_mid,  g_mid);
    cudaGetSymbolAddress((void**)&Wq_hi,  g_Wqkv_hi); cudaGetSymbolAddress((void**)&Wq_lo, g_Wqkv_lo);
    cudaGetSymbolAddress((void**)&Wp_hi,  g_Wprj_hi); cudaGetSymbolAddress((void**)&Wp_lo, g_Wprj_lo);
    cudaGetSymbolAddress((void**)&W1_hi,  g_W1_hi);  cudaGetSymbolAddress((void**)&W1_lo,  g_W1_lo);
    cudaGetSymbolAddress((void**)&W2_hi,  g_W2_hi);  cudaGetSymbolAddress((void**)&W2_lo,  g_W2_lo);

    const int SMEM1 = 2 * 2 * TILE_BYTES;   // 40960
    const int SMEM2 = 2 * 3 * TILE_BYTES;   // 61440
    cudaFuncSetAttribute((const void*)gemm_cs<2, 2, 0>, cudaFuncAttributeMaxDynamicSharedMemorySize, SMEM2);
    cudaFuncSetAttribute((const void*)gemm_cs<2, 0, 0>, cudaFuncAttributeMaxDynamicSharedMemorySize, SMEM2);
    cudaFuncSetAttribute((const void*)gemm_cs<2, 3, 0>, cudaFuncAttributeMaxDynamicSharedMemorySize, SMEM2);
    cudaFuncSetAttribute((const void*)gemm_cs<1, 2, 1>, cudaFuncAttributeMaxDynamicSharedMemorySize, SMEM1);
    cudaFuncSetAttribute((const void*)gemm_cs<1, 2, 2>, cudaFuncAttributeMaxDynamicSharedMemorySize, SMEM1);

    const float inv_sqrt_T = 1.0f / sqrtf((float)T_);
    dim3 tb(32, 8);

    // Weight transpose + x32 scale + split (once)
    transpose_split_f32<<<dim3(3 * D_ / 32, D_ / 32), tb>>>(Wqkv,  Wq_hi, Wq_lo, 3 * D_, D_, WSCALE);
    transpose_split_f32<<<dim3(D_ / 32,     D_ / 32), tb>>>(Wproj, Wp_hi, Wp_lo, D_,     D_, WSCALE);
    transpose_split_f32<<<dim3(4 * D_ / 32, D_ / 32), tb>>>(W1,    W1_hi, W1_lo, 4 * D_, D_, WSCALE);
    transpose_split_f32<<<dim3(D_ / 32, 4 * D_ / 32), tb>>>(W2,    W2_hi, W2_lo, D_, 4 * D_, WSCALE);

    // 1. LN1 -> fp16 h
    ln_half<<<ROWS, 256>>>(x, ln1_g, ln1_b, p_h);

    // 2. QKV GEMM (2-pass) -> plain fp16 kqv
    gemm_cs<2, 2, 0><<<dim3(3 * D_ / 128, ROWS / 128, 1), 256, SMEM2>>>(
        p_h, nullptr, Wq_hi, Wq_lo, bqkv, nullptr, p_kqv,
        D_, D_, D_, 3 * D_, 0, 0, 0, WALPHA);

    // 3. V^T, batched
    transpose_h<<<dim3(D_ / 32, T_ / 32, B_), tb>>>(
        p_kqv + 2 * D_, p_vT, 3 * D_, T_,
        (long long)T_ * 3 * D_, (long long)D_ * T_);

    // 4. scores = q @ k^T * inv_sqrt_T (1-pass, lower-tri blocks) -> fp16
    gemm_cs<1, 2, 1><<<dim3(T_ / 128, T_ / 128, B_), 256, SMEM1>>>(
        p_kqv + D_, nullptr, p_kqv, nullptr, nullptr, nullptr, p_sc16,
        D_, 3 * D_, 3 * D_, T_,
        (long long)T_ * 3 * D_, (long long)T_ * 3 * D_, (long long)T_ * T_, inv_sqrt_T);

    // 5. softmax -> fp16 probs
    softmax_h<<<dim3(T_, B_), 256>>>(p_sc16, p_p);

    // 6. attn @ v (1-pass, K clipped) -> fp16 at
    gemm_cs<1, 2, 2><<<dim3(D_ / 128, T_ / 128, B_), 256, SMEM1>>>(
        p_p, nullptr, p_vT, nullptr, nullptr, nullptr, p_at,
        T_, T_, T_, D_,
        (long long)T_ * T_, (long long)D_ * T_, (long long)T_ * D_, 1.f);

    // 7. proj (2-pass) -> fp32 a
    gemm_cs<2, 0, 0><<<dim3(D_ / 128, ROWS / 128, 1), 256, SMEM2>>>(
        p_at, nullptr, Wp_hi, Wp_lo, bproj, p_a, nullptr,
        D_, D_, D_, D_, 0, 0, 0, WALPHA);

    // 8. LN2 -> fp16 h2
    ln_half<<<ROWS, 256>>>(p_a, ln2_g, ln2_b, p_h2);

    // 9. MLP up + GELU (2-pass) -> fp16 mid
    gemm_cs<2, 3, 0><<<dim3(4 * D_ / 128, ROWS / 128, 1), 256, SMEM2>>>(
        p_h2, nullptr, W1_hi, W1_lo, b1, nullptr, p_mid,
        D_, D_, D_, 4 * D_, 0, 0, 0, WALPHA);

    // 10. MLP down (2-pass) -> fp32 out
    gemm_cs<2, 0, 0><<<dim3(D_ / 128, ROWS / 128, 1), 256, SMEM2>>>(
        p_mid, nullptr, W2_hi, W2_lo, b2, out, nullptr,
        4 * D_, 4 * D_, 4 * D_, D_, 0, 0, 0, WALPHA);
}

// round 9
// speedup vs baseline: 6.1796x; 1.1841x over previous
#include <cuda_runtime.h>
#include <cuda_fp16.h>
#include <math.h>
#include <stdint.h>

// Problem constants
#define B_ 4
#define T_ 2048
#define D_ 1024
#define ROWS (B_ * T_)        // 8192
#define EPS 1e-5f

typedef __half fp16;

// ---------------------------------------------------------------------------
// Scratch (allocation-free: __device__ globals)
// ---------------------------------------------------------------------------
__device__ float g_a  [ROWS * D_];              // fp32 proj out (LN2 input)

__device__ fp16 g_sc16 [(size_t)B_ * T_ * T_];  // fp16 scores
__device__ fp16 g_p    [(size_t)B_ * T_ * T_];  // fp16 probs
__device__ fp16 g_h    [ROWS * D_];
__device__ fp16 g_kqv  [ROWS * 3 * D_];
__device__ fp16 g_vT   [(size_t)B_ * D_ * T_];
__device__ fp16 g_at   [ROWS * D_];
__device__ fp16 g_h2   [ROWS * D_];
__device__ fp16 g_mid  [ROWS * 4 * D_];
__device__ fp16 g_Wqkv_hi[3 * D_ * D_],   g_Wqkv_lo[3 * D_ * D_];
__device__ fp16 g_Wprj_hi[D_ * D_],       g_Wprj_lo[D_ * D_];
__device__ fp16 g_W1_hi  [4 * D_ * D_],   g_W1_lo  [4 * D_ * D_];
__device__ fp16 g_W2_hi  [D_ * 4 * D_],   g_W2_lo  [D_ * 4 * D_];

#define WSCALE 32.0f
#define WALPHA (1.0f / 32.0f)

// ---------------------------------------------------------------------------
// helpers
// ---------------------------------------------------------------------------
__device__ __forceinline__ void split1(float v, fp16& h, fp16& l) {
    h = __float2half_rn(v);
    l = __float2half_rn(v - __half2float(h));
}
__device__ __forceinline__ uint32_t pack2h(fp16 a, fp16 b) {
    return (uint32_t)__half_as_ushort(a) | ((uint32_t)__half_as_ushort(b) << 16);
}
__device__ __forceinline__ void mma_fp16(float* d, const uint32_t* a, const uint32_t* b) {
    asm volatile(
        "mma.sync.aligned.m16n8k16.row.col.f32.f16.f16.f32 "
        "{%0,%1,%2,%3}, {%4,%5,%6,%7}, {%8,%9}, {%0,%1,%2,%3};"
        : "+f"(d[0]), "+f"(d[1]), "+f"(d[2]), "+f"(d[3])
        : "r"(a[0]), "r"(a[1]), "r"(a[2]), "r"(a[3]),
          "r"(b[0]), "r"(b[1]));
}
__device__ __forceinline__ uint32_t smem_u32(const void* p) {
    uint32_t a;
    asm("{ .reg .u64 t; cvta.to.shared.u64 t, %1; cvt.u32.u64 %0, t; }" : "=r"(a) : "l"(p));
    return a;
}
__device__ __forceinline__ void cp16(uint32_t dst, const void* src) {
    asm volatile("cp.async.ca.shared.global [%0], [%1], 16;" :: "r"(dst), "l"(src));
}
#define CP_COMMIT() asm volatile("cp.async.commit_group;" ::: "memory")
#define CP_WAIT(n)  asm volatile("cp.async.wait_group %0;" :: "n"(n) : "memory")

#define LDSM_X4(d0, d1, d2, d3, addr) \
    asm volatile("ldmatrix.sync.aligned.m8n8.x4.shared.b16 {%0,%1,%2,%3}, [%4];" \
        : "=r"(d0), "=r"(d1), "=r"(d2), "=r"(d3) : "r"(addr))

// SMEM tile geometry: 128 rows x 32 fp16, row stride 40 elems (80B)
#define TILE_BYTES 10240

// ---------------------------------------------------------------------------
// GEMM: C[M,N] = alpha*(A @ B^T) (+bias)
// PASSES=1: A fp16, B fp16.  PASSES=2: A fp16, B hi+lo.
// Tile order in stage: A_hi, B_hi, [B_lo]
// EPI: 0=fp32 out, 2=fp16 out, 3=gelu+fp16 out
// CMODE: 0=dense, 1=causal block skip, 2=causal K clip
// ---------------------------------------------------------------------------
template <int PASSES, int EPI, int CMODE>
__global__ void __launch_bounds__(256) gemm_cs(
    const fp16* __restrict__ Ahi,
    const fp16* __restrict__ Bhi, const fp16* __restrict__ Blo,
    const float* __restrict__ bias,
    float* __restrict__ Cf, fp16* __restrict__ Chi,
    int K, int lda, int ldb, int ldc,
    long long sA, long long sB, long long sC, float alpha)
{
    constexpr int NTILES = (PASSES == 2 ? 3 : 2);
    constexpr int STAGE_BYTES = NTILES * TILE_BYTES;

    const int bx = blockIdx.x, by = blockIdx.y, bz = blockIdx.z;
    if (CMODE == 1 && bx > by) return;

    extern __shared__ fp16 smem[];
    const uint32_t sb = smem_u32(smem);

    Ahi += sA * bz;
    Bhi += sB * bz;
    if (PASSES >= 2) Blo += sB * bz;

    const int m0 = by * 128, n0 = bx * 128;
    int Kend = K;
    if (CMODE == 2) { int ke = (by + 1) * 128; if (ke < K) Kend = ke; }
    const int NC = Kend >> 5;

    const int tid = threadIdx.x;
    const int wid = tid >> 5, lane = tid & 31;
    const int wm = wid & 1, wn = wid >> 1;
    const int g = lane >> 2, tig = lane & 3;

    const uint32_t a_loff = (uint32_t)(((lane & 7) + ((lane >> 3) & 1) * 8) * 80 + ((lane >> 4) & 1) * 16);
    const uint32_t b_loff = (uint32_t)(((lane & 7) + ((lane >> 4) & 1) * 8) * 80 + ((lane >> 3) & 1) * 16);

    const int lrow = tid >> 1;
    const int lc   = (tid & 1) * 2;

    const fp16* pA_hi = Ahi + (size_t)(m0 + lrow) * lda + lc * 8;
    const fp16* pB_hi = Bhi + (size_t)(n0 + lrow) * ldb + lc * 8;
    const fp16* pB_lo = (PASSES >= 2) ? (Blo + (size_t)(n0 + lrow) * ldb + lc * 8) : nullptr;
    const uint32_t dbase = sb + lrow * 80 + lc * 16;

    auto issue = [&](int kc, int buf) {
        const uint32_t d0 = dbase + buf * STAGE_BYTES;
        const int ko = kc * 32;
        cp16(d0,                     pA_hi + ko);
        cp16(d0 + 16,                pA_hi + ko + 8);
        cp16(d0 + TILE_BYTES,        pB_hi + ko);
        cp16(d0 + TILE_BYTES + 16,   pB_hi + ko + 8);
        if (PASSES >= 2) {
            cp16(d0 + 2*TILE_BYTES,      pB_lo + ko);
            cp16(d0 + 2*TILE_BYTES + 16, pB_lo + ko + 8);
        }
    };

    float acc[4][4][4];
    #pragma unroll
    for (int i = 0; i < 4; i++)
        #pragma unroll
        for (int j = 0; j < 4; j++)
            #pragma unroll
            for (int r = 0; r < 4; r++) acc[i][j][r] = 0.f;

    issue(0, 0);
    CP_COMMIT();

    int buf = 0;
    for (int kc = 0; kc < NC; kc++) {
        if (kc + 1 < NC) {
            issue(kc + 1, buf ^ 1);
            CP_COMMIT();
            CP_WAIT(1);
        } else {
            CP_WAIT(0);
        }
        __syncthreads();

        const uint32_t stage = sb + buf * STAGE_BYTES;
        const uint32_t aH = stage + (uint32_t)(wm * 64 * 80) + a_loff;
        const uint32_t bH = stage + TILE_BYTES + (uint32_t)(wn * 32 * 80) + b_loff;
        const uint32_t bL = bH + TILE_BYTES;

        #pragma unroll
        for (int kk2 = 0; kk2 < 64; kk2 += 32) {
            uint32_t af[4][4], bh[4][2], bl[4][2];
            #pragma unroll
            for (int mt = 0; mt < 4; mt++)
                LDSM_X4(af[mt][0], af[mt][1], af[mt][2], af[mt][3], aH + mt * 1280 + kk2);
            #pragma unroll
            for (int p = 0; p < 2; p++)
                LDSM_X4(bh[2*p][0], bh[2*p][1], bh[2*p+1][0], bh[2*p+1][1], bH + p * 1280 + kk2);
            // pass 1: A x B_hi
            #pragma unroll
            for (int mt = 0; mt < 4; mt++)
                #pragma unroll
                for (int nt = 0; nt < 4; nt++)
                    mma_fp16(acc[mt][nt], af[mt], bh[nt]);
            // pass 2: A x B_lo
            if (PASSES >= 2) {
                #pragma unroll
                for (int p = 0; p < 2; p++)
                    LDSM_X4(bl[2*p][0], bl[2*p][1], bl[2*p+1][0], bl[2*p+1][1], bL + p * 1280 + kk2);
                #pragma unroll
                for (int mt = 0; mt < 4; mt++)
                    #pragma unroll
                    for (int nt = 0; nt < 4; nt++)
                        mma_fp16(acc[mt][nt], af[mt], bl[nt]);
            }
        }
        __syncthreads();
        buf ^= 1;
    }

    // epilogue
    if (EPI == 0) Cf += sC * bz;
    else Chi += sC * bz;

    #pragma unroll
    for (int mt = 0; mt < 4; mt++) {
        #pragma unroll
        for (int nt = 0; nt < 4; nt++) {
            int m = m0 + wm * 64 + mt * 16 + g;
            int n = n0 + wn * 32 + nt * 8 + tig * 2;
            float2 bv = make_float2(0.f, 0.f);
            if (bias) bv = __ldg((const float2*)(bias + n));
            #pragma unroll
            for (int half_ = 0; half_ < 2; half_++) {
                float vx = acc[mt][nt][half_ * 2 + 0] * alpha + bv.x;
                float vy = acc[mt][nt][half_ * 2 + 1] * alpha + bv.y;
                if (EPI == 3) {
                    const float c0 = 0.7978845608028654f, c1 = 0.044715f;
                    vx = 0.5f * vx * (1.f + tanhf(c0 * (vx + c1 * vx * vx * vx)));
                    vy = 0.5f * vy * (1.f + tanhf(c0 * (vy + c1 * vy * vy * vy)));
                }
                size_t off = (size_t)(m + half_ * 8) * ldc + n;
                if (EPI == 0) {
                    *(float2*)(Cf + off) = make_float2(vx, vy);
                } else {
                    *(uint32_t*)(Chi + off) = pack2h(__float2half_rn(vx), __float2half_rn(vy));
                }
            }
        }
    }
}

// ---------------------------------------------------------------------------
// Weight transpose + scale + split
// ---------------------------------------------------------------------------
__global__ void __launch_bounds__(256) transpose_split_f32(
    const float* __restrict__ in, fp16* __restrict__ ohi, fp16* __restrict__ olo,
    int ldi, int ldo, float scale)
{
    __shared__ float t[32][33];
    const int c0 = blockIdx.x * 32, r0 = blockIdx.y * 32;
    const int x = threadIdx.x, y = threadIdx.y;
    #pragma unroll
    for (int i = 0; i < 4; i++)
        t[y + i * 8][x] = in[(size_t)(r0 + y + i * 8) * ldi + c0 + x];
    __syncthreads();
    #pragma unroll
    for (int i = 0; i < 4; i++) {
        float v = t[x][y + i * 8] * scale;
        fp16 h, l;
        split1(v, h, l);
        size_t off = (size_t)(c0 + y + i * 8) * ldo + r0 + x;
        ohi[off] = h;
        olo[off] = l;
    }
}

// ---------------------------------------------------------------------------
// fp16 transpose (V -> V^T), batched
// ---------------------------------------------------------------------------
__global__ void __launch_bounds__(256) transpose_h(
    const fp16* __restrict__ in, fp16* __restrict__ out,
    int ldi, int ldo, long long sI, long long sO)
{
    __shared__ fp16 t[32][33];
    in  += sI * blockIdx.z;
    out += sO * blockIdx.z;
    const int c0 = blockIdx.x * 32, r0 = blockIdx.y * 32;
    const int x = threadIdx.x, y = threadIdx.y;
    #pragma unroll
    for (int i = 0; i < 4; i++)
        t[y + i * 8][x] = in[(size_t)(r0 + y + i * 8) * ldi + c0 + x];
    __syncthreads();
    #pragma unroll
    for (int i = 0; i < 4; i++)
        out[(size_t)(c0 + y + i * 8) * ldo + r0 + x] = t[x][y + i * 8];
}

// ---------------------------------------------------------------------------
// LayerNorm -> fp16 out (row cached in SMEM)
// ---------------------------------------------------------------------------
__global__ void __launch_bounds__(256) ln_half(
    const float* __restrict__ x, const float* __restrict__ gamma,
    const float* __restrict__ beta, fp16* __restrict__ o)
{
    __shared__ float xc[D_];
    const int row = blockIdx.x;
    const float* xr = x + (size_t)row * D_;

    float s = 0.f, ss = 0.f;
    for (int i = threadIdx.x; i < D_; i += 256) {
        float v = xr[i];
        xc[i] = v;
        s += v; ss += v * v;
    }
    __shared__ float rs[8], rss[8];
    #pragma unroll
    for (int o2 = 16; o2 > 0; o2 >>= 1) {
        s  += __shfl_down_sync(0xffffffffu, s,  o2);
        ss += __shfl_down_sync(0xffffffffu, ss, o2);
    }
    int wid = threadIdx.x >> 5, lid = threadIdx.x & 31;
    if (lid == 0) { rs[wid] = s; rss[wid] = ss; }
    __syncthreads();
    __shared__ float s_mu, s_rstd;
    if (threadIdx.x == 0) {
        float ts = 0.f, tss = 0.f;
        #pragma unroll
        for (int i = 0; i < 8; i++) { ts += rs[i]; tss += rss[i]; }
        float mu = ts / D_;
        float var = tss / D_ - mu * mu;
        s_mu = mu;
        s_rstd = rsqrtf(var + EPS);
    }
    __syncthreads();
    float mu = s_mu, rstd = s_rstd;
    for (int i = threadIdx.x; i < D_; i += 256) {
        float v = (xc[i] - mu) * rstd * gamma[i] + beta[i];
        o[(size_t)row * D_ + i] = __float2half_rn(v);
    }
}

// ---------------------------------------------------------------------------
// Causal softmax: fp16 scores -> fp16 probs (zero-fill only to block edge)
// ---------------------------------------------------------------------------
__global__ void __launch_bounds__(256) softmax_h(
    const fp16* __restrict__ sc, fp16* __restrict__ pr)
{
    __shared__ float cache[T_];
    const int t = blockIdx.x, b = blockIdx.y;
    const size_t ro = ((size_t)b * T_ + t) * T_;
    const fp16* row = sc + ro;
    const int n = t + 1;
    const int blk_end = ((t >> 7) + 1) << 7;

    __shared__ float red[8];
    __shared__ float s_bc;

    float mx = -INFINITY;
    for (int i = threadIdx.x; i < n; i += 256) {
        float v = __half2float(row[i]);
        cache[i] = v;
        mx = fmaxf(mx, v);
    }
    #pragma unroll
    for (int o = 16; o > 0; o >>= 1) mx = fmaxf(mx, __shfl_down_sync(0xffffffffu, mx, o));
    int wid = threadIdx.x >> 5, lid = threadIdx.x & 31;
    if (lid == 0) red[wid] = mx;
    __syncthreads();
    if (threadIdx.x == 0) {
        float m = red[0];
        #pragma unroll
        for (int i = 1; i < 8; i++) m = fmaxf(m, red[i]);
        s_bc = m;
    }
    __syncthreads();
    mx = s_bc;

    float sum = 0.f;
    for (int i = threadIdx.x; i < n; i += 256) {
        float e = expf(cache[i] - mx);
        cache[i] = e;
        sum += e;
    }
    #pragma unroll
    for (int o = 16; o > 0; o >>= 1) sum += __shfl_down_sync(0xffffffffu, sum, o);
    if (lid == 0) red[wid] = sum;
    __syncthreads();
    if (threadIdx.x == 0) {
        float tot = 0.f;
        #pragma unroll
        for (int i = 0; i < 8; i++) tot += red[i];
        s_bc = 1.f / tot;
    }
    __syncthreads();
    float inv = s_bc;
    for (int i = threadIdx.x; i < n; i += 256)
        pr[ro + i] = __float2half_rn(cache[i] * inv);
    const fp16 z = __float2half(0.f);
    for (int i = n + threadIdx.x; i < blk_end; i += 256)
        pr[ro + i] = z;
}

// ---------------------------------------------------------------------------
// launch
// ---------------------------------------------------------------------------
extern "C" void kernel_launch(void* const* d_in, const int* in_sizes, int n_in,
                              void* d_out, int out_size)
{
    const float* x     = (const float*)d_in[0];
    const float* ln1_g = (const float*)d_in[1];
    const float* ln1_b = (const float*)d_in[2];
    const float* Wqkv  = (const float*)d_in[3];
    const float* bqkv  = (const float*)d_in[4];
    const float* Wproj = (const float*)d_in[5];
    const float* bproj = (const float*)d_in[6];
    const float* ln2_g = (const float*)d_in[7];
    const float* ln2_b = (const float*)d_in[8];
    const float* W1    = (const float*)d_in[9];
    const float* b1    = (const float*)d_in[10];
    const float* W2    = (const float*)d_in[11];
    const float* b2    = (const float*)d_in[12];
    float* out = (float*)d_out;

    float *p_a;
    fp16 *p_sc16, *p_p, *p_h, *p_kqv, *p_vT, *p_at, *p_h2, *p_mid;
    fp16 *Wq_hi, *Wq_lo, *Wp_hi, *Wp_lo, *W1_hi, *W1_lo, *W2_hi, *W2_lo;

    cudaGetSymbolAddress((void**)&p_a,    g_a);
    cudaGetSymbolAddress((void**)&p_sc16, g_sc16);
    cudaGetSymbolAddress((void**)&p_p,    g_p);
    cudaGetSymbolAddress((void**)&p_h,    g_h);
    cudaGetSymbolAddress((void**)&p_kqv,  g_kqv);
    cudaGetSymbolAddress((void**)&p_vT,   g_vT);
    cudaGetSymbolAddress((void**)&p_at,   g_at);
    cudaGetSymbolAddress((void**)&p_h2,   g_h2);
    cudaGetSymbolAddress((void**)&p_mid,  g_mid);
    cudaGetSymbolAddress((void**)&Wq_hi,  g_Wqkv_hi); cudaGetSymbolAddress((void**)&Wq_lo, g_Wqkv_lo);
    cudaGetSymbolAddress((void**)&Wp_hi,  g_Wprj_hi); cudaGetSymbolAddress((void**)&Wp_lo, g_Wprj_lo);
    cudaGetSymbolAddress((void**)&W1_hi,  g_W1_hi);  cudaGetSymbolAddress((void**)&W1_lo,  g_W1_lo);
    cudaGetSymbolAddress((void**)&W2_hi,  g_W2_hi);  cudaGetSymbolAddress((void**)&W2_lo,  g_W2_lo);

    const int SMEM1 = 2 * 2 * TILE_BYTES;   // 40960
    const int SMEM2 = 2 * 3 * TILE_BYTES;   // 61440
    cudaFuncSetAttribute((const void*)gemm_cs<2, 2, 0>, cudaFuncAttributeMaxDynamicSharedMemorySize, SMEM2);
    cudaFuncSetAttribute((const void*)gemm_cs<2, 0, 0>, cudaFuncAttributeMaxDynamicSharedMemorySize, SMEM2);
    cudaFuncSetAttribute((const void*)gemm_cs<1, 2, 1>, cudaFuncAttributeMaxDynamicSharedMemorySize, SMEM1);
    cudaFuncSetAttribute((const void*)gemm_cs<1, 2, 2>, cudaFuncAttributeMaxDynamicSharedMemorySize, SMEM1);
    cudaFuncSetAttribute((const void*)gemm_cs<1, 3, 0>, cudaFuncAttributeMaxDynamicSharedMemorySize, SMEM1);
    cudaFuncSetAttribute((const void*)gemm_cs<1, 0, 0>, cudaFuncAttributeMaxDynamicSharedMemorySize, SMEM1);

    const float inv_sqrt_T = 1.0f / sqrtf((float)T_);
    dim3 tb(32, 8);

    // Weight transpose + x32 scale + split (once)
    transpose_split_f32<<<dim3(3 * D_ / 32, D_ / 32), tb>>>(Wqkv,  Wq_hi, Wq_lo, 3 * D_, D_, WSCALE);
    transpose_split_f32<<<dim3(D_ / 32,     D_ / 32), tb>>>(Wproj, Wp_hi, Wp_lo, D_,     D_, WSCALE);
    transpose_split_f32<<<dim3(4 * D_ / 32, D_ / 32), tb>>>(W1,    W1_hi, W1_lo, 4 * D_, D_, WSCALE);
    transpose_split_f32<<<dim3(D_ / 32, 4 * D_ / 32), tb>>>(W2,    W2_hi, W2_lo, D_, 4 * D_, WSCALE);

    // 1. LN1 -> fp16 h
    ln_half<<<ROWS, 256>>>(x, ln1_g, ln1_b, p_h);

    // 2. QKV GEMM (2-pass) -> plain fp16 kqv
    gemm_cs<2, 2, 0><<<dim3(3 * D_ / 128, ROWS / 128, 1), 256, SMEM2>>>(
        p_h, Wq_hi, Wq_lo, bqkv, nullptr, p_kqv,
        D_, D_, D_, 3 * D_, 0, 0, 0, WALPHA);

    // 3. V^T, batched
    transpose_h<<<dim3(D_ / 32, T_ / 32, B_), tb>>>(
        p_kqv + 2 * D_, p_vT, 3 * D_, T_,
        (long long)T_ * 3 * D_, (long long)D_ * T_);

    // 4. scores = q @ k^T * inv_sqrt_T (1-pass, lower-tri blocks) -> fp16
    gemm_cs<1, 2, 1><<<dim3(T_ / 128, T_ / 128, B_), 256, SMEM1>>>(
        p_kqv + D_, p_kqv, nullptr, nullptr, nullptr, p_sc16,
        D_, 3 * D_, 3 * D_, T_,
        (long long)T_ * 3 * D_, (long long)T_ * 3 * D_, (long long)T_ * T_, inv_sqrt_T);

    // 5. softmax -> fp16 probs
    softmax_h<<<dim3(T_, B_), 256>>>(p_sc16, p_p);

    // 6. attn @ v (1-pass, K clipped) -> fp16 at
    gemm_cs<1, 2, 2><<<dim3(D_ / 128, T_ / 128, B_), 256, SMEM1>>>(
        p_p, p_vT, nullptr, nullptr, nullptr, p_at,
        T_, T_, T_, D_,
        (long long)T_ * T_, (long long)D_ * T_, (long long)T_ * D_, 1.f);

    // 7. proj (2-pass) -> fp32 a
    gemm_cs<2, 0, 0><<<dim3(D_ / 128, ROWS / 128, 1), 256, SMEM2>>>(
        p_at, Wp_hi, Wp_lo, bproj, p_a, nullptr,
        D_, D_, D_, D_, 0, 0, 0, WALPHA);

    // 8. LN2 -> fp16 h2
    ln_half<<<ROWS, 256>>>(p_a, ln2_g, ln2_b, p_h2);

    // 9. MLP up + GELU (1-pass) -> fp16 mid
    gemm_cs<1, 3, 0><<<dim3(4 * D_ / 128, ROWS / 128, 1), 256, SMEM1>>>(
        p_h2, W1_hi, nullptr, b1, nullptr, p_mid,
        D_, D_, D_, 4 * D_, 0, 0, 0, WALPHA);

    // 10. MLP down (1-pass) -> fp32 out
    gemm_cs<1, 0, 0><<<dim3(D_ / 128, ROWS / 128, 1), 256, SMEM1>>>(
        p_mid, W2_hi, nullptr, b2, out, nullptr,
        4 * D_, 4 * D_, 4 * D_, D_, 0, 0, 0, WALPHA);
}

// round 10
// speedup vs baseline: 6.8670x; 1.1112x over previous
#include <cuda_runtime.h>
#include <cuda_fp16.h>
#include <math.h>
#include <stdint.h>

// Problem constants
#define B_ 4
#define T_ 2048
#define D_ 1024
#define ROWS (B_ * T_)        // 8192
#define EPS 1e-5f

typedef __half fp16;

// ---------------------------------------------------------------------------
// Scratch (allocation-free: __device__ globals)
// ---------------------------------------------------------------------------
__device__ float g_a  [ROWS * D_];              // fp32 proj out (LN2 input)

__device__ fp16 g_sc16 [(size_t)B_ * T_ * T_];  // fp16 scores
__device__ fp16 g_p    [(size_t)B_ * T_ * T_];  // fp16 probs
__device__ fp16 g_h    [ROWS * D_];
__device__ fp16 g_kqv  [ROWS * 3 * D_];
__device__ fp16 g_vT   [(size_t)B_ * D_ * T_];
__device__ fp16 g_at   [ROWS * D_];
__device__ fp16 g_h2   [ROWS * D_];
__device__ fp16 g_mid  [ROWS * 4 * D_];
__device__ fp16 g_WqkvT[3 * D_ * D_];
__device__ fp16 g_WprjT[D_ * D_];
__device__ fp16 g_W1T  [4 * D_ * D_];
__device__ fp16 g_W2T  [D_ * 4 * D_];

// ---------------------------------------------------------------------------
// helpers
// ---------------------------------------------------------------------------
__device__ __forceinline__ uint32_t pack2h(fp16 a, fp16 b) {
    return (uint32_t)__half_as_ushort(a) | ((uint32_t)__half_as_ushort(b) << 16);
}
__device__ __forceinline__ void mma_fp16(float* d, const uint32_t* a, const uint32_t* b) {
    asm volatile(
        "mma.sync.aligned.m16n8k16.row.col.f32.f16.f16.f32 "
        "{%0,%1,%2,%3}, {%4,%5,%6,%7}, {%8,%9}, {%0,%1,%2,%3};"
        : "+f"(d[0]), "+f"(d[1]), "+f"(d[2]), "+f"(d[3])
        : "r"(a[0]), "r"(a[1]), "r"(a[2]), "r"(a[3]),
          "r"(b[0]), "r"(b[1]));
}
__device__ __forceinline__ uint32_t smem_u32(const void* p) {
    uint32_t a;
    asm("{ .reg .u64 t; cvta.to.shared.u64 t, %1; cvt.u32.u64 %0, t; }" : "=r"(a) : "l"(p));
    return a;
}
__device__ __forceinline__ void cp16(uint32_t dst, const void* src) {
    asm volatile("cp.async.ca.shared.global [%0], [%1], 16;" :: "r"(dst), "l"(src));
}
#define CP_COMMIT() asm volatile("cp.async.commit_group;" ::: "memory")
#define CP_WAIT(n)  asm volatile("cp.async.wait_group %0;" :: "n"(n) : "memory")

#define LDSM_X4(d0, d1, d2, d3, addr) \
    asm volatile("ldmatrix.sync.aligned.m8n8.x4.shared.b16 {%0,%1,%2,%3}, [%4];" \
        : "=r"(d0), "=r"(d1), "=r"(d2), "=r"(d3) : "r"(addr))

// SMEM tile geometry: 128 rows x 32 fp16, row stride 40 elems (80B)
#define TILE_BYTES 10240
#define STAGE_BYTES (2 * TILE_BYTES)    // A + B tiles
#define SMEM_BYTES (2 * STAGE_BYTES)    // double buffered = 40960

// ---------------------------------------------------------------------------
// 1-pass fp16 NT GEMM: C[M,N] = alpha*(A @ B^T) (+bias)
// EPI: 0=fp32 out, 2=fp16 out, 3=gelu+fp16 out
// CMODE: 0=dense, 1=causal block skip, 2=causal K clip
// ---------------------------------------------------------------------------
template <int EPI, int CMODE>
__global__ void __launch_bounds__(256) gemm_h(
    const fp16* __restrict__ A, const fp16* __restrict__ Bm,
    const float* __restrict__ bias,
    float* __restrict__ Cf, fp16* __restrict__ Ch,
    int K, int lda, int ldb, int ldc,
    long long sA, long long sB, long long sC, float alpha)
{
    const int bx = blockIdx.x, by = blockIdx.y, bz = blockIdx.z;
    if (CMODE == 1 && bx > by) return;

    extern __shared__ fp16 smem[];
    const uint32_t sb = smem_u32(smem);

    A  += sA * bz;
    Bm += sB * bz;

    const int m0 = by * 128, n0 = bx * 128;
    int Kend = K;
    if (CMODE == 2) { int ke = (by + 1) * 128; if (ke < K) Kend = ke; }
    const int NC = Kend >> 5;

    const int tid = threadIdx.x;
    const int wid = tid >> 5, lane = tid & 31;
    const int wm = wid & 1, wn = wid >> 1;
    const int g = lane >> 2, tig = lane & 3;

    const uint32_t a_loff = (uint32_t)(((lane & 7) + ((lane >> 3) & 1) * 8) * 80 + ((lane >> 4) & 1) * 16);
    const uint32_t b_loff = (uint32_t)(((lane & 7) + ((lane >> 4) & 1) * 8) * 80 + ((lane >> 3) & 1) * 16);

    const int lrow = tid >> 1;
    const int lc   = (tid & 1) * 2;

    const fp16* pA = A  + (size_t)(m0 + lrow) * lda + lc * 8;
    const fp16* pB = Bm + (size_t)(n0 + lrow) * ldb + lc * 8;
    const uint32_t dbase = sb + lrow * 80 + lc * 16;

    auto issue = [&](int kc, int buf) {
        const uint32_t d0 = dbase + buf * STAGE_BYTES;
        const int ko = kc * 32;
        cp16(d0,                   pA + ko);
        cp16(d0 + 16,              pA + ko + 8);
        cp16(d0 + TILE_BYTES,      pB + ko);
        cp16(d0 + TILE_BYTES + 16, pB + ko + 8);
    };

    float acc[4][4][4];
    #pragma unroll
    for (int i = 0; i < 4; i++)
        #pragma unroll
        for (int j = 0; j < 4; j++)
            #pragma unroll
            for (int r = 0; r < 4; r++) acc[i][j][r] = 0.f;

    issue(0, 0);
    CP_COMMIT();

    int buf = 0;
    for (int kc = 0; kc < NC; kc++) {
        if (kc + 1 < NC) {
            issue(kc + 1, buf ^ 1);
            CP_COMMIT();
            CP_WAIT(1);
        } else {
            CP_WAIT(0);
        }
        __syncthreads();

        const uint32_t stage = sb + buf * STAGE_BYTES;
        const uint32_t aT = stage + (uint32_t)(wm * 64 * 80) + a_loff;
        const uint32_t bT = stage + TILE_BYTES + (uint32_t)(wn * 32 * 80) + b_loff;

        #pragma unroll
        for (int kk2 = 0; kk2 < 64; kk2 += 32) {
            uint32_t af[4][4], bf[4][2];
            #pragma unroll
            for (int mt = 0; mt < 4; mt++)
                LDSM_X4(af[mt][0], af[mt][1], af[mt][2], af[mt][3], aT + mt * 1280 + kk2);
            #pragma unroll
            for (int p = 0; p < 2; p++)
                LDSM_X4(bf[2*p][0], bf[2*p][1], bf[2*p+1][0], bf[2*p+1][1], bT + p * 1280 + kk2);
            #pragma unroll
            for (int mt = 0; mt < 4; mt++)
                #pragma unroll
                for (int nt = 0; nt < 4; nt++)
                    mma_fp16(acc[mt][nt], af[mt], bf[nt]);
        }
        __syncthreads();
        buf ^= 1;
    }

    // epilogue
    if (EPI == 0) Cf += sC * bz;
    else Ch += sC * bz;

    #pragma unroll
    for (int mt = 0; mt < 4; mt++) {
        #pragma unroll
        for (int nt = 0; nt < 4; nt++) {
            int m = m0 + wm * 64 + mt * 16 + g;
            int n = n0 + wn * 32 + nt * 8 + tig * 2;
            float2 bv = make_float2(0.f, 0.f);
            if (bias) bv = __ldg((const float2*)(bias + n));
            #pragma unroll
            for (int half_ = 0; half_ < 2; half_++) {
                float vx = acc[mt][nt][half_ * 2 + 0] * alpha + bv.x;
                float vy = acc[mt][nt][half_ * 2 + 1] * alpha + bv.y;
                if (EPI == 3) {
                    const float c0 = 0.7978845608028654f, c1 = 0.044715f;
                    vx = 0.5f * vx * (1.f + tanhf(c0 * (vx + c1 * vx * vx * vx)));
                    vy = 0.5f * vy * (1.f + tanhf(c0 * (vy + c1 * vy * vy * vy)));
                }
                size_t off = (size_t)(m + half_ * 8) * ldc + n;
                if (EPI == 0) {
                    *(float2*)(Cf + off) = make_float2(vx, vy);
                } else {
                    *(uint32_t*)(Ch + off) = pack2h(__float2half_rn(vx), __float2half_rn(vy));
                }
            }
        }
    }
}

// ---------------------------------------------------------------------------
// Weight transpose -> fp16: out[c][r] = fp16(in[r][c])
// ---------------------------------------------------------------------------
__global__ void __launch_bounds__(256) transpose_h_f32(
    const float* __restrict__ in, fp16* __restrict__ out, int ldi, int ldo)
{
    __shared__ float t[32][33];
    const int c0 = blockIdx.x * 32, r0 = blockIdx.y * 32;
    const int x = threadIdx.x, y = threadIdx.y;
    #pragma unroll
    for (int i = 0; i < 4; i++)
        t[y + i * 8][x] = in[(size_t)(r0 + y + i * 8) * ldi + c0 + x];
    __syncthreads();
    #pragma unroll
    for (int i = 0; i < 4; i++)
        out[(size_t)(c0 + y + i * 8) * ldo + r0 + x] = __float2half_rn(t[x][y + i * 8]);
}

// ---------------------------------------------------------------------------
// fp16 transpose (V -> V^T), batched
// ---------------------------------------------------------------------------
__global__ void __launch_bounds__(256) transpose_h(
    const fp16* __restrict__ in, fp16* __restrict__ out,
    int ldi, int ldo, long long sI, long long sO)
{
    __shared__ fp16 t[32][33];
    in  += sI * blockIdx.z;
    out += sO * blockIdx.z;
    const int c0 = blockIdx.x * 32, r0 = blockIdx.y * 32;
    const int x = threadIdx.x, y = threadIdx.y;
    #pragma unroll
    for (int i = 0; i < 4; i++)
        t[y + i * 8][x] = in[(size_t)(r0 + y + i * 8) * ldi + c0 + x];
    __syncthreads();
    #pragma unroll
    for (int i = 0; i < 4; i++)
        out[(size_t)(c0 + y + i * 8) * ldo + r0 + x] = t[x][y + i * 8];
}

// ---------------------------------------------------------------------------
// LayerNorm -> fp16 out (row cached in SMEM)
// ---------------------------------------------------------------------------
__global__ void __launch_bounds__(256) ln_half(
    const float* __restrict__ x, const float* __restrict__ gamma,
    const float* __restrict__ beta, fp16* __restrict__ o)
{
    __shared__ float xc[D_];
    const int row = blockIdx.x;
    const float* xr = x + (size_t)row * D_;

    float s = 0.f, ss = 0.f;
    for (int i = threadIdx.x; i < D_; i += 256) {
        float v = xr[i];
        xc[i] = v;
        s += v; ss += v * v;
    }
    __shared__ float rs[8], rss[8];
    #pragma unroll
    for (int o2 = 16; o2 > 0; o2 >>= 1) {
        s  += __shfl_down_sync(0xffffffffu, s,  o2);
        ss += __shfl_down_sync(0xffffffffu, ss, o2);
    }
    int wid = threadIdx.x >> 5, lid = threadIdx.x & 31;
    if (lid == 0) { rs[wid] = s; rss[wid] = ss; }
    __syncthreads();
    __shared__ float s_mu, s_rstd;
    if (threadIdx.x == 0) {
        float ts = 0.f, tss = 0.f;
        #pragma unroll
        for (int i = 0; i < 8; i++) { ts += rs[i]; tss += rss[i]; }
        float mu = ts / D_;
        float var = tss / D_ - mu * mu;
        s_mu = mu;
        s_rstd = rsqrtf(var + EPS);
    }
    __syncthreads();
    float mu = s_mu, rstd = s_rstd;
    for (int i = threadIdx.x; i < D_; i += 256) {
        float v = (xc[i] - mu) * rstd * gamma[i] + beta[i];
        o[(size_t)row * D_ + i] = __float2half_rn(v);
    }
}

// ---------------------------------------------------------------------------
// Causal softmax: fp16 scores -> fp16 probs (zero-fill only to block edge)
// ---------------------------------------------------------------------------
__global__ void __launch_bounds__(256) softmax_h(
    const fp16* __restrict__ sc, fp16* __restrict__ pr)
{
    __shared__ float cache[T_];
    const int t = blockIdx.x, b = blockIdx.y;
    const size_t ro = ((size_t)b * T_ + t) * T_;
    const fp16* row = sc + ro;
    const int n = t + 1;
    const int blk_end = ((t >> 7) + 1) << 7;

    __shared__ float red[8];
    __shared__ float s_bc;

    float mx = -INFINITY;
    for (int i = threadIdx.x; i < n; i += 256) {
        float v = __half2float(row[i]);
        cache[i] = v;
        mx = fmaxf(mx, v);
    }
    #pragma unroll
    for (int o = 16; o > 0; o >>= 1) mx = fmaxf(mx, __shfl_down_sync(0xffffffffu, mx, o));
    int wid = threadIdx.x >> 5, lid = threadIdx.x & 31;
    if (lid == 0) red[wid] = mx;
    __syncthreads();
    if (threadIdx.x == 0) {
        float m = red[0];
        #pragma unroll
        for (int i = 1; i < 8; i++) m = fmaxf(m, red[i]);
        s_bc = m;
    }
    __syncthreads();
    mx = s_bc;

    float sum = 0.f;
    for (int i = threadIdx.x; i < n; i += 256) {
        float e = expf(cache[i] - mx);
        cache[i] = e;
        sum += e;
    }
    #pragma unroll
    for (int o = 16; o > 0; o >>= 1) sum += __shfl_down_sync(0xffffffffu, sum, o);
    if (lid == 0) red[wid] = sum;
    __syncthreads();
    if (threadIdx.x == 0) {
        float tot = 0.f;
        #pragma unroll
        for (int i = 0; i < 8; i++) tot += red[i];
        s_bc = 1.f / tot;
    }
    __syncthreads();
    float inv = s_bc;
    for (int i = threadIdx.x; i < n; i += 256)
        pr[ro + i] = __float2half_rn(cache[i] * inv);
    const fp16 z = __float2half(0.f);
    for (int i = n + threadIdx.x; i < blk_end; i += 256)
        pr[ro + i] = z;
}

// ---------------------------------------------------------------------------
// launch
// ---------------------------------------------------------------------------
extern "C" void kernel_launch(void* const* d_in, const int* in_sizes, int n_in,
                              void* d_out, int out_size)
{
    const float* x     = (const float*)d_in[0];
    const float* ln1_g = (const float*)d_in[1];
    const float* ln1_b = (const float*)d_in[2];
    const float* Wqkv  = (const float*)d_in[3];
    const float* bqkv  = (const float*)d_in[4];
    const float* Wproj = (const float*)d_in[5];
    const float* bproj = (const float*)d_in[6];
    const float* ln2_g = (const float*)d_in[7];
    const float* ln2_b = (const float*)d_in[8];
    const float* W1    = (const float*)d_in[9];
    const float* b1    = (const float*)d_in[10];
    const float* W2    = (const float*)d_in[11];
    const float* b2    = (const float*)d_in[12];
    float* out = (float*)d_out;

    float *p_a;
    fp16 *p_sc16, *p_p, *p_h, *p_kqv, *p_vT, *p_at, *p_h2, *p_mid;
    fp16 *WqT, *WpT, *W1T, *W2T;

    cudaGetSymbolAddress((void**)&p_a,    g_a);
    cudaGetSymbolAddress((void**)&p_sc16, g_sc16);
    cudaGetSymbolAddress((void**)&p_p,    g_p);
    cudaGetSymbolAddress((void**)&p_h,    g_h);
    cudaGetSymbolAddress((void**)&p_kqv,  g_kqv);
    cudaGetSymbolAddress((void**)&p_vT,   g_vT);
    cudaGetSymbolAddress((void**)&p_at,   g_at);
    cudaGetSymbolAddress((void**)&p_h2,   g_h2);
    cudaGetSymbolAddress((void**)&p_mid,  g_mid);
    cudaGetSymbolAddress((void**)&WqT,    g_WqkvT);
    cudaGetSymbolAddress((void**)&WpT,    g_WprjT);
    cudaGetSymbolAddress((void**)&W1T,    g_W1T);
    cudaGetSymbolAddress((void**)&W2T,    g_W2T);

    cudaFuncSetAttribute((const void*)gemm_h<2, 0>, cudaFuncAttributeMaxDynamicSharedMemorySize, SMEM_BYTES);
    cudaFuncSetAttribute((const void*)gemm_h<0, 0>, cudaFuncAttributeMaxDynamicSharedMemorySize, SMEM_BYTES);
    cudaFuncSetAttribute((const void*)gemm_h<3, 0>, cudaFuncAttributeMaxDynamicSharedMemorySize, SMEM_BYTES);
    cudaFuncSetAttribute((const void*)gemm_h<2, 1>, cudaFuncAttributeMaxDynamicSharedMemorySize, SMEM_BYTES);
    cudaFuncSetAttribute((const void*)gemm_h<2, 2>, cudaFuncAttributeMaxDynamicSharedMemorySize, SMEM_BYTES);

    const float inv_sqrt_T = 1.0f / sqrtf((float)T_);
    dim3 tb(32, 8);

    // Weight transpose -> fp16 (once)
    transpose_h_f32<<<dim3(3 * D_ / 32, D_ / 32), tb>>>(Wqkv,  WqT, 3 * D_, D_);
    transpose_h_f32<<<dim3(D_ / 32,     D_ / 32), tb>>>(Wproj, WpT, D_,     D_);
    transpose_h_f32<<<dim3(4 * D_ / 32, D_ / 32), tb>>>(W1,    W1T, 4 * D_, D_);
    transpose_h_f32<<<dim3(D_ / 32, 4 * D_ / 32), tb>>>(W2,    W2T, D_, 4 * D_);

    // 1. LN1 -> fp16 h
    ln_half<<<ROWS, 256>>>(x, ln1_g, ln1_b, p_h);

    // 2. QKV GEMM -> fp16 kqv
    gemm_h<2, 0><<<dim3(3 * D_ / 128, ROWS / 128, 1), 256, SMEM_BYTES>>>(
        p_h, WqT, bqkv, nullptr, p_kqv,
        D_, D_, D_, 3 * D_, 0, 0, 0, 1.f);

    // 3. V^T, batched
    transpose_h<<<dim3(D_ / 32, T_ / 32, B_), tb>>>(
        p_kqv + 2 * D_, p_vT, 3 * D_, T_,
        (long long)T_ * 3 * D_, (long long)D_ * T_);

    // 4. scores = q @ k^T * inv_sqrt_T (lower-tri blocks) -> fp16
    gemm_h<2, 1><<<dim3(T_ / 128, T_ / 128, B_), 256, SMEM_BYTES>>>(
        p_kqv + D_, p_kqv, nullptr, nullptr, p_sc16,
        D_, 3 * D_, 3 * D_, T_,
        (long long)T_ * 3 * D_, (long long)T_ * 3 * D_, (long long)T_ * T_, inv_sqrt_T);

    // 5. softmax -> fp16 probs
    softmax_h<<<dim3(T_, B_), 256>>>(p_sc16, p_p);

    // 6. attn @ v (K clipped) -> fp16 at
    gemm_h<2, 2><<<dim3(D_ / 128, T_ / 128, B_), 256, SMEM_BYTES>>>(
        p_p, p_vT, nullptr, nullptr, p_at,
        T_, T_, T_, D_,
        (long long)T_ * T_, (long long)D_ * T_, (long long)T_ * D_, 1.f);

    // 7. proj -> fp32 a
    gemm_h<0, 0><<<dim3(D_ / 128, ROWS / 128, 1), 256, SMEM_BYTES>>>(
        p_at, WpT, bproj, p_a, nullptr,
        D_, D_, D_, D_, 0, 0, 0, 1.f);

    // 8. LN2 -> fp16 h2
    ln_half<<<ROWS, 256>>>(p_a, ln2_g, ln2_b, p_h2);

    // 9. MLP up + GELU -> fp16 mid
    gemm_h<3, 0><<<dim3(4 * D_ / 128, ROWS / 128, 1), 256, SMEM_BYTES>>>(
        p_h2, W1T, b1, nullptr, p_mid,
        D_, D_, D_, 4 * D_, 0, 0, 0, 1.f);

    // 10. MLP down -> fp32 out
    gemm_h<0, 0><<<dim3(D_ / 128, ROWS / 128, 1), 256, SMEM_BYTES>>>(
        p_mid, W2T, b2, out, nullptr,
        4 * D_, 4 * D_, 4 * D_, D_, 0, 0, 0, 1.f);
}

// round 11
// speedup vs baseline: 7.4496x; 1.0848x over previous
#include <cuda_runtime.h>
#include <cuda_fp16.h>
#include <math.h>
#include <stdint.h>

// Problem constants
#define B_ 4
#define T_ 2048
#define D_ 1024
#define ROWS (B_ * T_)        // 8192
#define EPS 1e-5f

typedef __half fp16;

// ---------------------------------------------------------------------------
// Scratch (allocation-free: __device__ globals)
// ---------------------------------------------------------------------------
__device__ float g_a  [ROWS * D_];              // fp32 proj out (LN2 input)

__device__ fp16 g_sc16 [(size_t)B_ * T_ * T_];  // fp16 scores
__device__ fp16 g_p    [(size_t)B_ * T_ * T_];  // fp16 probs
__device__ fp16 g_h    [ROWS * D_];
__device__ fp16 g_kqv  [ROWS * 3 * D_];
__device__ fp16 g_vT   [(size_t)B_ * D_ * T_];
__device__ fp16 g_at   [ROWS * D_];
__device__ fp16 g_h2   [ROWS * D_];
__device__ fp16 g_mid  [ROWS * 4 * D_];
__device__ fp16 g_WqkvT[3 * D_ * D_];
__device__ fp16 g_WprjT[D_ * D_];
__device__ fp16 g_W1T  [4 * D_ * D_];
__device__ fp16 g_W2T  [D_ * 4 * D_];

// ---------------------------------------------------------------------------
// helpers
// ---------------------------------------------------------------------------
__device__ __forceinline__ uint32_t pack2h(fp16 a, fp16 b) {
    return (uint32_t)__half_as_ushort(a) | ((uint32_t)__half_as_ushort(b) << 16);
}
__device__ __forceinline__ void mma_fp16(float* d, const uint32_t* a, const uint32_t* b) {
    asm volatile(
        "mma.sync.aligned.m16n8k16.row.col.f32.f16.f16.f32 "
        "{%0,%1,%2,%3}, {%4,%5,%6,%7}, {%8,%9}, {%0,%1,%2,%3};"
        : "+f"(d[0]), "+f"(d[1]), "+f"(d[2]), "+f"(d[3])
        : "r"(a[0]), "r"(a[1]), "r"(a[2]), "r"(a[3]),
          "r"(b[0]), "r"(b[1]));
}
__device__ __forceinline__ uint32_t smem_u32(const void* p) {
    uint32_t a;
    asm("{ .reg .u64 t; cvta.to.shared.u64 t, %1; cvt.u32.u64 %0, t; }" : "=r"(a) : "l"(p));
    return a;
}
__device__ __forceinline__ void cp16(uint32_t dst, const void* src) {
    asm volatile("cp.async.ca.shared.global [%0], [%1], 16;" :: "r"(dst), "l"(src));
}
#define CP_COMMIT() asm volatile("cp.async.commit_group;" ::: "memory")
#define CP_WAIT1()  asm volatile("cp.async.wait_group 1;" ::: "memory")
#define CP_WAIT0()  asm volatile("cp.async.wait_group 0;" ::: "memory")

#define LDSM_X4(d0, d1, d2, d3, addr) \
    asm volatile("ldmatrix.sync.aligned.m8n8.x4.shared.b16 {%0,%1,%2,%3}, [%4];" \
        : "=r"(d0), "=r"(d1), "=r"(d2), "=r"(d3) : "r"(addr))

// SMEM tile geometry: 128 rows x 32 fp16, row stride 40 elems (80B)
#define TILE_BYTES 10240
#define STAGE_BYTES (2 * TILE_BYTES)    // A + B tiles = 20480
#define NSTAGES 3
#define SMEM_BYTES (NSTAGES * STAGE_BYTES)   // 61440

// ---------------------------------------------------------------------------
// 1-pass fp16 NT GEMM, 3-stage cp.async pipeline, 1 sync per chunk.
// C[M,N] = alpha*(A @ B^T) (+bias)
// EPI: 0=fp32 out, 2=fp16 out, 3=gelu+fp16 out
// CMODE: 0=dense, 1=causal block skip, 2=causal K clip
// ---------------------------------------------------------------------------
template <int EPI, int CMODE>
__global__ void __launch_bounds__(256) gemm_h(
    const fp16* __restrict__ A, const fp16* __restrict__ Bm,
    const float* __restrict__ bias,
    float* __restrict__ Cf, fp16* __restrict__ Ch,
    int K, int lda, int ldb, int ldc,
    long long sA, long long sB, long long sC, float alpha)
{
    const int bx = blockIdx.x, by = blockIdx.y, bz = blockIdx.z;
    if (CMODE == 1 && bx > by) return;

    extern __shared__ fp16 smem[];
    const uint32_t sb = smem_u32(smem);

    A  += sA * bz;
    Bm += sB * bz;

    const int m0 = by * 128, n0 = bx * 128;
    int Kend = K;
    if (CMODE == 2) { int ke = (by + 1) * 128; if (ke < K) Kend = ke; }
    const int NC = Kend >> 5;    // >= 4 for all our shapes

    const int tid = threadIdx.x;
    const int wid = tid >> 5, lane = tid & 31;
    const int wm = wid & 1, wn = wid >> 1;
    const int g = lane >> 2, tig = lane & 3;

    const uint32_t a_loff = (uint32_t)(((lane & 7) + ((lane >> 3) & 1) * 8) * 80 + ((lane >> 4) & 1) * 16);
    const uint32_t b_loff = (uint32_t)(((lane & 7) + ((lane >> 4) & 1) * 8) * 80 + ((lane >> 3) & 1) * 16);

    const int lrow = tid >> 1;
    const int lc   = (tid & 1) * 2;

    const fp16* pA = A  + (size_t)(m0 + lrow) * lda + lc * 8;
    const fp16* pB = Bm + (size_t)(n0 + lrow) * ldb + lc * 8;
    const uint32_t dbase = sb + lrow * 80 + lc * 16;

    auto issue = [&](int kc, int buf) {
        const uint32_t d0 = dbase + buf * STAGE_BYTES;
        const int ko = kc * 32;
        cp16(d0,                   pA + ko);
        cp16(d0 + 16,              pA + ko + 8);
        cp16(d0 + TILE_BYTES,      pB + ko);
        cp16(d0 + TILE_BYTES + 16, pB + ko + 8);
    };

    float acc[4][4][4];
    #pragma unroll
    for (int i = 0; i < 4; i++)
        #pragma unroll
        for (int j = 0; j < 4; j++)
            #pragma unroll
            for (int r = 0; r < 4; r++) acc[i][j][r] = 0.f;

    // prime 2 stages
    issue(0, 0); CP_COMMIT();
    issue(1, 1); CP_COMMIT();

    int buf = 0;
    for (int kc = 0; kc < NC; kc++) {
        if (kc + 1 < NC) { CP_WAIT1(); } else { CP_WAIT0(); }
        __syncthreads();

        const uint32_t stage = sb + buf * STAGE_BYTES;
        const uint32_t aT = stage + (uint32_t)(wm * 64 * 80) + a_loff;
        const uint32_t bT = stage + TILE_BYTES + (uint32_t)(wn * 32 * 80) + b_loff;

        #pragma unroll
        for (int kk2 = 0; kk2 < 64; kk2 += 32) {
            uint32_t af[4][4], bf[4][2];
            #pragma unroll
            for (int mt = 0; mt < 4; mt++)
                LDSM_X4(af[mt][0], af[mt][1], af[mt][2], af[mt][3], aT + mt * 1280 + kk2);
            #pragma unroll
            for (int p = 0; p < 2; p++)
                LDSM_X4(bf[2*p][0], bf[2*p][1], bf[2*p+1][0], bf[2*p+1][1], bT + p * 1280 + kk2);
            #pragma unroll
            for (int mt = 0; mt < 4; mt++)
                #pragma unroll
                for (int nt = 0; nt < 4; nt++)
                    mma_fp16(acc[mt][nt], af[mt], bf[nt]);
        }

        // prefetch stage kc+2 into the buffer consumed at kc-1 (safe: sync above)
        if (kc + 2 < NC) {
            issue(kc + 2, (buf + 2) % NSTAGES);
            CP_COMMIT();
        }
        buf = (buf + 1) % NSTAGES;
    }

    // epilogue
    if (EPI == 0) Cf += sC * bz;
    else Ch += sC * bz;

    #pragma unroll
    for (int mt = 0; mt < 4; mt++) {
        #pragma unroll
        for (int nt = 0; nt < 4; nt++) {
            int m = m0 + wm * 64 + mt * 16 + g;
            int n = n0 + wn * 32 + nt * 8 + tig * 2;
            float2 bv = make_float2(0.f, 0.f);
            if (bias) bv = __ldg((const float2*)(bias + n));
            #pragma unroll
            for (int half_ = 0; half_ < 2; half_++) {
                float vx = acc[mt][nt][half_ * 2 + 0] * alpha + bv.x;
                float vy = acc[mt][nt][half_ * 2 + 1] * alpha + bv.y;
                if (EPI == 3) {
                    const float c0 = 0.7978845608028654f, c1 = 0.044715f;
                    vx = 0.5f * vx * (1.f + tanhf(c0 * (vx + c1 * vx * vx * vx)));
                    vy = 0.5f * vy * (1.f + tanhf(c0 * (vy + c1 * vy * vy * vy)));
                }
                size_t off = (size_t)(m + half_ * 8) * ldc + n;
                if (EPI == 0) {
                    *(float2*)(Cf + off) = make_float2(vx, vy);
                } else {
                    *(uint32_t*)(Ch + off) = pack2h(__float2half_rn(vx), __float2half_rn(vy));
                }
            }
        }
    }
}

// ---------------------------------------------------------------------------
// Weight transpose -> fp16: out[c][r] = fp16(in[r][c])
// ---------------------------------------------------------------------------
__global__ void __launch_bounds__(256) transpose_h_f32(
    const float* __restrict__ in, fp16* __restrict__ out, int ldi, int ldo)
{
    __shared__ float t[32][33];
    const int c0 = blockIdx.x * 32, r0 = blockIdx.y * 32;
    const int x = threadIdx.x, y = threadIdx.y;
    #pragma unroll
    for (int i = 0; i < 4; i++)
        t[y + i * 8][x] = in[(size_t)(r0 + y + i * 8) * ldi + c0 + x];
    __syncthreads();
    #pragma unroll
    for (int i = 0; i < 4; i++)
        out[(size_t)(c0 + y + i * 8) * ldo + r0 + x] = __float2half_rn(t[x][y + i * 8]);
}

// ---------------------------------------------------------------------------
// fp16 transpose (V -> V^T), batched
// ---------------------------------------------------------------------------
__global__ void __launch_bounds__(256) transpose_h(
    const fp16* __restrict__ in, fp16* __restrict__ out,
    int ldi, int ldo, long long sI, long long sO)
{
    __shared__ fp16 t[32][33];
    in  += sI * blockIdx.z;
    out += sO * blockIdx.z;
    const int c0 = blockIdx.x * 32, r0 = blockIdx.y * 32;
    const int x = threadIdx.x, y = threadIdx.y;
    #pragma unroll
    for (int i = 0; i < 4; i++)
        t[y + i * 8][x] = in[(size_t)(r0 + y + i * 8) * ldi + c0 + x];
    __syncthreads();
    #pragma unroll
    for (int i = 0; i < 4; i++)
        out[(size_t)(c0 + y + i * 8) * ldo + r0 + x] = t[x][y + i * 8];
}

// ---------------------------------------------------------------------------
// LayerNorm -> fp16 out (vectorized, row cached in SMEM)
// ---------------------------------------------------------------------------
__global__ void __launch_bounds__(256) ln_half(
    const float* __restrict__ x, const float* __restrict__ gamma,
    const float* __restrict__ beta, fp16* __restrict__ o)
{
    __shared__ float4 xc[D_ / 4];
    const int row = blockIdx.x;
    const float4* xr = (const float4*)(x + (size_t)row * D_);

    float s = 0.f, ss = 0.f;
    {
        float4 v = __ldg(xr + threadIdx.x);
        xc[threadIdx.x] = v;
        s  = v.x + v.y + v.z + v.w;
        ss = v.x * v.x + v.y * v.y + v.z * v.z + v.w * v.w;
    }
    __shared__ float rs[8], rss[8];
    #pragma unroll
    for (int o2 = 16; o2 > 0; o2 >>= 1) {
        s  += __shfl_down_sync(0xffffffffu, s,  o2);
        ss += __shfl_down_sync(0xffffffffu, ss, o2);
    }
    int wid = threadIdx.x >> 5, lid = threadIdx.x & 31;
    if (lid == 0) { rs[wid] = s; rss[wid] = ss; }
    __syncthreads();
    __shared__ float s_mu, s_rstd;
    if (threadIdx.x == 0) {
        float ts = 0.f, tss = 0.f;
        #pragma unroll
        for (int i = 0; i < 8; i++) { ts += rs[i]; tss += rss[i]; }
        float mu = ts / D_;
        float var = tss / D_ - mu * mu;
        s_mu = mu;
        s_rstd = rsqrtf(var + EPS);
    }
    __syncthreads();
    float mu = s_mu, rstd = s_rstd;
    {
        int i = threadIdx.x;
        float4 v = xc[i];
        float4 gm = __ldg((const float4*)gamma + i);
        float4 bt = __ldg((const float4*)beta + i);
        fp16 h0 = __float2half_rn((v.x - mu) * rstd * gm.x + bt.x);
        fp16 h1 = __float2half_rn((v.y - mu) * rstd * gm.y + bt.y);
        fp16 h2 = __float2half_rn((v.z - mu) * rstd * gm.z + bt.z);
        fp16 h3 = __float2half_rn((v.w - mu) * rstd * gm.w + bt.w);
        uint2 pk = make_uint2(pack2h(h0, h1), pack2h(h2, h3));
        *(uint2*)(o + (size_t)row * D_ + i * 4) = pk;
    }
}

// ---------------------------------------------------------------------------
// Causal softmax: fp16 scores -> fp16 probs (fast exp, fill to block edge)
// ---------------------------------------------------------------------------
__global__ void __launch_bounds__(256) softmax_h(
    const fp16* __restrict__ sc, fp16* __restrict__ pr)
{
    __shared__ float cache[T_];
    const int t = blockIdx.x, b = blockIdx.y;
    const size_t ro = ((size_t)b * T_ + t) * T_;
    const fp16* row = sc + ro;
    const int n = t + 1;
    const int blk_end = ((t >> 7) + 1) << 7;

    __shared__ float red[8];
    __shared__ float s_bc;

    float mx = -INFINITY;
    for (int i = threadIdx.x; i < n; i += 256) {
        float v = __half2float(row[i]);
        cache[i] = v;
        mx = fmaxf(mx, v);
    }
    #pragma unroll
    for (int o = 16; o > 0; o >>= 1) mx = fmaxf(mx, __shfl_down_sync(0xffffffffu, mx, o));
    int wid = threadIdx.x >> 5, lid = threadIdx.x & 31;
    if (lid == 0) red[wid] = mx;
    __syncthreads();
    if (threadIdx.x == 0) {
        float m = red[0];
        #pragma unroll
        for (int i = 1; i < 8; i++) m = fmaxf(m, red[i]);
        s_bc = m;
    }
    __syncthreads();
    mx = s_bc;

    float sum = 0.f;
    for (int i = threadIdx.x; i < n; i += 256) {
        float e = __expf(cache[i] - mx);
        cache[i] = e;
        sum += e;
    }
    #pragma unroll
    for (int o = 16; o > 0; o >>= 1) sum += __shfl_down_sync(0xffffffffu, sum, o);
    if (lid == 0) red[wid] = sum;
    __syncthreads();
    if (threadIdx.x == 0) {
        float tot = 0.f;
        #pragma unroll
        for (int i = 0; i < 8; i++) tot += red[i];
        s_bc = 1.f / tot;
    }
    __syncthreads();
    float inv = s_bc;
    for (int i = threadIdx.x; i < n; i += 256)
        pr[ro + i] = __float2half_rn(cache[i] * inv);
    const fp16 z = __float2half(0.f);
    for (int i = n + threadIdx.x; i < blk_end; i += 256)
        pr[ro + i] = z;
}

// ---------------------------------------------------------------------------
// launch
// ---------------------------------------------------------------------------
extern "C" void kernel_launch(void* const* d_in, const int* in_sizes, int n_in,
                              void* d_out, int out_size)
{
    const float* x     = (const float*)d_in[0];
    const float* ln1_g = (const float*)d_in[1];
    const float* ln1_b = (const float*)d_in[2];
    const float* Wqkv  = (const float*)d_in[3];
    const float* bqkv  = (const float*)d_in[4];
    const float* Wproj = (const float*)d_in[5];
    const float* bproj = (const float*)d_in[6];
    const float* ln2_g = (const float*)d_in[7];
    const float* ln2_b = (const float*)d_in[8];
    const float* W1    = (const float*)d_in[9];
    const float* b1    = (const float*)d_in[10];
    const float* W2    = (const float*)d_in[11];
    const float* b2    = (const float*)d_in[12];
    float* out = (float*)d_out;

    float *p_a;
    fp16 *p_sc16, *p_p, *p_h, *p_kqv, *p_vT, *p_at, *p_h2, *p_mid;
    fp16 *WqT, *WpT, *W1T, *W2T;

    cudaGetSymbolAddress((void**)&p_a,    g_a);
    cudaGetSymbolAddress((void**)&p_sc16, g_sc16);
    cudaGetSymbolAddress((void**)&p_p,    g_p);
    cudaGetSymbolAddress((void**)&p_h,    g_h);
    cudaGetSymbolAddress((void**)&p_kqv,  g_kqv);
    cudaGetSymbolAddress((void**)&p_vT,   g_vT);
    cudaGetSymbolAddress((void**)&p_at,   g_at);
    cudaGetSymbolAddress((void**)&p_h2,   g_h2);
    cudaGetSymbolAddress((void**)&p_mid,  g_mid);
    cudaGetSymbolAddress((void**)&WqT,    g_WqkvT);
    cudaGetSymbolAddress((void**)&WpT,    g_WprjT);
    cudaGetSymbolAddress((void**)&W1T,    g_W1T);
    cudaGetSymbolAddress((void**)&W2T,    g_W2T);

    cudaFuncSetAttribute((const void*)gemm_h<2, 0>, cudaFuncAttributeMaxDynamicSharedMemorySize, SMEM_BYTES);
    cudaFuncSetAttribute((const void*)gemm_h<0, 0>, cudaFuncAttributeMaxDynamicSharedMemorySize, SMEM_BYTES);
    cudaFuncSetAttribute((const void*)gemm_h<3, 0>, cudaFuncAttributeMaxDynamicSharedMemorySize, SMEM_BYTES);
    cudaFuncSetAttribute((const void*)gemm_h<2, 1>, cudaFuncAttributeMaxDynamicSharedMemorySize, SMEM_BYTES);
    cudaFuncSetAttribute((const void*)gemm_h<2, 2>, cudaFuncAttributeMaxDynamicSharedMemorySize, SMEM_BYTES);

    const float inv_sqrt_T = 1.0f / sqrtf((float)T_);
    dim3 tb(32, 8);

    // Weight transpose -> fp16 (once)
    transpose_h_f32<<<dim3(3 * D_ / 32, D_ / 32), tb>>>(Wqkv,  WqT, 3 * D_, D_);
    transpose_h_f32<<<dim3(D_ / 32,     D_ / 32), tb>>>(Wproj, WpT, D_,     D_);
    transpose_h_f32<<<dim3(4 * D_ / 32, D_ / 32), tb>>>(W1,    W1T, 4 * D_, D_);
    transpose_h_f32<<<dim3(D_ / 32, 4 * D_ / 32), tb>>>(W2,    W2T, D_, 4 * D_);

    // 1. LN1 -> fp16 h
    ln_half<<<ROWS, 256>>>(x, ln1_g, ln1_b, p_h);

    // 2. QKV GEMM -> fp16 kqv
    gemm_h<2, 0><<<dim3(3 * D_ / 128, ROWS / 128, 1), 256, SMEM_BYTES>>>(
        p_h, WqT, bqkv, nullptr, p_kqv,
        D_, D_, D_, 3 * D_, 0, 0, 0, 1.f);

    // 3. V^T, batched
    transpose_h<<<dim3(D_ / 32, T_ / 32, B_), tb>>>(
        p_kqv + 2 * D_, p_vT, 3 * D_, T_,
        (long long)T_ * 3 * D_, (long long)D_ * T_);

    // 4. scores = q @ k^T * inv_sqrt_T (lower-tri blocks) -> fp16
    gemm_h<2, 1><<<dim3(T_ / 128, T_ / 128, B_), 256, SMEM_BYTES>>>(
        p_kqv + D_, p_kqv, nullptr, nullptr, p_sc16,
        D_, 3 * D_, 3 * D_, T_,
        (long long)T_ * 3 * D_, (long long)T_ * 3 * D_, (long long)T_ * T_, inv_sqrt_T);

    // 5. softmax -> fp16 probs
    softmax_h<<<dim3(T_, B_), 256>>>(p_sc16, p_p);

    // 6. attn @ v (K clipped) -> fp16 at
    gemm_h<2, 2><<<dim3(D_ / 128, T_ / 128, B_), 256, SMEM_BYTES>>>(
        p_p, p_vT, nullptr, nullptr, p_at,
        T_, T_, T_, D_,
        (long long)T_ * T_, (long long)D_ * T_, (long long)T_ * D_, 1.f);

    // 7. proj -> fp32 a
    gemm_h<0, 0><<<dim3(D_ / 128, ROWS / 128, 1), 256, SMEM_BYTES>>>(
        p_at, WpT, bproj, p_a, nullptr,
        D_, D_, D_, D_, 0, 0, 0, 1.f);

    // 8. LN2 -> fp16 h2
    ln_half<<<ROWS, 256>>>(p_a, ln2_g, ln2_b, p_h2);

    // 9. MLP up + GELU -> fp16 mid
    gemm_h<3, 0><<<dim3(4 * D_ / 128, ROWS / 128, 1), 256, SMEM_BYTES>>>(
        p_h2, W1T, b1, nullptr, p_mid,
        D_, D_, D_, 4 * D_, 0, 0, 0, 1.f);

    // 10. MLP down -> fp32 out
    gemm_h<0, 0><<<dim3(D_ / 128, ROWS / 128, 1), 256, SMEM_BYTES>>>(
        p_mid, W2T, b2, out, nullptr,
        4 * D_, 4 * D_, 4 * D_, D_, 0, 0, 0, 1.f);
}

// round 12
// speedup vs baseline: 7.5521x; 1.0138x over previous
#include <cuda_runtime.h>
#include <cuda_fp16.h>
#include <math.h>
#include <stdint.h>

// Problem constants
#define B_ 4
#define T_ 2048
#define D_ 1024
#define ROWS (B_ * T_)        // 8192
#define EPS 1e-5f

typedef __half fp16;

// ---------------------------------------------------------------------------
// Scratch (allocation-free: __device__ globals)
// ---------------------------------------------------------------------------
__device__ float g_a  [ROWS * D_];              // fp32 proj out (LN2 input)

__device__ fp16 g_sc16 [(size_t)B_ * T_ * T_];  // fp16 scores
__device__ fp16 g_p    [(size_t)B_ * T_ * T_];  // fp16 probs
__device__ fp16 g_h    [ROWS * D_];
__device__ fp16 g_kqv  [ROWS * 3 * D_];
__device__ fp16 g_vT   [(size_t)B_ * D_ * T_];
__device__ fp16 g_at   [ROWS * D_];
__device__ fp16 g_h2   [ROWS * D_];
__device__ fp16 g_mid  [ROWS * 4 * D_];
__device__ fp16 g_WqkvT[3 * D_ * D_];
__device__ fp16 g_WprjT[D_ * D_];
__device__ fp16 g_W1T  [4 * D_ * D_];
__device__ fp16 g_W2T  [D_ * 4 * D_];

// ---------------------------------------------------------------------------
// helpers
// ---------------------------------------------------------------------------
__device__ __forceinline__ uint32_t pack2h(fp16 a, fp16 b) {
    return (uint32_t)__half_as_ushort(a) | ((uint32_t)__half_as_ushort(b) << 16);
}
__device__ __forceinline__ void mma_fp16(float* d, const uint32_t* a, const uint32_t* b) {
    asm volatile(
        "mma.sync.aligned.m16n8k16.row.col.f32.f16.f16.f32 "
        "{%0,%1,%2,%3}, {%4,%5,%6,%7}, {%8,%9}, {%0,%1,%2,%3};"
        : "+f"(d[0]), "+f"(d[1]), "+f"(d[2]), "+f"(d[3])
        : "r"(a[0]), "r"(a[1]), "r"(a[2]), "r"(a[3]),
          "r"(b[0]), "r"(b[1]));
}
__device__ __forceinline__ uint32_t smem_u32(const void* p) {
    uint32_t a;
    asm("{ .reg .u64 t; cvta.to.shared.u64 t, %1; cvt.u32.u64 %0, t; }" : "=r"(a) : "l"(p));
    return a;
}
__device__ __forceinline__ void cp16(uint32_t dst, const void* src) {
    asm volatile("cp.async.ca.shared.global [%0], [%1], 16;" :: "r"(dst), "l"(src));
}
#define CP_COMMIT() asm volatile("cp.async.commit_group;" ::: "memory")
#define CP_WAIT1()  asm volatile("cp.async.wait_group 1;" ::: "memory")
#define CP_WAIT0()  asm volatile("cp.async.wait_group 0;" ::: "memory")

#define LDSM_X4(d0, d1, d2, d3, addr) \
    asm volatile("ldmatrix.sync.aligned.m8n8.x4.shared.b16 {%0,%1,%2,%3}, [%4];" \
        : "=r"(d0), "=r"(d1), "=r"(d2), "=r"(d3) : "r"(addr))

// SMEM tile geometry: 128 rows x 32 fp16, row stride 40 elems (80B)
#define TILE_BYTES 10240
#define STAGE_BYTES (2 * TILE_BYTES)    // A + B tiles = 20480
#define NSTAGES 3
#define SMEM_BYTES (NSTAGES * STAGE_BYTES)   // 61440; x2 CTAs = 122880 fits

// ---------------------------------------------------------------------------
// 1-pass fp16 NT GEMM, 3-stage cp.async pipeline, 1 sync per chunk.
// Forced 2 CTAs/SM via launch bounds (<=128 regs).
// C[M,N] = alpha*(A @ B^T) (+bias)
// EPI: 0=fp32 out, 2=fp16 out, 3=gelu+fp16 out
// CMODE: 0=dense, 1=causal block skip, 2=causal K clip (by reversed: heavy first)
// ---------------------------------------------------------------------------
template <int EPI, int CMODE>
__global__ void __launch_bounds__(256, 2) gemm_h(
    const fp16* __restrict__ A, const fp16* __restrict__ Bm,
    const float* __restrict__ bias,
    float* __restrict__ Cf, fp16* __restrict__ Ch,
    int K, int lda, int ldb, int ldc,
    long long sA, long long sB, long long sC, float alpha)
{
    const int bx = blockIdx.x, bz = blockIdx.z;
    // For CMODE==2, reverse the y order so the heaviest CTAs (largest K clip)
    // are scheduled first, eliminating the long scheduling tail.
    const int by = (CMODE == 2) ? (gridDim.y - 1 - blockIdx.y) : blockIdx.y;
    if (CMODE == 1 && bx > by) return;

    extern __shared__ fp16 smem[];
    const uint32_t sb = smem_u32(smem);

    A  += sA * bz;
    Bm += sB * bz;

    const int m0 = by * 128, n0 = bx * 128;
    int Kend = K;
    if (CMODE == 2) { int ke = (by + 1) * 128; if (ke < K) Kend = ke; }
    const int NC = Kend >> 5;

    const int tid = threadIdx.x;
    const int wid = tid >> 5, lane = tid & 31;
    const int wm = wid & 1, wn = wid >> 1;
    const int g = lane >> 2, tig = lane & 3;

    const uint32_t a_loff = (uint32_t)(((lane & 7) + ((lane >> 3) & 1) * 8) * 80 + ((lane >> 4) & 1) * 16);
    const uint32_t b_loff = (uint32_t)(((lane & 7) + ((lane >> 4) & 1) * 8) * 80 + ((lane >> 3) & 1) * 16);

    const int lrow = tid >> 1;
    const int lc   = (tid & 1) * 2;

    const fp16* pA = A  + (size_t)(m0 + lrow) * lda + lc * 8;
    const fp16* pB = Bm + (size_t)(n0 + lrow) * ldb + lc * 8;
    const uint32_t dbase = sb + lrow * 80 + lc * 16;

    auto issue = [&](int kc, int buf) {
        const uint32_t d0 = dbase + buf * STAGE_BYTES;
        const int ko = kc * 32;
        cp16(d0,                   pA + ko);
        cp16(d0 + 16,              pA + ko + 8);
        cp16(d0 + TILE_BYTES,      pB + ko);
        cp16(d0 + TILE_BYTES + 16, pB + ko + 8);
    };

    float acc[4][4][4];
    #pragma unroll
    for (int i = 0; i < 4; i++)
        #pragma unroll
        for (int j = 0; j < 4; j++)
            #pragma unroll
            for (int r = 0; r < 4; r++) acc[i][j][r] = 0.f;

    // prime 2 stages
    issue(0, 0); CP_COMMIT();
    issue(1, 1); CP_COMMIT();

    int buf = 0;
    for (int kc = 0; kc < NC; kc++) {
        if (kc + 1 < NC) { CP_WAIT1(); } else { CP_WAIT0(); }
        __syncthreads();

        const uint32_t stage = sb + buf * STAGE_BYTES;
        const uint32_t aT = stage + (uint32_t)(wm * 64 * 80) + a_loff;
        const uint32_t bT = stage + TILE_BYTES + (uint32_t)(wn * 32 * 80) + b_loff;

        #pragma unroll
        for (int kk2 = 0; kk2 < 64; kk2 += 32) {
            uint32_t af[4][4], bf[4][2];
            #pragma unroll
            for (int mt = 0; mt < 4; mt++)
                LDSM_X4(af[mt][0], af[mt][1], af[mt][2], af[mt][3], aT + mt * 1280 + kk2);
            #pragma unroll
            for (int p = 0; p < 2; p++)
                LDSM_X4(bf[2*p][0], bf[2*p][1], bf[2*p+1][0], bf[2*p+1][1], bT + p * 1280 + kk2);
            #pragma unroll
            for (int mt = 0; mt < 4; mt++)
                #pragma unroll
                for (int nt = 0; nt < 4; nt++)
                    mma_fp16(acc[mt][nt], af[mt], bf[nt]);
        }

        // prefetch stage kc+2 into the buffer consumed at kc-1 (safe: sync above)
        if (kc + 2 < NC) {
            issue(kc + 2, (buf + 2) % NSTAGES);
            CP_COMMIT();
        }
        buf = (buf + 1) % NSTAGES;
    }

    // epilogue
    if (EPI == 0) Cf += sC * bz;
    else Ch += sC * bz;

    #pragma unroll
    for (int mt = 0; mt < 4; mt++) {
        #pragma unroll
        for (int nt = 0; nt < 4; nt++) {
            int m = m0 + wm * 64 + mt * 16 + g;
            int n = n0 + wn * 32 + nt * 8 + tig * 2;
            float2 bv = make_float2(0.f, 0.f);
            if (bias) bv = __ldg((const float2*)(bias + n));
            #pragma unroll
            for (int half_ = 0; half_ < 2; half_++) {
                float vx = acc[mt][nt][half_ * 2 + 0] * alpha + bv.x;
                float vy = acc[mt][nt][half_ * 2 + 1] * alpha + bv.y;
                if (EPI == 3) {
                    const float c0 = 0.7978845608028654f, c1 = 0.044715f;
                    vx = 0.5f * vx * (1.f + tanhf(c0 * (vx + c1 * vx * vx * vx)));
                    vy = 0.5f * vy * (1.f + tanhf(c0 * (vy + c1 * vy * vy * vy)));
                }
                size_t off = (size_t)(m + half_ * 8) * ldc + n;
                if (EPI == 0) {
                    *(float2*)(Cf + off) = make_float2(vx, vy);
                } else {
                    *(uint32_t*)(Ch + off) = pack2h(__float2half_rn(vx), __float2half_rn(vy));
                }
            }
        }
    }
}

// ---------------------------------------------------------------------------
// Weight transpose -> fp16: out[c][r] = fp16(in[r][c])
// ---------------------------------------------------------------------------
__global__ void __launch_bounds__(256) transpose_h_f32(
    const float* __restrict__ in, fp16* __restrict__ out, int ldi, int ldo)
{
    __shared__ float t[32][33];
    const int c0 = blockIdx.x * 32, r0 = blockIdx.y * 32;
    const int x = threadIdx.x, y = threadIdx.y;
    #pragma unroll
    for (int i = 0; i < 4; i++)
        t[y + i * 8][x] = in[(size_t)(r0 + y + i * 8) * ldi + c0 + x];
    __syncthreads();
    #pragma unroll
    for (int i = 0; i < 4; i++)
        out[(size_t)(c0 + y + i * 8) * ldo + r0 + x] = __float2half_rn(t[x][y + i * 8]);
}

// ---------------------------------------------------------------------------
// fp16 transpose (V -> V^T), batched
// ---------------------------------------------------------------------------
__global__ void __launch_bounds__(256) transpose_h(
    const fp16* __restrict__ in, fp16* __restrict__ out,
    int ldi, int ldo, long long sI, long long sO)
{
    __shared__ fp16 t[32][33];
    in  += sI * blockIdx.z;
    out += sO * blockIdx.z;
    const int c0 = blockIdx.x * 32, r0 = blockIdx.y * 32;
    const int x = threadIdx.x, y = threadIdx.y;
    #pragma unroll
    for (int i = 0; i < 4; i++)
        t[y + i * 8][x] = in[(size_t)(r0 + y + i * 8) * ldi + c0 + x];
    __syncthreads();
    #pragma unroll
    for (int i = 0; i < 4; i++)
        out[(size_t)(c0 + y + i * 8) * ldo + r0 + x] = t[x][y + i * 8];
}

// ---------------------------------------------------------------------------
// LayerNorm -> fp16 out (vectorized, row cached in SMEM)
// ---------------------------------------------------------------------------
__global__ void __launch_bounds__(256) ln_half(
    const float* __restrict__ x, const float* __restrict__ gamma,
    const float* __restrict__ beta, fp16* __restrict__ o)
{
    __shared__ float4 xc[D_ / 4];
    const int row = blockIdx.x;
    const float4* xr = (const float4*)(x + (size_t)row * D_);

    float s = 0.f, ss = 0.f;
    {
        float4 v = __ldg(xr + threadIdx.x);
        xc[threadIdx.x] = v;
        s  = v.x + v.y + v.z + v.w;
        ss = v.x * v.x + v.y * v.y + v.z * v.z + v.w * v.w;
    }
    __shared__ float rs[8], rss[8];
    #pragma unroll
    for (int o2 = 16; o2 > 0; o2 >>= 1) {
        s  += __shfl_down_sync(0xffffffffu, s,  o2);
        ss += __shfl_down_sync(0xffffffffu, ss, o2);
    }
    int wid = threadIdx.x >> 5, lid = threadIdx.x & 31;
    if (lid == 0) { rs[wid] = s; rss[wid] = ss; }
    __syncthreads();
    __shared__ float s_mu, s_rstd;
    if (threadIdx.x == 0) {
        float ts = 0.f, tss = 0.f;
        #pragma unroll
        for (int i = 0; i < 8; i++) { ts += rs[i]; tss += rss[i]; }
        float mu = ts / D_;
        float var = tss / D_ - mu * mu;
        s_mu = mu;
        s_rstd = rsqrtf(var + EPS);
    }
    __syncthreads();
    float mu = s_mu, rstd = s_rstd;
    {
        int i = threadIdx.x;
        float4 v = xc[i];
        float4 gm = __ldg((const float4*)gamma + i);
        float4 bt = __ldg((const float4*)beta + i);
        fp16 h0 = __float2half_rn((v.x - mu) * rstd * gm.x + bt.x);
        fp16 h1 = __float2half_rn((v.y - mu) * rstd * gm.y + bt.y);
        fp16 h2 = __float2half_rn((v.z - mu) * rstd * gm.z + bt.z);
        fp16 h3 = __float2half_rn((v.w - mu) * rstd * gm.w + bt.w);
        uint2 pk = make_uint2(pack2h(h0, h1), pack2h(h2, h3));
        *(uint2*)(o + (size_t)row * D_ + i * 4) = pk;
    }
}

// ---------------------------------------------------------------------------
// Causal softmax: fp16 scores -> fp16 probs (fast exp, fill to block edge)
// ---------------------------------------------------------------------------
__global__ void __launch_bounds__(256) softmax_h(
    const fp16* __restrict__ sc, fp16* __restrict__ pr)
{
    __shared__ float cache[T_];
    const int t = blockIdx.x, b = blockIdx.y;
    const size_t ro = ((size_t)b * T_ + t) * T_;
    const fp16* row = sc + ro;
    const int n = t + 1;
    const int blk_end = ((t >> 7) + 1) << 7;

    __shared__ float red[8];
    __shared__ float s_bc;

    float mx = -INFINITY;
    for (int i = threadIdx.x; i < n; i += 256) {
        float v = __half2float(row[i]);
        cache[i] = v;
        mx = fmaxf(mx, v);
    }
    #pragma unroll
    for (int o = 16; o > 0; o >>= 1) mx = fmaxf(mx, __shfl_down_sync(0xffffffffu, mx, o));
    int wid = threadIdx.x >> 5, lid = threadIdx.x & 31;
    if (lid == 0) red[wid] = mx;
    __syncthreads();
    if (threadIdx.x == 0) {
        float m = red[0];
        #pragma unroll
        for (int i = 1; i < 8; i++) m = fmaxf(m, red[i]);
        s_bc = m;
    }
    __syncthreads();
    mx = s_bc;

    float sum = 0.f;
    for (int i = threadIdx.x; i < n; i += 256) {
        float e = __expf(cache[i] - mx);
        cache[i] = e;
        sum += e;
    }
    #pragma unroll
    for (int o = 16; o > 0; o >>= 1) sum += __shfl_down_sync(0xffffffffu, sum, o);
    if (lid == 0) red[wid] = sum;
    __syncthreads();
    if (threadIdx.x == 0) {
        float tot = 0.f;
        #pragma unroll
        for (int i = 0; i < 8; i++) tot += red[i];
        s_bc = 1.f / tot;
    }
    __syncthreads();
    float inv = s_bc;
    for (int i = threadIdx.x; i < n; i += 256)
        pr[ro + i] = __float2half_rn(cache[i] * inv);
    const fp16 z = __float2half(0.f);
    for (int i = n + threadIdx.x; i < blk_end; i += 256)
        pr[ro + i] = z;
}

// ---------------------------------------------------------------------------
// launch
// ---------------------------------------------------------------------------
extern "C" void kernel_launch(void* const* d_in, const int* in_sizes, int n_in,
                              void* d_out, int out_size)
{
    const float* x     = (const float*)d_in[0];
    const float* ln1_g = (const float*)d_in[1];
    const float* ln1_b = (const float*)d_in[2];
    const float* Wqkv  = (const float*)d_in[3];
    const float* bqkv  = (const float*)d_in[4];
    const float* Wproj = (const float*)d_in[5];
    const float* bproj = (const float*)d_in[6];
    const float* ln2_g = (const float*)d_in[7];
    const float* ln2_b = (const float*)d_in[8];
    const float* W1    = (const float*)d_in[9];
    const float* b1    = (const float*)d_in[10];
    const float* W2    = (const float*)d_in[11];
    const float* b2    = (const float*)d_in[12];
    float* out = (float*)d_out;

    float *p_a;
    fp16 *p_sc16, *p_p, *p_h, *p_kqv, *p_vT, *p_at, *p_h2, *p_mid;
    fp16 *WqT, *WpT, *W1T, *W2T;

    cudaGetSymbolAddress((void**)&p_a,    g_a);
    cudaGetSymbolAddress((void**)&p_sc16, g_sc16);
    cudaGetSymbolAddress((void**)&p_p,    g_p);
    cudaGetSymbolAddress((void**)&p_h,    g_h);
    cudaGetSymbolAddress((void**)&p_kqv,  g_kqv);
    cudaGetSymbolAddress((void**)&p_vT,   g_vT);
    cudaGetSymbolAddress((void**)&p_at,   g_at);
    cudaGetSymbolAddress((void**)&p_h2,   g_h2);
    cudaGetSymbolAddress((void**)&p_mid,  g_mid);
    cudaGetSymbolAddress((void**)&WqT,    g_WqkvT);
    cudaGetSymbolAddress((void**)&WpT,    g_WprjT);
    cudaGetSymbolAddress((void**)&W1T,    g_W1T);
    cudaGetSymbolAddress((void**)&W2T,    g_W2T);

    cudaFuncSetAttribute((const void*)gemm_h<2, 0>, cudaFuncAttributeMaxDynamicSharedMemorySize, SMEM_BYTES);
    cudaFuncSetAttribute((const void*)gemm_h<0, 0>, cudaFuncAttributeMaxDynamicSharedMemorySize, SMEM_BYTES);
    cudaFuncSetAttribute((const void*)gemm_h<3, 0>, cudaFuncAttributeMaxDynamicSharedMemorySize, SMEM_BYTES);
    cudaFuncSetAttribute((const void*)gemm_h<2, 1>, cudaFuncAttributeMaxDynamicSharedMemorySize, SMEM_BYTES);
    cudaFuncSetAttribute((const void*)gemm_h<2, 2>, cudaFuncAttributeMaxDynamicSharedMemorySize, SMEM_BYTES);

    const float inv_sqrt_T = 1.0f / sqrtf((float)T_);
    dim3 tb(32, 8);

    // Weight transpose -> fp16 (once)
    transpose_h_f32<<<dim3(3 * D_ / 32, D_ / 32), tb>>>(Wqkv,  WqT, 3 * D_, D_);
    transpose_h_f32<<<dim3(D_ / 32,     D_ / 32), tb>>>(Wproj, WpT, D_,     D_);
    transpose_h_f32<<<dim3(4 * D_ / 32, D_ / 32), tb>>>(W1,    W1T, 4 * D_, D_);
    transpose_h_f32<<<dim3(D_ / 32, 4 * D_ / 32), tb>>>(W2,    W2T, D_, 4 * D_);

    // 1. LN1 -> fp16 h
    ln_half<<<ROWS, 256>>>(x, ln1_g, ln1_b, p_h);

    // 2. QKV GEMM -> fp16 kqv
    gemm_h<2, 0><<<dim3(3 * D_ / 128, ROWS / 128, 1), 256, SMEM_BYTES>>>(
        p_h, WqT, bqkv, nullptr, p_kqv,
        D_, D_, D_, 3 * D_, 0, 0, 0, 1.f);

    // 3. V^T, batched
    transpose_h<<<dim3(D_ / 32, T_ / 32, B_), tb>>>(
        p_kqv + 2 * D_, p_vT, 3 * D_, T_,
        (long long)T_ * 3 * D_, (long long)D_ * T_);

    // 4. scores = q @ k^T * inv_sqrt_T (lower-tri blocks) -> fp16
    gemm_h<2, 1><<<dim3(T_ / 128, T_ / 128, B_), 256, SMEM_BYTES>>>(
        p_kqv + D_, p_kqv, nullptr, nullptr, p_sc16,
        D_, 3 * D_, 3 * D_, T_,
        (long long)T_ * 3 * D_, (long long)T_ * 3 * D_, (long long)T_ * T_, inv_sqrt_T);

    // 5. softmax -> fp16 probs
    softmax_h<<<dim3(T_, B_), 256>>>(p_sc16, p_p);

    // 6. attn @ v (K clipped, heavy CTAs first) -> fp16 at
    gemm_h<2, 2><<<dim3(D_ / 128, T_ / 128, B_), 256, SMEM_BYTES>>>(
        p_p, p_vT, nullptr, nullptr, p_at,
        T_, T_, T_, D_,
        (long long)T_ * T_, (long long)D_ * T_, (long long)T_ * D_, 1.f);

    // 7. proj -> fp32 a
    gemm_h<0, 0><<<dim3(D_ / 128, ROWS / 128, 1), 256, SMEM_BYTES>>>(
        p_at, WpT, bproj, p_a, nullptr,
        D_, D_, D_, D_, 0, 0, 0, 1.f);

    // 8. LN2 -> fp16 h2
    ln_half<<<ROWS, 256>>>(p_a, ln2_g, ln2_b, p_h2);

    // 9. MLP up + GELU -> fp16 mid
    gemm_h<3, 0><<<dim3(4 * D_ / 128, ROWS / 128, 1), 256, SMEM_BYTES>>>(
        p_h2, W1T, b1, nullptr, p_mid,
        D_, D_, D_, 4 * D_, 0, 0, 0, 1.f);

    // 10. MLP down -> fp32 out
    gemm_h<0, 0><<<dim3(D_ / 128, ROWS / 128, 1), 256, SMEM_BYTES>>>(
        p_mid, W2T, b2, out, nullptr,
        4 * D_, 4 * D_, 4 * D_, D_, 0, 0, 0, 1.f);
}